// round 11
// baseline (speedup 1.0000x reference)
#include <cuda_runtime.h>
#include <cuda_bf16.h>
#include <cstdint>
#include <math.h>

#define BI 4
#define LI 2048
#define DI 1024
#define HI 16

typedef __nv_bfloat16 bf16;
#define ELI ((size_t)8192*1024)
#define ELW ((size_t)1024*1024)

// device-global scratch (allocation-free rule)
__device__ __align__(256) bf16 g_qhi[ELI], g_qlo[ELI], g_khi[ELI], g_klo[ELI], g_vhi[ELI], g_vlo[ELI];
__device__ __align__(256) bf16 g_wqhi[ELW], g_wqlo[ELW], g_wkhi[ELW], g_wklo[ELW];
__device__ __align__(256) bf16 g_wvhi[ELW], g_wvlo[ELW], g_wohi[ELW], g_wolo[ELW];
__device__ __align__(256) bf16 g_Qhi[ELI], g_Qlo[ELI], g_Khi[ELI], g_Klo[ELI];   // [bh][l][64]
__device__ __align__(256) bf16 g_VHhi[ELI], g_VHlo[ELI];                         // [bh][l][64]
__device__ __align__(256) bf16 g_Vthi[ELI], g_Vtlo[ELI];                         // [bh][64][2048]
__device__ __align__(256) bf16 g_Ohi[ELI], g_Olo[ELI];                           // [8192][1024]
__device__ __align__(256) float g_O2[ELI];
__device__ __align__(256) float g_M[(size_t)64*2048], g_I[(size_t)64*2048];

// ---------------- helpers ----------------
__device__ __forceinline__ uint32_t s2u(const void* p) {
    uint32_t a;
    asm("{ .reg .u64 t; cvta.to.shared.u64 t, %1; cvt.u32.u64 %0, t; }" : "=r"(a) : "l"(p));
    return a;
}
__device__ __forceinline__ void ldm4(uint32_t* r, uint32_t a) {
    asm volatile("ldmatrix.sync.aligned.m8n8.x4.shared.b16 {%0,%1,%2,%3}, [%4];"
                 : "=r"(r[0]), "=r"(r[1]), "=r"(r[2]), "=r"(r[3]) : "r"(a));
}
__device__ __forceinline__ void mma16816(float* c, const uint32_t* a, const uint32_t* b) {
    asm volatile("mma.sync.aligned.m16n8k16.row.col.f32.bf16.bf16.f32 "
                 "{%0,%1,%2,%3}, {%4,%5,%6,%7}, {%8,%9}, {%0,%1,%2,%3};"
                 : "+f"(c[0]), "+f"(c[1]), "+f"(c[2]), "+f"(c[3])
                 : "r"(a[0]), "r"(a[1]), "r"(a[2]), "r"(a[3]), "r"(b[0]), "r"(b[1]));
}
#define CP16(d, s)   asm volatile("cp.async.cg.shared.global [%0], [%1], 16;" :: "r"(d), "l"(s))
#define CP_COMMIT()  asm volatile("cp.async.commit_group;")
#define CP_WAIT0()   asm volatile("cp.async.wait_group 0;")

__device__ __forceinline__ void split2(float x0, float x1, unsigned& H, unsigned& L) {
    bf16 h0 = __float2bfloat16(x0), h1 = __float2bfloat16(x1);
    bf16 l0 = __float2bfloat16(x0 - __bfloat162float(h0));
    bf16 l1 = __float2bfloat16(x1 - __bfloat162float(h1));
    H = (unsigned)__bfloat16_as_ushort(h0) | ((unsigned)__bfloat16_as_ushort(h1) << 16);
    L = (unsigned)__bfloat16_as_ushort(l0) | ((unsigned)__bfloat16_as_ushort(l1) << 16);
}

struct CvtSet { const float* s[4]; bf16* h[4]; bf16* l[4]; int n4; };
__global__ void __launch_bounds__(256) convert_multi(CvtSet p) {
    int y = blockIdx.y;
    int i = blockIdx.x * 256 + threadIdx.x;
    if (i >= p.n4) return;
    float4 v = ((const float4*)p.s[y])[i];
    unsigned h01, l01, h23, l23;
    split2(v.x, v.y, h01, l01); split2(v.z, v.w, h23, l23);
    ((uint2*)p.h[y])[i] = make_uint2(h01, h23);
    ((uint2*)p.l[y])[i] = make_uint2(l01, l23);
}

// GEMM parameter block
struct GP {
    const bf16 *Ahi, *Alo, *Bhi, *Blo;
    float* Cf; bf16 *Chi, *Clo;
    const float *bias, *gM, *gI;
    int K;
};
struct GP3 { GP g[3]; };

// ---------------------------------------------------------------------------
// mma.sync split-bf16 GEMM (BK=32, 2-stage cp.async, one sync per chunk).
// MMA issue order: three term-passes over all accumulators, so consecutive
// HMMAs never share an accumulator (RAW distance = 16 MMAs).
// MODE 0: QKV proj (grid.z selects q/k/v) -> Chi/Clo scatter [bh][l][64], +bias
// MODE 1: out proj -> Cf [8192][1024], +bias
// MODE 3: attn@V   -> normalize attn in place via gM/gI, split, MMA -> Chi/Clo
// ---------------------------------------------------------------------------
template<int BN, int MODE>
__global__ void __launch_bounds__(256, 2)
gemm_mma(GP3 P)
{
    constexpr int BM = 128, BK = 32, BKP = 40;
    constexpr int ASZ = BM * BKP * 2;
    constexpr int BSZ = BN * BKP * 2;
    constexpr int STAGE = 2 * ASZ + 2 * BSZ;
    constexpr int NF = BN / 16;
    constexpr int BV = BN / 64;

    GP p = P.g[MODE == 0 ? blockIdx.z : 0];
    extern __shared__ char smem[];
    const uint32_t sbase = s2u(smem);
    __shared__ float sM[128], sI[128];

    const int t = threadIdx.x, l = t & 31, wid = t >> 5;
    const int wm = wid & 3, wn = wid >> 2;
    const int gid = l >> 2, tig = l & 3;
    const int bc = blockIdx.x, br = blockIdx.y, z = blockIdx.z;

    const bf16 *Ah = p.Ahi, *Al = p.Alo, *Bh = p.Bhi, *Bl = p.Blo;
    float* Aw = nullptr;
    if (MODE == 3) {
        Aw = p.Cf + ((size_t)((z & 15) * BI + (z >> 4))) * LI * LI;
        size_t o = (size_t)z * 64 * LI; Bh += o; Bl += o;
        if (t < 128) {
            size_t r = (size_t)z * LI + br * 128 + t;
            sM[t] = p.gM[r]; sI[t] = p.gI[r];
        }
        __syncthreads();
    }
    const int K = p.K;

    int aoff[2], boff[NF / 2];
    #pragma unroll
    for (int mi = 0; mi < 2; mi++)
        aoff[mi] = ((wm * 32 + mi * 16 + (l & 15)) * BKP + ((l & 16) >> 1)) * 2;
    #pragma unroll
    for (int pp = 0; pp < NF / 2; pp++)
        boff[pp] = ((wn * (BN / 2) + pp * 16 + (l & 7) + ((l >> 1) & 8)) * BKP + (l & 8)) * 2;

    float acc[2][NF][4];
    #pragma unroll
    for (int mi = 0; mi < 2; mi++)
        #pragma unroll
        for (int ni = 0; ni < NF; ni++)
            #pragma unroll
            for (int c = 0; c < 4; c++) acc[mi][ni][c] = 0.f;

    const int n = K / BK;
    float4 raf[4];

    auto issue = [&](int ck) {
        int k0 = ck * BK;
        uint32_t sd = sbase + (ck & 1) * STAGE;
        if (MODE != 3) {
            #pragma unroll
            for (int i = 0; i < 2; i++) {
                int vi = t + i * 256, row = vi >> 2, kc = (vi & 3) * 8;
                uint32_t off = (uint32_t)(row * BKP + kc) * 2;
                size_t g = (size_t)(br * 128 + row) * K + k0 + kc;
                CP16(sd + off,       Ah + g);
                CP16(sd + ASZ + off, Al + g);
            }
        }
        #pragma unroll
        for (int i = 0; i < BV; i++) {
            int vi = t + i * 256, row = vi >> 2, kc = (vi & 3) * 8;
            uint32_t off = (uint32_t)(row * BKP + kc) * 2;
            size_t g = (size_t)(bc * BN + row) * K + k0 + kc;
            CP16(sd + 2 * ASZ + off,       Bh + g);
            CP16(sd + 2 * ASZ + BSZ + off, Bl + g);
        }
    };
    auto ldg3 = [&](int ck) {
        int k0 = ck * BK;
        #pragma unroll
        for (int i = 0; i < 4; i++) {
            int vi = t + i * 256, row = vi >> 3, kc = (vi & 7) * 4;
            raf[i] = *(const float4*)(Aw + (size_t)(br * 128 + row) * K + k0 + kc);
        }
    };
    auto proc3 = [&](int ck) {
        int k0 = ck * BK;
        char* st = smem + (ck & 1) * STAGE;
        #pragma unroll
        for (int i = 0; i < 4; i++) {
            int vi = t + i * 256, row = vi >> 3, kc = (vi & 7) * 4;
            float M = sM[row], I = sI[row];
            float4 v = raf[i];
            v.x = __expf(v.x - M) * I; v.y = __expf(v.y - M) * I;
            v.z = __expf(v.z - M) * I; v.w = __expf(v.w - M) * I;
            *(float4*)(Aw + (size_t)(br * 128 + row) * K + k0 + kc) = v;
            unsigned h01, l01, h23, l23;
            split2(v.x, v.y, h01, l01); split2(v.z, v.w, h23, l23);
            *(uint2*)(st + (row * BKP + kc) * 2)       = make_uint2(h01, h23);
            *(uint2*)(st + ASZ + (row * BKP + kc) * 2) = make_uint2(l01, l23);
        }
    };
    auto compute = [&](int buf) {
        uint32_t sb = sbase + buf * STAGE;
        #pragma unroll
        for (int ks = 0; ks < 2; ks++) {
            int kb = ks * 32;
            uint32_t ah[2][4], al[2][4];
            #pragma unroll
            for (int mi = 0; mi < 2; mi++) {
                ldm4(ah[mi], sb + aoff[mi] + kb);
                ldm4(al[mi], sb + ASZ + aoff[mi] + kb);
            }
            uint32_t bh[NF][2], bl[NF][2];
            #pragma unroll
            for (int pp = 0; pp < NF / 2; pp++) {
                uint32_t r[4];
                ldm4(r, sb + 2 * ASZ + boff[pp] + kb);
                bh[2*pp][0] = r[0]; bh[2*pp][1] = r[1]; bh[2*pp+1][0] = r[2]; bh[2*pp+1][1] = r[3];
                ldm4(r, sb + 2 * ASZ + BSZ + boff[pp] + kb);
                bl[2*pp][0] = r[0]; bl[2*pp][1] = r[1]; bl[2*pp+1][0] = r[2]; bl[2*pp+1][1] = r[3];
            }
            // three term-passes: consecutive MMAs hit different accumulators
            #pragma unroll
            for (int mi = 0; mi < 2; mi++)
                #pragma unroll
                for (int ni = 0; ni < NF; ni++)
                    mma16816(acc[mi][ni], ah[mi], bh[ni]);
            #pragma unroll
            for (int mi = 0; mi < 2; mi++)
                #pragma unroll
                for (int ni = 0; ni < NF; ni++)
                    mma16816(acc[mi][ni], ah[mi], bl[ni]);
            #pragma unroll
            for (int mi = 0; mi < 2; mi++)
                #pragma unroll
                for (int ni = 0; ni < NF; ni++)
                    mma16816(acc[mi][ni], al[mi], bh[ni]);
        }
    };

    // pipeline: 2-stage ring, one sync per chunk (issue after barrier)
    if (MODE == 3) { ldg3(0); issue(0); proc3(0); }
    else           { issue(0); }
    CP_COMMIT();
    for (int ck = 0; ck < n; ck++) {
        CP_WAIT0();
        __syncthreads();
        if (ck + 1 < n) { issue(ck + 1); if (MODE == 3) ldg3(ck + 1); }
        compute(ck & 1);
        if (MODE == 3 && ck + 1 < n) proc3(ck + 1);
        CP_COMMIT();
    }

    // epilogue
    #pragma unroll
    for (int mi = 0; mi < 2; mi++)
        #pragma unroll
        for (int ni = 0; ni < NF; ni++)
            #pragma unroll
            for (int h = 0; h < 2; h++) {
                int gi = br * 128 + wm * 32 + mi * 16 + gid + h * 8;
                int gj = bc * BN + wn * (BN / 2) + ni * 8 + tig * 2;
                float v0 = acc[mi][ni][h * 2 + 0];
                float v1 = acc[mi][ni][h * 2 + 1];
                if (MODE == 1) {
                    v0 += p.bias[gj]; v1 += p.bias[gj + 1];
                    *(float2*)&p.Cf[(size_t)gi * DI + gj] = make_float2(v0, v1);
                } else if (MODE == 0) {
                    v0 += p.bias[gj]; v1 += p.bias[gj + 1];
                    unsigned H, L;
                    split2(v0, v1, H, L);
                    size_t e = (((size_t)((gi >> 11) * HI + (gj >> 6)) * LI + (gi & 2047)) << 6) + (gj & 63);
                    ((unsigned*)p.Chi)[e >> 1] = H;
                    ((unsigned*)p.Clo)[e >> 1] = L;
                } else {
                    unsigned H, L;
                    split2(v0, v1, H, L);
                    size_t e = ((size_t)(z >> 4) * LI + gi) * DI + (z & 15) * 64 + gj;
                    ((unsigned*)p.Chi)[e >> 1] = H;
                    ((unsigned*)p.Clo)[e >> 1] = L;
                }
            }
}

// ---------------------------------------------------------------------------
// Scores kernel (persistent row-block): grid (br=16, z=64).
// Q tile (128x64, hi+lo) loaded once; loop over 16 K-column tiles
// (2 BK=32 chunks each, double-buffered B ring, one sync per chunk).
// Term-pass MMA ordering as above. Online softmax stats -> M, 1/S.
// ---------------------------------------------------------------------------
__global__ void __launch_bounds__(256, 2)
scores_mma(const bf16* __restrict__ Qhi, const bf16* __restrict__ Qlo,
           const bf16* __restrict__ Khi, const bf16* __restrict__ Klo,
           float* __restrict__ attn, float* __restrict__ gM, float* __restrict__ gI)
{
    constexpr int BKP = 40;
    constexpr int PAN = 128 * BKP * 2;          // 10240 B: one plane, one 32-k panel
    extern __shared__ char smem[];
    const uint32_t sbase = s2u(smem);
    __shared__ float sm_m[2][128], sm_s[2][128];

    const int t = threadIdx.x, l = t & 31, wid = t >> 5;
    const int wm = wid & 3, wn = wid >> 2;
    const int gid = l >> 2, tig = l & 3;
    const int br = blockIdx.x, z = blockIdx.y;

    const bf16* Ah = Qhi + (size_t)z * LI * 64;
    const bf16* Al = Qlo + (size_t)z * LI * 64;
    const bf16* Bh = Khi + (size_t)z * LI * 64;
    const bf16* Bl = Klo + (size_t)z * LI * 64;
    float* Cf = attn + ((size_t)((z & 15) * BI + (z >> 4))) * LI * LI;

    int aoff[2], boff[4];
    #pragma unroll
    for (int mi = 0; mi < 2; mi++)
        aoff[mi] = ((wm * 32 + mi * 16 + (l & 15)) * BKP + ((l & 16) >> 1)) * 2;
    #pragma unroll
    for (int pp = 0; pp < 4; pp++)
        boff[pp] = ((wn * 64 + pp * 16 + (l & 7) + ((l >> 1) & 8)) * BKP + (l & 8)) * 2;

    // issue full A tile once: 2 panels x 2 planes
    #pragma unroll
    for (int ck = 0; ck < 2; ck++)
        #pragma unroll
        for (int i = 0; i < 2; i++) {
            int vi = t + i * 256, row = vi >> 2, kc = (vi & 3) * 8;
            uint32_t off = (uint32_t)(row * BKP + kc) * 2;
            size_t g = (size_t)(br * 128 + row) * 64 + ck * 32 + kc;
            CP16(sbase + ck * 2 * PAN + off,       Ah + g);
            CP16(sbase + ck * 2 * PAN + PAN + off, Al + g);
        }
    CP_COMMIT();

    auto issueB = [&](int s) {        // s = bc*2 + ck  -> ring slot s&1
        int bc = s >> 1, ck = s & 1;
        uint32_t sd = sbase + 4 * PAN + (s & 1) * 2 * PAN;
        #pragma unroll
        for (int i = 0; i < 2; i++) {
            int vi = t + i * 256, row = vi >> 2, kc = (vi & 3) * 8;
            uint32_t off = (uint32_t)(row * BKP + kc) * 2;
            size_t g = (size_t)(bc * 128 + row) * 64 + ck * 32 + kc;
            CP16(sd + off,       Bh + g);
            CP16(sd + PAN + off, Bl + g);
        }
    };

    float acc[2][8][4];
    #pragma unroll
    for (int mi = 0; mi < 2; mi++)
        #pragma unroll
        for (int ni = 0; ni < 8; ni++)
            #pragma unroll
            for (int c = 0; c < 4; c++) acc[mi][ni][c] = 0.f;

    float rm[2][2], rs[2][2];
    #pragma unroll
    for (int mi = 0; mi < 2; mi++)
        #pragma unroll
        for (int h = 0; h < 2; h++) { rm[mi][h] = -INFINITY; rs[mi][h] = 0.f; }

    issueB(0); CP_COMMIT();

    for (int s = 0; s < 32; s++) {
        CP_WAIT0();
        __syncthreads();
        if (s + 1 < 32) issueB(s + 1);
        CP_COMMIT();

        // compute chunk: A panel (s&1), B ring slot (s&1)
        {
            int ck = s & 1;
            uint32_t ab = sbase + ck * 2 * PAN;
            uint32_t bb = sbase + 4 * PAN + ck * 2 * PAN;
            #pragma unroll
            for (int ks = 0; ks < 2; ks++) {
                int kb = ks * 32;
                uint32_t ah[2][4], al[2][4];
                #pragma unroll
                for (int mi = 0; mi < 2; mi++) {
                    ldm4(ah[mi], ab + aoff[mi] + kb);
                    ldm4(al[mi], ab + PAN + aoff[mi] + kb);
                }
                uint32_t bhf[8][2], blf[8][2];
                #pragma unroll
                for (int pp = 0; pp < 4; pp++) {
                    uint32_t r[4];
                    ldm4(r, bb + boff[pp] + kb);
                    bhf[2*pp][0] = r[0]; bhf[2*pp][1] = r[1]; bhf[2*pp+1][0] = r[2]; bhf[2*pp+1][1] = r[3];
                    ldm4(r, bb + PAN + boff[pp] + kb);
                    blf[2*pp][0] = r[0]; blf[2*pp][1] = r[1]; blf[2*pp+1][0] = r[2]; blf[2*pp+1][1] = r[3];
                }
                // three term-passes
                #pragma unroll
                for (int mi = 0; mi < 2; mi++)
                    #pragma unroll
                    for (int ni = 0; ni < 8; ni++)
                        mma16816(acc[mi][ni], ah[mi], bhf[ni]);
                #pragma unroll
                for (int mi = 0; mi < 2; mi++)
                    #pragma unroll
                    for (int ni = 0; ni < 8; ni++)
                        mma16816(acc[mi][ni], ah[mi], blf[ni]);
                #pragma unroll
                for (int mi = 0; mi < 2; mi++)
                    #pragma unroll
                    for (int ni = 0; ni < 8; ni++)
                        mma16816(acc[mi][ni], al[mi], bhf[ni]);
            }
        }

        if (s & 1) {
            int bc = s >> 1;
            // scale + diag mask
            #pragma unroll
            for (int mi = 0; mi < 2; mi++)
                #pragma unroll
                for (int ni = 0; ni < 8; ni++)
                    #pragma unroll
                    for (int c = 0; c < 4; c++) {
                        int gi = br * 128 + wm * 32 + mi * 16 + gid + (c >> 1) * 8;
                        int gj = bc * 128 + wn * 64 + ni * 8 + tig * 2 + (c & 1);
                        float v = acc[mi][ni][c] * 0.125f;
                        if (gi == gj) v = -INFINITY;
                        acc[mi][ni][c] = v;
                    }
            // write raw scores
            #pragma unroll
            for (int mi = 0; mi < 2; mi++)
                #pragma unroll
                for (int ni = 0; ni < 8; ni++)
                    #pragma unroll
                    for (int h = 0; h < 2; h++) {
                        int gi = br * 128 + wm * 32 + mi * 16 + gid + h * 8;
                        int gj = bc * 128 + wn * 64 + ni * 8 + tig * 2;
                        *(float2*)&Cf[(size_t)gi * LI + gj] =
                            make_float2(acc[mi][ni][h * 2], acc[mi][ni][h * 2 + 1]);
                    }
            // online stats update
            #pragma unroll
            for (int mi = 0; mi < 2; mi++)
                #pragma unroll
                for (int h = 0; h < 2; h++) {
                    float m = -INFINITY;
                    #pragma unroll
                    for (int ni = 0; ni < 8; ni++) {
                        m = fmaxf(m, acc[mi][ni][h * 2 + 0]);
                        m = fmaxf(m, acc[mi][ni][h * 2 + 1]);
                    }
                    m = fmaxf(m, __shfl_xor_sync(0xffffffffu, m, 1));
                    m = fmaxf(m, __shfl_xor_sync(0xffffffffu, m, 2));
                    float sl = 0.f;
                    #pragma unroll
                    for (int ni = 0; ni < 8; ni++) {
                        sl += __expf(acc[mi][ni][h * 2 + 0] - m);
                        sl += __expf(acc[mi][ni][h * 2 + 1] - m);
                    }
                    sl += __shfl_xor_sync(0xffffffffu, sl, 1);
                    sl += __shfl_xor_sync(0xffffffffu, sl, 2);
                    float mo = rm[mi][h];
                    float mn = fmaxf(mo, m);
                    rs[mi][h] = rs[mi][h] * __expf(mo - mn) + sl * __expf(m - mn);
                    rm[mi][h] = mn;
                }
            // reset acc
            #pragma unroll
            for (int mi = 0; mi < 2; mi++)
                #pragma unroll
                for (int ni = 0; ni < 8; ni++)
                    #pragma unroll
                    for (int c = 0; c < 4; c++) acc[mi][ni][c] = 0.f;
        }
    }

    // merge the two wn warps, write M and 1/S
    #pragma unroll
    for (int mi = 0; mi < 2; mi++)
        #pragma unroll
        for (int h = 0; h < 2; h++) {
            int rl = wm * 32 + mi * 16 + h * 8 + gid;
            if (tig == 0) { sm_m[wn][rl] = rm[mi][h]; sm_s[wn][rl] = rs[mi][h]; }
        }
    __syncthreads();
    if (t < 128) {
        float m0 = sm_m[0][t], m1 = sm_m[1][t];
        float s0 = sm_s[0][t], s1 = sm_s[1][t];
        float m = fmaxf(m0, m1);
        float ssum = s0 * __expf(m0 - m) + s1 * __expf(m1 - m);
        size_t r = (size_t)z * LI + br * 128 + t;
        gM[r] = m; gI[r] = 1.f / ssum;
    }
}

// ---------------- V transpose (hi+lo): [bh][l][64] -> [bh][64][2048] ----------
__global__ void __launch_bounds__(256) transpose_bf(const bf16* __restrict__ ih, const bf16* __restrict__ il,
                                                    bf16* __restrict__ oh, bf16* __restrict__ ol) {
    __shared__ bf16 th[32][33], tl[32][33];
    int z = blockIdx.z, l0 = blockIdx.y * 32, d0 = blockIdx.x * 32;
    int x = threadIdx.x, y = threadIdx.y;
    #pragma unroll
    for (int i = 0; i < 32; i += 8) {
        size_t g = ((size_t)z * LI + l0 + y + i) * 64 + d0 + x;
        th[y + i][x] = ih[g]; tl[y + i][x] = il[g];
    }
    __syncthreads();
    #pragma unroll
    for (int i = 0; i < 32; i += 8) {
        size_t g = ((size_t)z * 64 + d0 + y + i) * LI + l0 + x;
        oh[g] = th[x][y + i]; ol[g] = tl[x][y + i];
    }
}

// ---------------- residual + LayerNorm ----------------
__device__ __forceinline__ float warpSum(float v) {
    #pragma unroll
    for (int o = 16; o; o >>= 1) v += __shfl_xor_sync(0xffffffffu, v, o);
    return v;
}
__global__ void __launch_bounds__(256) ln_kernel(const float* __restrict__ o2, const float* __restrict__ res,
                                                 const float* __restrict__ gamma, const float* __restrict__ beta,
                                                 float* __restrict__ out) {
    size_t row = blockIdx.x;
    int t = threadIdx.x;
    float4 a = ((const float4*)(o2 + row * DI))[t];
    float4 r = ((const float4*)(res + row * DI))[t];
    float x0 = a.x + r.x, x1 = a.y + r.y, x2 = a.z + r.z, x3 = a.w + r.w;
    float s = x0 + x1 + x2 + x3, sq = x0 * x0 + x1 * x1 + x2 * x2 + x3 * x3;
    s = warpSum(s); sq = warpSum(sq);
    __shared__ float rs[8], rq[8];
    if ((t & 31) == 0) { rs[t >> 5] = s; rq[t >> 5] = sq; }
    __syncthreads();
    s = 0.f; sq = 0.f;
    #pragma unroll
    for (int i = 0; i < 8; i++) { s += rs[i]; sq += rq[i]; }
    float mu = s * (1.0f / DI);
    float rstd = rsqrtf(sq * (1.0f / DI) - mu * mu + 1e-5f);
    float4 g = ((const float4*)gamma)[t], b = ((const float4*)beta)[t];
    float4 o;
    o.x = (x0 - mu) * rstd * g.x + b.x; o.y = (x1 - mu) * rstd * g.y + b.y;
    o.z = (x2 - mu) * rstd * g.z + b.z; o.w = (x3 - mu) * rstd * g.w + b.w;
    ((float4*)(out + row * DI))[t] = o;
}

// ---------------------------------------------------------------------------
extern "C" void kernel_launch(void* const* d_in, const int* in_sizes, int n_in,
                              void* d_out, int out_size)
{
    const float* q  = (const float*)d_in[0];
    const float* k  = (const float*)d_in[1];
    const float* v  = (const float*)d_in[2];
    const float* Wq = (const float*)d_in[3];  const float* bq = (const float*)d_in[4];
    const float* Wk = (const float*)d_in[5];  const float* bk = (const float*)d_in[6];
    const float* Wv = (const float*)d_in[7];  const float* bv = (const float*)d_in[8];
    const float* Wo = (const float*)d_in[9];  const float* bo = (const float*)d_in[10];
    const float* gamma = (const float*)d_in[11];
    const float* beta  = (const float*)d_in[12];

    float* out  = (float*)d_out;
    float* attn = out + (size_t)BI * LI * DI;

    bf16 *qhi,*qlo,*khi,*klo,*vhi,*vlo,*wqh,*wql,*wkh,*wkl,*wvh,*wvl,*woh,*wol;
    bf16 *Qhi,*Qlo,*Khi,*Klo,*VHh,*VHl,*Vth,*Vtl,*Ohi,*Olo;
    float *O2, *M, *I;
    cudaGetSymbolAddress((void**)&qhi, g_qhi);  cudaGetSymbolAddress((void**)&qlo, g_qlo);
    cudaGetSymbolAddress((void**)&khi, g_khi);  cudaGetSymbolAddress((void**)&klo, g_klo);
    cudaGetSymbolAddress((void**)&vhi, g_vhi);  cudaGetSymbolAddress((void**)&vlo, g_vlo);
    cudaGetSymbolAddress((void**)&wqh, g_wqhi); cudaGetSymbolAddress((void**)&wql, g_wqlo);
    cudaGetSymbolAddress((void**)&wkh, g_wkhi); cudaGetSymbolAddress((void**)&wkl, g_wklo);
    cudaGetSymbolAddress((void**)&wvh, g_wvhi); cudaGetSymbolAddress((void**)&wvl, g_wvlo);
    cudaGetSymbolAddress((void**)&woh, g_wohi); cudaGetSymbolAddress((void**)&wol, g_wolo);
    cudaGetSymbolAddress((void**)&Qhi, g_Qhi);  cudaGetSymbolAddress((void**)&Qlo, g_Qlo);
    cudaGetSymbolAddress((void**)&Khi, g_Khi);  cudaGetSymbolAddress((void**)&Klo, g_Klo);
    cudaGetSymbolAddress((void**)&VHh, g_VHhi); cudaGetSymbolAddress((void**)&VHl, g_VHlo);
    cudaGetSymbolAddress((void**)&Vth, g_Vthi); cudaGetSymbolAddress((void**)&Vtl, g_Vtlo);
    cudaGetSymbolAddress((void**)&Ohi, g_Ohi);  cudaGetSymbolAddress((void**)&Olo, g_Olo);
    cudaGetSymbolAddress((void**)&O2,  g_O2);
    cudaGetSymbolAddress((void**)&M,   g_M);    cudaGetSymbolAddress((void**)&I,   g_I);

    const int SM128 = 2 * (2*128*40*2 + 2*128*40*2);   // 81920
    const int SM64  = 2 * (2*128*40*2 + 2*64*40*2);    // 61440
    const int SMSC  = 81920;
    cudaFuncSetAttribute(gemm_mma<128,0>, cudaFuncAttributeMaxDynamicSharedMemorySize, SM128);
    cudaFuncSetAttribute(gemm_mma<128,1>, cudaFuncAttributeMaxDynamicSharedMemorySize, SM128);
    cudaFuncSetAttribute(gemm_mma<64,3>,  cudaFuncAttributeMaxDynamicSharedMemorySize, SM64);
    cudaFuncSetAttribute(scores_mma,      cudaFuncAttributeMaxDynamicSharedMemorySize, SMSC);

    // input/weight splits
    CvtSet ci; ci.s[0]=q; ci.s[1]=k; ci.s[2]=v; ci.s[3]=q;
    ci.h[0]=qhi; ci.h[1]=khi; ci.h[2]=vhi; ci.h[3]=qhi;
    ci.l[0]=qlo; ci.l[1]=klo; ci.l[2]=vlo; ci.l[3]=qlo;
    ci.n4 = 2097152;
    convert_multi<<<dim3(8192,3), 256>>>(ci);
    CvtSet cw; cw.s[0]=Wq; cw.s[1]=Wk; cw.s[2]=Wv; cw.s[3]=Wo;
    cw.h[0]=wqh; cw.h[1]=wkh; cw.h[2]=wvh; cw.h[3]=woh;
    cw.l[0]=wql; cw.l[1]=wkl; cw.l[2]=wvl; cw.l[3]=wol;
    cw.n4 = 262144;
    convert_multi<<<dim3(1024,4), 256>>>(cw);

    // merged QKV projections
    GP3 P; memset(&P, 0, sizeof(P));
    P.g[0] = { qhi,qlo, wqh,wql, nullptr,Qhi,Qlo, bq, nullptr,nullptr, DI };
    P.g[1] = { khi,klo, wkh,wkl, nullptr,Khi,Klo, bk, nullptr,nullptr, DI };
    P.g[2] = { vhi,vlo, wvh,wvl, nullptr,VHh,VHl, bv, nullptr,nullptr, DI };
    gemm_mma<128,0><<<dim3(8,64,3), 256, SM128>>>(P);

    transpose_bf<<<dim3(2,64,64), dim3(32,8)>>>(VHh, VHl, Vth, Vtl);

    // persistent scores + online softmax stats
    scores_mma<<<dim3(16,64), 256, SMSC>>>(Qhi,Qlo, Khi,Klo, attn, M, I);

    // fused normalize + attn write + attn @ V
    GP3 P3; memset(&P3, 0, sizeof(P3));
    P3.g[0] = { nullptr,nullptr, Vth,Vtl, attn,Ohi,Olo, nullptr, M,I, LI };
    gemm_mma<64,3><<<dim3(1,16,64), 256, SM64>>>(P3);

    // output projection + residual/LN
    GP3 P4; memset(&P4, 0, sizeof(P4));
    P4.g[0] = { Ohi,Olo, woh,wol, O2,nullptr,nullptr, bo, nullptr,nullptr, DI };
    gemm_mma<128,1><<<dim3(8,64,1), 256, SM128>>>(P4);
    ln_kernel<<<BI*LI, 256>>>(O2, q, gamma, beta, out);
}

// round 12
// speedup vs baseline: 1.0008x; 1.0008x over previous
#include <cuda_runtime.h>
#include <cuda_bf16.h>
#include <cstdint>
#include <math.h>

#define BI 4
#define LI 2048
#define DI 1024
#define HI 16

typedef __nv_bfloat16 bf16;
#define ELI ((size_t)8192*1024)
#define ELW ((size_t)1024*1024)

// device-global scratch (allocation-free rule)
__device__ __align__(256) bf16 g_qhi[ELI], g_qlo[ELI], g_khi[ELI], g_klo[ELI], g_vhi[ELI], g_vlo[ELI];
__device__ __align__(256) bf16 g_wqhi[ELW], g_wqlo[ELW], g_wkhi[ELW], g_wklo[ELW];
__device__ __align__(256) bf16 g_wvhi[ELW], g_wvlo[ELW], g_wohi[ELW], g_wolo[ELW];
__device__ __align__(256) bf16 g_Qhi[ELI], g_Qlo[ELI], g_Khi[ELI], g_Klo[ELI];   // [bh][l][64]
__device__ __align__(256) bf16 g_VHhi[ELI], g_VHlo[ELI];                         // [bh][l][64]
__device__ __align__(256) bf16 g_Vthi[ELI], g_Vtlo[ELI];                         // [bh][64][2048]
__device__ __align__(256) bf16 g_Ohi[ELI], g_Olo[ELI];                           // [8192][1024]
__device__ __align__(256) float g_O2[ELI];
__device__ __align__(256) float g_M[(size_t)64*2048], g_I[(size_t)64*2048];

// ---------------- helpers ----------------
__device__ __forceinline__ uint32_t s2u(const void* p) {
    uint32_t a;
    asm("{ .reg .u64 t; cvta.to.shared.u64 t, %1; cvt.u32.u64 %0, t; }" : "=r"(a) : "l"(p));
    return a;
}
__device__ __forceinline__ void ldm4(uint32_t* r, uint32_t a) {
    asm volatile("ldmatrix.sync.aligned.m8n8.x4.shared.b16 {%0,%1,%2,%3}, [%4];"
                 : "=r"(r[0]), "=r"(r[1]), "=r"(r[2]), "=r"(r[3]) : "r"(a));
}
__device__ __forceinline__ void mma16816(float* c, const uint32_t* a, const uint32_t* b) {
    asm volatile("mma.sync.aligned.m16n8k16.row.col.f32.bf16.bf16.f32 "
                 "{%0,%1,%2,%3}, {%4,%5,%6,%7}, {%8,%9}, {%0,%1,%2,%3};"
                 : "+f"(c[0]), "+f"(c[1]), "+f"(c[2]), "+f"(c[3])
                 : "r"(a[0]), "r"(a[1]), "r"(a[2]), "r"(a[3]), "r"(b[0]), "r"(b[1]));
}
#define CP16(d, s)   asm volatile("cp.async.cg.shared.global [%0], [%1], 16;" :: "r"(d), "l"(s))
#define CP_COMMIT()  asm volatile("cp.async.commit_group;")
#define CP_WAIT0()   asm volatile("cp.async.wait_group 0;")

__device__ __forceinline__ void split2(float x0, float x1, unsigned& H, unsigned& L) {
    bf16 h0 = __float2bfloat16(x0), h1 = __float2bfloat16(x1);
    bf16 l0 = __float2bfloat16(x0 - __bfloat162float(h0));
    bf16 l1 = __float2bfloat16(x1 - __bfloat162float(h1));
    H = (unsigned)__bfloat16_as_ushort(h0) | ((unsigned)__bfloat16_as_ushort(h1) << 16);
    L = (unsigned)__bfloat16_as_ushort(l0) | ((unsigned)__bfloat16_as_ushort(l1) << 16);
}

struct CvtSet { const float* s[4]; bf16* h[4]; bf16* l[4]; int n4; };
__global__ void __launch_bounds__(256) convert_multi(CvtSet p) {
    int y = blockIdx.y;
    int i = blockIdx.x * 256 + threadIdx.x;
    if (i >= p.n4) return;
    float4 v = ((const float4*)p.s[y])[i];
    unsigned h01, l01, h23, l23;
    split2(v.x, v.y, h01, l01); split2(v.z, v.w, h23, l23);
    ((uint2*)p.h[y])[i] = make_uint2(h01, h23);
    ((uint2*)p.l[y])[i] = make_uint2(l01, l23);
}

// GEMM parameter block
struct GP {
    const bf16 *Ahi, *Alo, *Bhi, *Blo;
    float* Cf; bf16 *Chi, *Clo;
    const float *bias, *gM, *gI;
    int K;
};
struct GP3 { GP g[3]; };

// ---------------------------------------------------------------------------
// mma.sync split-bf16 GEMM (BK=32, 2-stage cp.async, one sync per chunk).
// MMA issue order: three term-passes over all accumulators, so consecutive
// HMMAs never share an accumulator (RAW distance = 16 MMAs).
// MODE 0: QKV proj (grid.z selects q/k/v) -> Chi/Clo scatter [bh][l][64], +bias
// MODE 1: out proj -> Cf [8192][1024], +bias
// MODE 3: attn@V   -> normalize attn in place via gM/gI, split, MMA -> Chi/Clo
// ---------------------------------------------------------------------------
template<int BN, int MODE>
__global__ void __launch_bounds__(256, 2)
gemm_mma(GP3 P)
{
    constexpr int BM = 128, BK = 32, BKP = 40;
    constexpr int ASZ = BM * BKP * 2;
    constexpr int BSZ = BN * BKP * 2;
    constexpr int STAGE = 2 * ASZ + 2 * BSZ;
    constexpr int NF = BN / 16;
    constexpr int BV = BN / 64;

    GP p = P.g[MODE == 0 ? blockIdx.z : 0];
    extern __shared__ char smem[];
    const uint32_t sbase = s2u(smem);
    __shared__ float sM[128], sI[128];

    const int t = threadIdx.x, l = t & 31, wid = t >> 5;
    const int wm = wid & 3, wn = wid >> 2;
    const int gid = l >> 2, tig = l & 3;
    const int bc = blockIdx.x, br = blockIdx.y, z = blockIdx.z;

    const bf16 *Ah = p.Ahi, *Al = p.Alo, *Bh = p.Bhi, *Bl = p.Blo;
    float* Aw = nullptr;
    if (MODE == 3) {
        Aw = p.Cf + ((size_t)((z & 15) * BI + (z >> 4))) * LI * LI;
        size_t o = (size_t)z * 64 * LI; Bh += o; Bl += o;
        if (t < 128) {
            size_t r = (size_t)z * LI + br * 128 + t;
            sM[t] = p.gM[r]; sI[t] = p.gI[r];
        }
        __syncthreads();
    }
    const int K = p.K;

    int aoff[2], boff[NF / 2];
    #pragma unroll
    for (int mi = 0; mi < 2; mi++)
        aoff[mi] = ((wm * 32 + mi * 16 + (l & 15)) * BKP + ((l & 16) >> 1)) * 2;
    #pragma unroll
    for (int pp = 0; pp < NF / 2; pp++)
        boff[pp] = ((wn * (BN / 2) + pp * 16 + (l & 7) + ((l >> 1) & 8)) * BKP + (l & 8)) * 2;

    float acc[2][NF][4];
    #pragma unroll
    for (int mi = 0; mi < 2; mi++)
        #pragma unroll
        for (int ni = 0; ni < NF; ni++)
            #pragma unroll
            for (int c = 0; c < 4; c++) acc[mi][ni][c] = 0.f;

    const int n = K / BK;
    float4 raf[4];

    auto issue = [&](int ck) {
        int k0 = ck * BK;
        uint32_t sd = sbase + (ck & 1) * STAGE;
        if (MODE != 3) {
            #pragma unroll
            for (int i = 0; i < 2; i++) {
                int vi = t + i * 256, row = vi >> 2, kc = (vi & 3) * 8;
                uint32_t off = (uint32_t)(row * BKP + kc) * 2;
                size_t g = (size_t)(br * 128 + row) * K + k0 + kc;
                CP16(sd + off,       Ah + g);
                CP16(sd + ASZ + off, Al + g);
            }
        }
        #pragma unroll
        for (int i = 0; i < BV; i++) {
            int vi = t + i * 256, row = vi >> 2, kc = (vi & 3) * 8;
            uint32_t off = (uint32_t)(row * BKP + kc) * 2;
            size_t g = (size_t)(bc * BN + row) * K + k0 + kc;
            CP16(sd + 2 * ASZ + off,       Bh + g);
            CP16(sd + 2 * ASZ + BSZ + off, Bl + g);
        }
    };
    auto ldg3 = [&](int ck) {
        int k0 = ck * BK;
        #pragma unroll
        for (int i = 0; i < 4; i++) {
            int vi = t + i * 256, row = vi >> 3, kc = (vi & 7) * 4;
            raf[i] = *(const float4*)(Aw + (size_t)(br * 128 + row) * K + k0 + kc);
        }
    };
    auto proc3 = [&](int ck) {
        int k0 = ck * BK;
        char* st = smem + (ck & 1) * STAGE;
        #pragma unroll
        for (int i = 0; i < 4; i++) {
            int vi = t + i * 256, row = vi >> 3, kc = (vi & 7) * 4;
            float M = sM[row], I = sI[row];
            float4 v = raf[i];
            v.x = __expf(v.x - M) * I; v.y = __expf(v.y - M) * I;
            v.z = __expf(v.z - M) * I; v.w = __expf(v.w - M) * I;
            *(float4*)(Aw + (size_t)(br * 128 + row) * K + k0 + kc) = v;
            unsigned h01, l01, h23, l23;
            split2(v.x, v.y, h01, l01); split2(v.z, v.w, h23, l23);
            *(uint2*)(st + (row * BKP + kc) * 2)       = make_uint2(h01, h23);
            *(uint2*)(st + ASZ + (row * BKP + kc) * 2) = make_uint2(l01, l23);
        }
    };
    auto compute = [&](int buf) {
        uint32_t sb = sbase + buf * STAGE;
        #pragma unroll
        for (int ks = 0; ks < 2; ks++) {
            int kb = ks * 32;
            uint32_t ah[2][4], al[2][4];
            #pragma unroll
            for (int mi = 0; mi < 2; mi++) {
                ldm4(ah[mi], sb + aoff[mi] + kb);
                ldm4(al[mi], sb + ASZ + aoff[mi] + kb);
            }
            uint32_t bh[NF][2], bl[NF][2];
            #pragma unroll
            for (int pp = 0; pp < NF / 2; pp++) {
                uint32_t r[4];
                ldm4(r, sb + 2 * ASZ + boff[pp] + kb);
                bh[2*pp][0] = r[0]; bh[2*pp][1] = r[1]; bh[2*pp+1][0] = r[2]; bh[2*pp+1][1] = r[3];
                ldm4(r, sb + 2 * ASZ + BSZ + boff[pp] + kb);
                bl[2*pp][0] = r[0]; bl[2*pp][1] = r[1]; bl[2*pp+1][0] = r[2]; bl[2*pp+1][1] = r[3];
            }
            // three term-passes: consecutive MMAs hit different accumulators
            #pragma unroll
            for (int mi = 0; mi < 2; mi++)
                #pragma unroll
                for (int ni = 0; ni < NF; ni++)
                    mma16816(acc[mi][ni], ah[mi], bh[ni]);
            #pragma unroll
            for (int mi = 0; mi < 2; mi++)
                #pragma unroll
                for (int ni = 0; ni < NF; ni++)
                    mma16816(acc[mi][ni], ah[mi], bl[ni]);
            #pragma unroll
            for (int mi = 0; mi < 2; mi++)
                #pragma unroll
                for (int ni = 0; ni < NF; ni++)
                    mma16816(acc[mi][ni], al[mi], bh[ni]);
        }
    };

    // pipeline: 2-stage ring, one sync per chunk (issue after barrier)
    if (MODE == 3) { ldg3(0); issue(0); proc3(0); }
    else           { issue(0); }
    CP_COMMIT();
    for (int ck = 0; ck < n; ck++) {
        CP_WAIT0();
        __syncthreads();
        if (ck + 1 < n) { issue(ck + 1); if (MODE == 3) ldg3(ck + 1); }
        compute(ck & 1);
        if (MODE == 3 && ck + 1 < n) proc3(ck + 1);
        CP_COMMIT();
    }

    // epilogue
    #pragma unroll
    for (int mi = 0; mi < 2; mi++)
        #pragma unroll
        for (int ni = 0; ni < NF; ni++)
            #pragma unroll
            for (int h = 0; h < 2; h++) {
                int gi = br * 128 + wm * 32 + mi * 16 + gid + h * 8;
                int gj = bc * BN + wn * (BN / 2) + ni * 8 + tig * 2;
                float v0 = acc[mi][ni][h * 2 + 0];
                float v1 = acc[mi][ni][h * 2 + 1];
                if (MODE == 1) {
                    v0 += p.bias[gj]; v1 += p.bias[gj + 1];
                    *(float2*)&p.Cf[(size_t)gi * DI + gj] = make_float2(v0, v1);
                } else if (MODE == 0) {
                    v0 += p.bias[gj]; v1 += p.bias[gj + 1];
                    unsigned H, L;
                    split2(v0, v1, H, L);
                    size_t e = (((size_t)((gi >> 11) * HI + (gj >> 6)) * LI + (gi & 2047)) << 6) + (gj & 63);
                    ((unsigned*)p.Chi)[e >> 1] = H;
                    ((unsigned*)p.Clo)[e >> 1] = L;
                } else {
                    unsigned H, L;
                    split2(v0, v1, H, L);
                    size_t e = ((size_t)(z >> 4) * LI + gi) * DI + (z & 15) * 64 + gj;
                    ((unsigned*)p.Chi)[e >> 1] = H;
                    ((unsigned*)p.Clo)[e >> 1] = L;
                }
            }
}

// ---------------------------------------------------------------------------
// Scores kernel (persistent row-block): grid (br=16, z=64).
// Q tile (128x64, hi+lo) loaded once; loop over 16 K-column tiles
// (2 BK=32 chunks each, double-buffered B ring, one sync per chunk).
// Term-pass MMA ordering as above. Online softmax stats -> M, 1/S.
// ---------------------------------------------------------------------------
__global__ void __launch_bounds__(256, 2)
scores_mma(const bf16* __restrict__ Qhi, const bf16* __restrict__ Qlo,
           const bf16* __restrict__ Khi, const bf16* __restrict__ Klo,
           float* __restrict__ attn, float* __restrict__ gM, float* __restrict__ gI)
{
    constexpr int BKP = 40;
    constexpr int PAN = 128 * BKP * 2;          // 10240 B: one plane, one 32-k panel
    extern __shared__ char smem[];
    const uint32_t sbase = s2u(smem);
    __shared__ float sm_m[2][128], sm_s[2][128];

    const int t = threadIdx.x, l = t & 31, wid = t >> 5;
    const int wm = wid & 3, wn = wid >> 2;
    const int gid = l >> 2, tig = l & 3;
    const int br = blockIdx.x, z = blockIdx.y;

    const bf16* Ah = Qhi + (size_t)z * LI * 64;
    const bf16* Al = Qlo + (size_t)z * LI * 64;
    const bf16* Bh = Khi + (size_t)z * LI * 64;
    const bf16* Bl = Klo + (size_t)z * LI * 64;
    float* Cf = attn + ((size_t)((z & 15) * BI + (z >> 4))) * LI * LI;

    int aoff[2], boff[4];
    #pragma unroll
    for (int mi = 0; mi < 2; mi++)
        aoff[mi] = ((wm * 32 + mi * 16 + (l & 15)) * BKP + ((l & 16) >> 1)) * 2;
    #pragma unroll
    for (int pp = 0; pp < 4; pp++)
        boff[pp] = ((wn * 64 + pp * 16 + (l & 7) + ((l >> 1) & 8)) * BKP + (l & 8)) * 2;

    // issue full A tile once: 2 panels x 2 planes
    #pragma unroll
    for (int ck = 0; ck < 2; ck++)
        #pragma unroll
        for (int i = 0; i < 2; i++) {
            int vi = t + i * 256, row = vi >> 2, kc = (vi & 3) * 8;
            uint32_t off = (uint32_t)(row * BKP + kc) * 2;
            size_t g = (size_t)(br * 128 + row) * 64 + ck * 32 + kc;
            CP16(sbase + ck * 2 * PAN + off,       Ah + g);
            CP16(sbase + ck * 2 * PAN + PAN + off, Al + g);
        }
    CP_COMMIT();

    auto issueB = [&](int s) {        // s = bc*2 + ck  -> ring slot s&1
        int bc = s >> 1, ck = s & 1;
        uint32_t sd = sbase + 4 * PAN + (s & 1) * 2 * PAN;
        #pragma unroll
        for (int i = 0; i < 2; i++) {
            int vi = t + i * 256, row = vi >> 2, kc = (vi & 3) * 8;
            uint32_t off = (uint32_t)(row * BKP + kc) * 2;
            size_t g = (size_t)(bc * 128 + row) * 64 + ck * 32 + kc;
            CP16(sd + off,       Bh + g);
            CP16(sd + PAN + off, Bl + g);
        }
    };

    float acc[2][8][4];
    #pragma unroll
    for (int mi = 0; mi < 2; mi++)
        #pragma unroll
        for (int ni = 0; ni < 8; ni++)
            #pragma unroll
            for (int c = 0; c < 4; c++) acc[mi][ni][c] = 0.f;

    float rm[2][2], rs[2][2];
    #pragma unroll
    for (int mi = 0; mi < 2; mi++)
        #pragma unroll
        for (int h = 0; h < 2; h++) { rm[mi][h] = -INFINITY; rs[mi][h] = 0.f; }

    issueB(0); CP_COMMIT();

    for (int s = 0; s < 32; s++) {
        CP_WAIT0();
        __syncthreads();
        if (s + 1 < 32) issueB(s + 1);
        CP_COMMIT();

        // compute chunk: A panel (s&1), B ring slot (s&1)
        {
            int ck = s & 1;
            uint32_t ab = sbase + ck * 2 * PAN;
            uint32_t bb = sbase + 4 * PAN + ck * 2 * PAN;
            #pragma unroll
            for (int ks = 0; ks < 2; ks++) {
                int kb = ks * 32;
                uint32_t ah[2][4], al[2][4];
                #pragma unroll
                for (int mi = 0; mi < 2; mi++) {
                    ldm4(ah[mi], ab + aoff[mi] + kb);
                    ldm4(al[mi], ab + PAN + aoff[mi] + kb);
                }
                uint32_t bhf[8][2], blf[8][2];
                #pragma unroll
                for (int pp = 0; pp < 4; pp++) {
                    uint32_t r[4];
                    ldm4(r, bb + boff[pp] + kb);
                    bhf[2*pp][0] = r[0]; bhf[2*pp][1] = r[1]; bhf[2*pp+1][0] = r[2]; bhf[2*pp+1][1] = r[3];
                    ldm4(r, bb + PAN + boff[pp] + kb);
                    blf[2*pp][0] = r[0]; blf[2*pp][1] = r[1]; blf[2*pp+1][0] = r[2]; blf[2*pp+1][1] = r[3];
                }
                // three term-passes
                #pragma unroll
                for (int mi = 0; mi < 2; mi++)
                    #pragma unroll
                    for (int ni = 0; ni < 8; ni++)
                        mma16816(acc[mi][ni], ah[mi], bhf[ni]);
                #pragma unroll
                for (int mi = 0; mi < 2; mi++)
                    #pragma unroll
                    for (int ni = 0; ni < 8; ni++)
                        mma16816(acc[mi][ni], ah[mi], blf[ni]);
                #pragma unroll
                for (int mi = 0; mi < 2; mi++)
                    #pragma unroll
                    for (int ni = 0; ni < 8; ni++)
                        mma16816(acc[mi][ni], al[mi], bhf[ni]);
            }
        }

        if (s & 1) {
            int bc = s >> 1;
            // scale + diag mask
            #pragma unroll
            for (int mi = 0; mi < 2; mi++)
                #pragma unroll
                for (int ni = 0; ni < 8; ni++)
                    #pragma unroll
                    for (int c = 0; c < 4; c++) {
                        int gi = br * 128 + wm * 32 + mi * 16 + gid + (c >> 1) * 8;
                        int gj = bc * 128 + wn * 64 + ni * 8 + tig * 2 + (c & 1);
                        float v = acc[mi][ni][c] * 0.125f;
                        if (gi == gj) v = -INFINITY;
                        acc[mi][ni][c] = v;
                    }
            // write raw scores
            #pragma unroll
            for (int mi = 0; mi < 2; mi++)
                #pragma unroll
                for (int ni = 0; ni < 8; ni++)
                    #pragma unroll
                    for (int h = 0; h < 2; h++) {
                        int gi = br * 128 + wm * 32 + mi * 16 + gid + h * 8;
                        int gj = bc * 128 + wn * 64 + ni * 8 + tig * 2;
                        *(float2*)&Cf[(size_t)gi * LI + gj] =
                            make_float2(acc[mi][ni][h * 2], acc[mi][ni][h * 2 + 1]);
                    }
            // online stats update
            #pragma unroll
            for (int mi = 0; mi < 2; mi++)
                #pragma unroll
                for (int h = 0; h < 2; h++) {
                    float m = -INFINITY;
                    #pragma unroll
                    for (int ni = 0; ni < 8; ni++) {
                        m = fmaxf(m, acc[mi][ni][h * 2 + 0]);
                        m = fmaxf(m, acc[mi][ni][h * 2 + 1]);
                    }
                    m = fmaxf(m, __shfl_xor_sync(0xffffffffu, m, 1));
                    m = fmaxf(m, __shfl_xor_sync(0xffffffffu, m, 2));
                    float sl = 0.f;
                    #pragma unroll
                    for (int ni = 0; ni < 8; ni++) {
                        sl += __expf(acc[mi][ni][h * 2 + 0] - m);
                        sl += __expf(acc[mi][ni][h * 2 + 1] - m);
                    }
                    sl += __shfl_xor_sync(0xffffffffu, sl, 1);
                    sl += __shfl_xor_sync(0xffffffffu, sl, 2);
                    float mo = rm[mi][h];
                    float mn = fmaxf(mo, m);
                    rs[mi][h] = rs[mi][h] * __expf(mo - mn) + sl * __expf(m - mn);
                    rm[mi][h] = mn;
                }
            // reset acc
            #pragma unroll
            for (int mi = 0; mi < 2; mi++)
                #pragma unroll
                for (int ni = 0; ni < 8; ni++)
                    #pragma unroll
                    for (int c = 0; c < 4; c++) acc[mi][ni][c] = 0.f;
        }
    }

    // merge the two wn warps, write M and 1/S
    #pragma unroll
    for (int mi = 0; mi < 2; mi++)
        #pragma unroll
        for (int h = 0; h < 2; h++) {
            int rl = wm * 32 + mi * 16 + h * 8 + gid;
            if (tig == 0) { sm_m[wn][rl] = rm[mi][h]; sm_s[wn][rl] = rs[mi][h]; }
        }
    __syncthreads();
    if (t < 128) {
        float m0 = sm_m[0][t], m1 = sm_m[1][t];
        float s0 = sm_s[0][t], s1 = sm_s[1][t];
        float m = fmaxf(m0, m1);
        float ssum = s0 * __expf(m0 - m) + s1 * __expf(m1 - m);
        size_t r = (size_t)z * LI + br * 128 + t;
        gM[r] = m; gI[r] = 1.f / ssum;
    }
}

// ---------------- V transpose (hi+lo): [bh][l][64] -> [bh][64][2048] ----------
__global__ void __launch_bounds__(256) transpose_bf(const bf16* __restrict__ ih, const bf16* __restrict__ il,
                                                    bf16* __restrict__ oh, bf16* __restrict__ ol) {
    __shared__ bf16 th[32][33], tl[32][33];
    int z = blockIdx.z, l0 = blockIdx.y * 32, d0 = blockIdx.x * 32;
    int x = threadIdx.x, y = threadIdx.y;
    #pragma unroll
    for (int i = 0; i < 32; i += 8) {
        size_t g = ((size_t)z * LI + l0 + y + i) * 64 + d0 + x;
        th[y + i][x] = ih[g]; tl[y + i][x] = il[g];
    }
    __syncthreads();
    #pragma unroll
    for (int i = 0; i < 32; i += 8) {
        size_t g = ((size_t)z * 64 + d0 + y + i) * LI + l0 + x;
        oh[g] = th[x][y + i]; ol[g] = tl[x][y + i];
    }
}

// ---------------- residual + LayerNorm ----------------
__device__ __forceinline__ float warpSum(float v) {
    #pragma unroll
    for (int o = 16; o; o >>= 1) v += __shfl_xor_sync(0xffffffffu, v, o);
    return v;
}
__global__ void __launch_bounds__(256) ln_kernel(const float* __restrict__ o2, const float* __restrict__ res,
                                                 const float* __restrict__ gamma, const float* __restrict__ beta,
                                                 float* __restrict__ out) {
    size_t row = blockIdx.x;
    int t = threadIdx.x;
    float4 a = ((const float4*)(o2 + row * DI))[t];
    float4 r = ((const float4*)(res + row * DI))[t];
    float x0 = a.x + r.x, x1 = a.y + r.y, x2 = a.z + r.z, x3 = a.w + r.w;
    float s = x0 + x1 + x2 + x3, sq = x0 * x0 + x1 * x1 + x2 * x2 + x3 * x3;
    s = warpSum(s); sq = warpSum(sq);
    __shared__ float rs[8], rq[8];
    if ((t & 31) == 0) { rs[t >> 5] = s; rq[t >> 5] = sq; }
    __syncthreads();
    s = 0.f; sq = 0.f;
    #pragma unroll
    for (int i = 0; i < 8; i++) { s += rs[i]; sq += rq[i]; }
    float mu = s * (1.0f / DI);
    float rstd = rsqrtf(sq * (1.0f / DI) - mu * mu + 1e-5f);
    float4 g = ((const float4*)gamma)[t], b = ((const float4*)beta)[t];
    float4 o;
    o.x = (x0 - mu) * rstd * g.x + b.x; o.y = (x1 - mu) * rstd * g.y + b.y;
    o.z = (x2 - mu) * rstd * g.z + b.z; o.w = (x3 - mu) * rstd * g.w + b.w;
    ((float4*)(out + row * DI))[t] = o;
}

// ---------------------------------------------------------------------------
extern "C" void kernel_launch(void* const* d_in, const int* in_sizes, int n_in,
                              void* d_out, int out_size)
{
    const float* q  = (const float*)d_in[0];
    const float* k  = (const float*)d_in[1];
    const float* v  = (const float*)d_in[2];
    const float* Wq = (const float*)d_in[3];  const float* bq = (const float*)d_in[4];
    const float* Wk = (const float*)d_in[5];  const float* bk = (const float*)d_in[6];
    const float* Wv = (const float*)d_in[7];  const float* bv = (const float*)d_in[8];
    const float* Wo = (const float*)d_in[9];  const float* bo = (const float*)d_in[10];
    const float* gamma = (const float*)d_in[11];
    const float* beta  = (const float*)d_in[12];

    float* out  = (float*)d_out;
    float* attn = out + (size_t)BI * LI * DI;

    bf16 *qhi,*qlo,*khi,*klo,*vhi,*vlo,*wqh,*wql,*wkh,*wkl,*wvh,*wvl,*woh,*wol;
    bf16 *Qhi,*Qlo,*Khi,*Klo,*VHh,*VHl,*Vth,*Vtl,*Ohi,*Olo;
    float *O2, *M, *I;
    cudaGetSymbolAddress((void**)&qhi, g_qhi);  cudaGetSymbolAddress((void**)&qlo, g_qlo);
    cudaGetSymbolAddress((void**)&khi, g_khi);  cudaGetSymbolAddress((void**)&klo, g_klo);
    cudaGetSymbolAddress((void**)&vhi, g_vhi);  cudaGetSymbolAddress((void**)&vlo, g_vlo);
    cudaGetSymbolAddress((void**)&wqh, g_wqhi); cudaGetSymbolAddress((void**)&wql, g_wqlo);
    cudaGetSymbolAddress((void**)&wkh, g_wkhi); cudaGetSymbolAddress((void**)&wkl, g_wklo);
    cudaGetSymbolAddress((void**)&wvh, g_wvhi); cudaGetSymbolAddress((void**)&wvl, g_wvlo);
    cudaGetSymbolAddress((void**)&woh, g_wohi); cudaGetSymbolAddress((void**)&wol, g_wolo);
    cudaGetSymbolAddress((void**)&Qhi, g_Qhi);  cudaGetSymbolAddress((void**)&Qlo, g_Qlo);
    cudaGetSymbolAddress((void**)&Khi, g_Khi);  cudaGetSymbolAddress((void**)&Klo, g_Klo);
    cudaGetSymbolAddress((void**)&VHh, g_VHhi); cudaGetSymbolAddress((void**)&VHl, g_VHlo);
    cudaGetSymbolAddress((void**)&Vth, g_Vthi); cudaGetSymbolAddress((void**)&Vtl, g_Vtlo);
    cudaGetSymbolAddress((void**)&Ohi, g_Ohi);  cudaGetSymbolAddress((void**)&Olo, g_Olo);
    cudaGetSymbolAddress((void**)&O2,  g_O2);
    cudaGetSymbolAddress((void**)&M,   g_M);    cudaGetSymbolAddress((void**)&I,   g_I);

    const int SM128 = 2 * (2*128*40*2 + 2*128*40*2);   // 81920
    const int SM64  = 2 * (2*128*40*2 + 2*64*40*2);    // 61440
    const int SMSC  = 81920;
    cudaFuncSetAttribute(gemm_mma<128,0>, cudaFuncAttributeMaxDynamicSharedMemorySize, SM128);
    cudaFuncSetAttribute(gemm_mma<128,1>, cudaFuncAttributeMaxDynamicSharedMemorySize, SM128);
    cudaFuncSetAttribute(gemm_mma<64,3>,  cudaFuncAttributeMaxDynamicSharedMemorySize, SM64);
    cudaFuncSetAttribute(scores_mma,      cudaFuncAttributeMaxDynamicSharedMemorySize, SMSC);

    // input/weight splits
    CvtSet ci; ci.s[0]=q; ci.s[1]=k; ci.s[2]=v; ci.s[3]=q;
    ci.h[0]=qhi; ci.h[1]=khi; ci.h[2]=vhi; ci.h[3]=qhi;
    ci.l[0]=qlo; ci.l[1]=klo; ci.l[2]=vlo; ci.l[3]=qlo;
    ci.n4 = 2097152;
    convert_multi<<<dim3(8192,3), 256>>>(ci);
    CvtSet cw; cw.s[0]=Wq; cw.s[1]=Wk; cw.s[2]=Wv; cw.s[3]=Wo;
    cw.h[0]=wqh; cw.h[1]=wkh; cw.h[2]=wvh; cw.h[3]=woh;
    cw.l[0]=wql; cw.l[1]=wkl; cw.l[2]=wvl; cw.l[3]=wol;
    cw.n4 = 262144;
    convert_multi<<<dim3(1024,4), 256>>>(cw);

    // merged QKV projections
    GP3 P; memset(&P, 0, sizeof(P));
    P.g[0] = { qhi,qlo, wqh,wql, nullptr,Qhi,Qlo, bq, nullptr,nullptr, DI };
    P.g[1] = { khi,klo, wkh,wkl, nullptr,Khi,Klo, bk, nullptr,nullptr, DI };
    P.g[2] = { vhi,vlo, wvh,wvl, nullptr,VHh,VHl, bv, nullptr,nullptr, DI };
    gemm_mma<128,0><<<dim3(8,64,3), 256, SM128>>>(P);

    transpose_bf<<<dim3(2,64,64), dim3(32,8)>>>(VHh, VHl, Vth, Vtl);

    // persistent scores + online softmax stats
    scores_mma<<<dim3(16,64), 256, SMSC>>>(Qhi,Qlo, Khi,Klo, attn, M, I);

    // fused normalize + attn write + attn @ V
    GP3 P3; memset(&P3, 0, sizeof(P3));
    P3.g[0] = { nullptr,nullptr, Vth,Vtl, attn,Ohi,Olo, nullptr, M,I, LI };
    gemm_mma<64,3><<<dim3(1,16,64), 256, SM64>>>(P3);

    // output projection + residual/LN
    GP3 P4; memset(&P4, 0, sizeof(P4));
    P4.g[0] = { Ohi,Olo, woh,wol, O2,nullptr,nullptr, bo, nullptr,nullptr, DI };
    gemm_mma<128,1><<<dim3(8,64,1), 256, SM128>>>(P4);
    ln_kernel<<<BI*LI, 256>>>(O2, q, gamma, beta, out);
}

// round 13
// speedup vs baseline: 1.0501x; 1.0492x over previous
#include <cuda_runtime.h>
#include <cuda_bf16.h>
#include <cuda_fp16.h>
#include <cstdint>
#include <math.h>

#define BI 4
#define LI 2048
#define DI 1024
#define HI 16

typedef __nv_bfloat16 bf16;
#define ELI ((size_t)8192*1024)
#define ELW ((size_t)1024*1024)

// device-global scratch (allocation-free rule). 16-bit buffers hold bf16 OR fp16 bits.
__device__ __align__(256) bf16 g_qhi[ELI], g_qlo[ELI], g_khi[ELI], g_klo[ELI], g_vhi[ELI], g_vlo[ELI];
__device__ __align__(256) bf16 g_wqhi[ELW], g_wqlo[ELW], g_wkhi[ELW], g_wklo[ELW];
__device__ __align__(256) bf16 g_wvhi[ELW], g_wvlo[ELW], g_wohi[ELW], g_wolo[ELW];
__device__ __align__(256) bf16 g_Qhi[ELI], g_Qlo[ELI], g_Khi[ELI], g_Klo[ELI];   // [bh][l][64] bf16
__device__ __align__(256) bf16 g_VHhi[ELI], g_VHlo[ELI];                         // [bh][l][64] fp16
__device__ __align__(256) bf16 g_Vthi[ELI], g_Vtlo[ELI];                         // [bh][64][2048] fp16
__device__ __align__(256) bf16 g_Ohi[ELI];                                       // [8192][1024] fp16 (single plane)
__device__ __align__(256) float g_O2[ELI];
__device__ __align__(256) float g_M[(size_t)64*2048], g_I[(size_t)64*2048];

// ---------------- helpers ----------------
__device__ __forceinline__ uint32_t s2u(const void* p) {
    uint32_t a;
    asm("{ .reg .u64 t; cvta.to.shared.u64 t, %1; cvt.u32.u64 %0, t; }" : "=r"(a) : "l"(p));
    return a;
}
__device__ __forceinline__ void ldm4(uint32_t* r, uint32_t a) {
    asm volatile("ldmatrix.sync.aligned.m8n8.x4.shared.b16 {%0,%1,%2,%3}, [%4];"
                 : "=r"(r[0]), "=r"(r[1]), "=r"(r[2]), "=r"(r[3]) : "r"(a));
}
__device__ __forceinline__ void mma_bf(float* c, const uint32_t* a, const uint32_t* b) {
    asm volatile("mma.sync.aligned.m16n8k16.row.col.f32.bf16.bf16.f32 "
                 "{%0,%1,%2,%3}, {%4,%5,%6,%7}, {%8,%9}, {%0,%1,%2,%3};"
                 : "+f"(c[0]), "+f"(c[1]), "+f"(c[2]), "+f"(c[3])
                 : "r"(a[0]), "r"(a[1]), "r"(a[2]), "r"(a[3]), "r"(b[0]), "r"(b[1]));
}
__device__ __forceinline__ void mma_fp(float* c, const uint32_t* a, const uint32_t* b) {
    asm volatile("mma.sync.aligned.m16n8k16.row.col.f32.f16.f16.f32 "
                 "{%0,%1,%2,%3}, {%4,%5,%6,%7}, {%8,%9}, {%0,%1,%2,%3};"
                 : "+f"(c[0]), "+f"(c[1]), "+f"(c[2]), "+f"(c[3])
                 : "r"(a[0]), "r"(a[1]), "r"(a[2]), "r"(a[3]), "r"(b[0]), "r"(b[1]));
}
#define CP16(d, s)   asm volatile("cp.async.cg.shared.global [%0], [%1], 16;" :: "r"(d), "l"(s))
#define CP_COMMIT()  asm volatile("cp.async.commit_group;")
#define CP_WAIT0()   asm volatile("cp.async.wait_group 0;")

__device__ __forceinline__ void split2(float x0, float x1, unsigned& H, unsigned& L) {
    bf16 h0 = __float2bfloat16(x0), h1 = __float2bfloat16(x1);
    bf16 l0 = __float2bfloat16(x0 - __bfloat162float(h0));
    bf16 l1 = __float2bfloat16(x1 - __bfloat162float(h1));
    H = (unsigned)__bfloat16_as_ushort(h0) | ((unsigned)__bfloat16_as_ushort(h1) << 16);
    L = (unsigned)__bfloat16_as_ushort(l0) | ((unsigned)__bfloat16_as_ushort(l1) << 16);
}
__device__ __forceinline__ void split2h(float x0, float x1, unsigned& H, unsigned& L) {
    __half h0 = __float2half_rn(x0), h1 = __float2half_rn(x1);
    __half l0 = __float2half_rn(x0 - __half2float(h0));
    __half l1 = __float2half_rn(x1 - __half2float(h1));
    H = (unsigned)__half_as_ushort(h0) | ((unsigned)__half_as_ushort(h1) << 16);
    L = (unsigned)__half_as_ushort(l0) | ((unsigned)__half_as_ushort(l1) << 16);
}
__device__ __forceinline__ unsigned pack2h(float x0, float x1) {
    __half2 h = __floats2half2_rn(x0, x1);
    return *reinterpret_cast<unsigned*>(&h);
}

struct CvtSet { const float* s[4]; bf16* h[4]; bf16* l[4]; int n4; int f16; };
__global__ void __launch_bounds__(256) convert_multi(CvtSet p) {
    int y = blockIdx.y;
    int i = blockIdx.x * 256 + threadIdx.x;
    if (i >= p.n4) return;
    float4 v = ((const float4*)p.s[y])[i];
    unsigned h01, l01, h23, l23;
    if (p.f16) { split2h(v.x, v.y, h01, l01); split2h(v.z, v.w, h23, l23); }
    else       { split2(v.x, v.y, h01, l01);  split2(v.z, v.w, h23, l23); }
    ((uint2*)p.h[y])[i] = make_uint2(h01, h23);
    ((uint2*)p.l[y])[i] = make_uint2(l01, l23);
}

// GEMM parameter block
struct GP {
    const bf16 *Ahi, *Alo, *Bhi, *Blo;
    float* Cf; bf16 *Chi, *Clo;
    const float *bias, *gM, *gI;
    int K;
};
struct GP3 { GP g[3]; };

// ---------------------------------------------------------------------------
// mma.sync split GEMM (BK=32, 2-stage cp.async, one sync per chunk).
// MODE 0: QKV proj, bf16 3-term. z==2 (V) epilogue splits to fp16; else bf16.
// MODE 1: out proj, fp16 2-term (A = Ohi single plane, B = Wo hi/lo). +bias.
// MODE 3: attn@V,  fp16 2-term (A = fp16(p) single plane, B = Vt hi/lo).
//         normalizes attn in place via gM/gI; epilogue -> Ohi fp16.
// ---------------------------------------------------------------------------
template<int BN, int MODE>
__global__ void __launch_bounds__(256, 2)
gemm_mma(GP3 P)
{
    constexpr int BM = 128, BK = 32, BKP = 40;
    constexpr int ASZ = BM * BKP * 2;
    constexpr int BSZ = BN * BKP * 2;
    constexpr int APL   = (MODE == 1 || MODE == 3) ? 1 : 2;   // A smem planes
    constexpr int TERMS = (MODE == 1 || MODE == 3) ? 2 : 3;
    constexpr bool F16  = (MODE == 1 || MODE == 3);
    constexpr int STAGE = APL * ASZ + 2 * BSZ;
    constexpr int NF = BN / 16;
    constexpr int BV = BN / 64;

    GP p = P.g[MODE == 0 ? blockIdx.z : 0];
    extern __shared__ char smem[];
    const uint32_t sbase = s2u(smem);
    __shared__ float sM[128], sI[128];

    const int t = threadIdx.x, l = t & 31, wid = t >> 5;
    const int wm = wid & 3, wn = wid >> 2;
    const int gid = l >> 2, tig = l & 3;
    const int bc = blockIdx.x, br = blockIdx.y, z = blockIdx.z;

    const bf16 *Ah = p.Ahi, *Al = p.Alo, *Bh = p.Bhi, *Bl = p.Blo;
    float* Aw = nullptr;
    if (MODE == 3) {
        Aw = p.Cf + ((size_t)((z & 15) * BI + (z >> 4))) * LI * LI;
        size_t o = (size_t)z * 64 * LI; Bh += o; Bl += o;
        if (t < 128) {
            size_t r = (size_t)z * LI + br * 128 + t;
            sM[t] = p.gM[r]; sI[t] = p.gI[r];
        }
        __syncthreads();
    }
    const int K = p.K;

    int aoff[2], boff[NF / 2];
    #pragma unroll
    for (int mi = 0; mi < 2; mi++)
        aoff[mi] = ((wm * 32 + mi * 16 + (l & 15)) * BKP + ((l & 16) >> 1)) * 2;
    #pragma unroll
    for (int pp = 0; pp < NF / 2; pp++)
        boff[pp] = ((wn * (BN / 2) + pp * 16 + (l & 7) + ((l >> 1) & 8)) * BKP + (l & 8)) * 2;

    float acc[2][NF][4];
    #pragma unroll
    for (int mi = 0; mi < 2; mi++)
        #pragma unroll
        for (int ni = 0; ni < NF; ni++)
            #pragma unroll
            for (int c = 0; c < 4; c++) acc[mi][ni][c] = 0.f;

    const int n = K / BK;
    float4 raf[4];

    auto issue = [&](int ck) {
        int k0 = ck * BK;
        uint32_t sd = sbase + (ck & 1) * STAGE;
        if (MODE != 3) {
            #pragma unroll
            for (int i = 0; i < 2; i++) {
                int vi = t + i * 256, row = vi >> 2, kc = (vi & 3) * 8;
                uint32_t off = (uint32_t)(row * BKP + kc) * 2;
                size_t g = (size_t)(br * 128 + row) * K + k0 + kc;
                CP16(sd + off, Ah + g);
                if (APL == 2) CP16(sd + ASZ + off, Al + g);
            }
        }
        #pragma unroll
        for (int i = 0; i < BV; i++) {
            int vi = t + i * 256, row = vi >> 2, kc = (vi & 3) * 8;
            uint32_t off = (uint32_t)(row * BKP + kc) * 2;
            size_t g = (size_t)(bc * BN + row) * K + k0 + kc;
            CP16(sd + APL * ASZ + off,       Bh + g);
            CP16(sd + APL * ASZ + BSZ + off, Bl + g);
        }
    };
    auto ldg3 = [&](int ck) {
        int k0 = ck * BK;
        #pragma unroll
        for (int i = 0; i < 4; i++) {
            int vi = t + i * 256, row = vi >> 3, kc = (vi & 7) * 4;
            raf[i] = *(const float4*)(Aw + (size_t)(br * 128 + row) * K + k0 + kc);
        }
    };
    auto proc3 = [&](int ck) {
        int k0 = ck * BK;
        char* st = smem + (ck & 1) * STAGE;
        #pragma unroll
        for (int i = 0; i < 4; i++) {
            int vi = t + i * 256, row = vi >> 3, kc = (vi & 7) * 4;
            float M = sM[row], I = sI[row];
            float4 v = raf[i];
            v.x = __expf(v.x - M) * I; v.y = __expf(v.y - M) * I;
            v.z = __expf(v.z - M) * I; v.w = __expf(v.w - M) * I;
            *(float4*)(Aw + (size_t)(br * 128 + row) * K + k0 + kc) = v;
            *(uint2*)(st + (row * BKP + kc) * 2) =
                make_uint2(pack2h(v.x, v.y), pack2h(v.z, v.w));
        }
    };
    auto compute = [&](int buf) {
        uint32_t sb = sbase + buf * STAGE;
        #pragma unroll
        for (int ks = 0; ks < 2; ks++) {
            int kb = ks * 32;
            uint32_t ah[2][4], al[2][4];
            #pragma unroll
            for (int mi = 0; mi < 2; mi++) {
                ldm4(ah[mi], sb + aoff[mi] + kb);
                if (TERMS == 3) ldm4(al[mi], sb + ASZ + aoff[mi] + kb);
            }
            uint32_t bh[NF][2], bl[NF][2];
            #pragma unroll
            for (int pp = 0; pp < NF / 2; pp++) {
                uint32_t r[4];
                ldm4(r, sb + APL * ASZ + boff[pp] + kb);
                bh[2*pp][0] = r[0]; bh[2*pp][1] = r[1]; bh[2*pp+1][0] = r[2]; bh[2*pp+1][1] = r[3];
                ldm4(r, sb + APL * ASZ + BSZ + boff[pp] + kb);
                bl[2*pp][0] = r[0]; bl[2*pp][1] = r[1]; bl[2*pp+1][0] = r[2]; bl[2*pp+1][1] = r[3];
            }
            #pragma unroll
            for (int mi = 0; mi < 2; mi++)
                #pragma unroll
                for (int ni = 0; ni < NF; ni++) {
                    if (F16) mma_fp(acc[mi][ni], ah[mi], bh[ni]);
                    else     mma_bf(acc[mi][ni], ah[mi], bh[ni]);
                }
            #pragma unroll
            for (int mi = 0; mi < 2; mi++)
                #pragma unroll
                for (int ni = 0; ni < NF; ni++) {
                    if (F16) mma_fp(acc[mi][ni], ah[mi], bl[ni]);
                    else     mma_bf(acc[mi][ni], ah[mi], bl[ni]);
                }
            if (TERMS == 3) {
                #pragma unroll
                for (int mi = 0; mi < 2; mi++)
                    #pragma unroll
                    for (int ni = 0; ni < NF; ni++)
                        mma_bf(acc[mi][ni], al[mi], bh[ni]);
            }
        }
    };

    // pipeline: 2-stage ring, one sync per chunk (issue after barrier)
    if (MODE == 3) { ldg3(0); issue(0); proc3(0); }
    else           { issue(0); }
    CP_COMMIT();
    for (int ck = 0; ck < n; ck++) {
        CP_WAIT0();
        __syncthreads();
        if (ck + 1 < n) { issue(ck + 1); if (MODE == 3) ldg3(ck + 1); }
        compute(ck & 1);
        if (MODE == 3 && ck + 1 < n) proc3(ck + 1);
        CP_COMMIT();
    }

    // epilogue
    #pragma unroll
    for (int mi = 0; mi < 2; mi++)
        #pragma unroll
        for (int ni = 0; ni < NF; ni++)
            #pragma unroll
            for (int h = 0; h < 2; h++) {
                int gi = br * 128 + wm * 32 + mi * 16 + gid + h * 8;
                int gj = bc * BN + wn * (BN / 2) + ni * 8 + tig * 2;
                float v0 = acc[mi][ni][h * 2 + 0];
                float v1 = acc[mi][ni][h * 2 + 1];
                if (MODE == 1) {
                    v0 += p.bias[gj]; v1 += p.bias[gj + 1];
                    *(float2*)&p.Cf[(size_t)gi * DI + gj] = make_float2(v0, v1);
                } else if (MODE == 0) {
                    v0 += p.bias[gj]; v1 += p.bias[gj + 1];
                    unsigned H, L;
                    if (z == 2) split2h(v0, v1, H, L);   // V -> fp16 planes
                    else        split2(v0, v1, H, L);    // Q,K -> bf16 planes
                    size_t e = (((size_t)((gi >> 11) * HI + (gj >> 6)) * LI + (gi & 2047)) << 6) + (gj & 63);
                    ((unsigned*)p.Chi)[e >> 1] = H;
                    ((unsigned*)p.Clo)[e >> 1] = L;
                } else { // MODE 3: single fp16 plane output
                    size_t e = ((size_t)(z >> 4) * LI + gi) * DI + (z & 15) * 64 + gj;
                    ((unsigned*)p.Chi)[e >> 1] = pack2h(v0, v1);
                }
            }
}

// ---------------------------------------------------------------------------
// Scores kernel (persistent row-block, bf16 3-term): grid (br=16, z=64).
// Q tile loaded once; loop over 16 K-column tiles (2 BK=32 chunks each,
// double-buffered B ring, one sync per chunk). Online softmax stats -> M, 1/S.
// Writes raw scaled+masked scores to attn.
// ---------------------------------------------------------------------------
__global__ void __launch_bounds__(256, 2)
scores_mma(const bf16* __restrict__ Qhi, const bf16* __restrict__ Qlo,
           const bf16* __restrict__ Khi, const bf16* __restrict__ Klo,
           float* __restrict__ attn, float* __restrict__ gM, float* __restrict__ gI)
{
    constexpr int BKP = 40;
    constexpr int PAN = 128 * BKP * 2;          // 10240 B: one plane, one 32-k panel
    extern __shared__ char smem[];
    const uint32_t sbase = s2u(smem);
    __shared__ float sm_m[2][128], sm_s[2][128];

    const int t = threadIdx.x, l = t & 31, wid = t >> 5;
    const int wm = wid & 3, wn = wid >> 2;
    const int gid = l >> 2, tig = l & 3;
    const int br = blockIdx.x, z = blockIdx.y;

    const bf16* Ah = Qhi + (size_t)z * LI * 64;
    const bf16* Al = Qlo + (size_t)z * LI * 64;
    const bf16* Bh = Khi + (size_t)z * LI * 64;
    const bf16* Bl = Klo + (size_t)z * LI * 64;
    float* Cf = attn + ((size_t)((z & 15) * BI + (z >> 4))) * LI * LI;

    int aoff[2], boff[4];
    #pragma unroll
    for (int mi = 0; mi < 2; mi++)
        aoff[mi] = ((wm * 32 + mi * 16 + (l & 15)) * BKP + ((l & 16) >> 1)) * 2;
    #pragma unroll
    for (int pp = 0; pp < 4; pp++)
        boff[pp] = ((wn * 64 + pp * 16 + (l & 7) + ((l >> 1) & 8)) * BKP + (l & 8)) * 2;

    // issue full A tile once: 2 panels x 2 planes, 512 CP16 per plane-panel
    #pragma unroll
    for (int ck = 0; ck < 2; ck++)
        #pragma unroll
        for (int i = 0; i < 2; i++) {
            int vi = t + i * 256, row = vi >> 2, kc = (vi & 3) * 8;
            uint32_t off = (uint32_t)(row * BKP + kc) * 2;
            size_t g = (size_t)(br * 128 + row) * 64 + ck * 32 + kc;
            CP16(sbase + ck * 2 * PAN + off,       Ah + g);
            CP16(sbase + ck * 2 * PAN + PAN + off, Al + g);
        }
    CP_COMMIT();

    auto issueB = [&](int s) {        // s = bc*2 + ck  -> ring slot s&1
        int bc = s >> 1, ck = s & 1;
        uint32_t sd = sbase + 4 * PAN + (s & 1) * 2 * PAN;
        #pragma unroll
        for (int i = 0; i < 2; i++) {
            int vi = t + i * 256, row = vi >> 2, kc = (vi & 3) * 8;
            uint32_t off = (uint32_t)(row * BKP + kc) * 2;
            size_t g = (size_t)(bc * 128 + row) * 64 + ck * 32 + kc;
            CP16(sd + off,       Bh + g);
            CP16(sd + PAN + off, Bl + g);
        }
    };

    float acc[2][8][4];
    #pragma unroll
    for (int mi = 0; mi < 2; mi++)
        #pragma unroll
        for (int ni = 0; ni < 8; ni++)
            #pragma unroll
            for (int c = 0; c < 4; c++) acc[mi][ni][c] = 0.f;

    float rm[2][2], rs[2][2];
    #pragma unroll
    for (int mi = 0; mi < 2; mi++)
        #pragma unroll
        for (int h = 0; h < 2; h++) { rm[mi][h] = -INFINITY; rs[mi][h] = 0.f; }

    issueB(0); CP_COMMIT();

    for (int s = 0; s < 32; s++) {
        CP_WAIT0();
        __syncthreads();
        if (s + 1 < 32) issueB(s + 1);
        CP_COMMIT();

        {
            int ck = s & 1;
            uint32_t ab = sbase + ck * 2 * PAN;
            uint32_t bb = sbase + 4 * PAN + ck * 2 * PAN;
            #pragma unroll
            for (int ks = 0; ks < 2; ks++) {
                int kb = ks * 32;
                uint32_t ah[2][4], al[2][4];
                #pragma unroll
                for (int mi = 0; mi < 2; mi++) {
                    ldm4(ah[mi], ab + aoff[mi] + kb);
                    ldm4(al[mi], ab + PAN + aoff[mi] + kb);
                }
                uint32_t bhf[8][2], blf[8][2];
                #pragma unroll
                for (int pp = 0; pp < 4; pp++) {
                    uint32_t r[4];
                    ldm4(r, bb + boff[pp] + kb);
                    bhf[2*pp][0] = r[0]; bhf[2*pp][1] = r[1]; bhf[2*pp+1][0] = r[2]; bhf[2*pp+1][1] = r[3];
                    ldm4(r, bb + PAN + boff[pp] + kb);
                    blf[2*pp][0] = r[0]; blf[2*pp][1] = r[1]; blf[2*pp+1][0] = r[2]; blf[2*pp+1][1] = r[3];
                }
                #pragma unroll
                for (int mi = 0; mi < 2; mi++)
                    #pragma unroll
                    for (int ni = 0; ni < 8; ni++)
                        mma_bf(acc[mi][ni], ah[mi], bhf[ni]);
                #pragma unroll
                for (int mi = 0; mi < 2; mi++)
                    #pragma unroll
                    for (int ni = 0; ni < 8; ni++)
                        mma_bf(acc[mi][ni], ah[mi], blf[ni]);
                #pragma unroll
                for (int mi = 0; mi < 2; mi++)
                    #pragma unroll
                    for (int ni = 0; ni < 8; ni++)
                        mma_bf(acc[mi][ni], al[mi], bhf[ni]);
            }
        }

        if (s & 1) {
            int bc = s >> 1;
            #pragma unroll
            for (int mi = 0; mi < 2; mi++)
                #pragma unroll
                for (int ni = 0; ni < 8; ni++)
                    #pragma unroll
                    for (int c = 0; c < 4; c++) {
                        int gi = br * 128 + wm * 32 + mi * 16 + gid + (c >> 1) * 8;
                        int gj = bc * 128 + wn * 64 + ni * 8 + tig * 2 + (c & 1);
                        float v = acc[mi][ni][c] * 0.125f;
                        if (gi == gj) v = -INFINITY;
                        acc[mi][ni][c] = v;
                    }
            #pragma unroll
            for (int mi = 0; mi < 2; mi++)
                #pragma unroll
                for (int ni = 0; ni < 8; ni++)
                    #pragma unroll
                    for (int h = 0; h < 2; h++) {
                        int gi = br * 128 + wm * 32 + mi * 16 + gid + h * 8;
                        int gj = bc * 128 + wn * 64 + ni * 8 + tig * 2;
                        *(float2*)&Cf[(size_t)gi * LI + gj] =
                            make_float2(acc[mi][ni][h * 2], acc[mi][ni][h * 2 + 1]);
                    }
            #pragma unroll
            for (int mi = 0; mi < 2; mi++)
                #pragma unroll
                for (int h = 0; h < 2; h++) {
                    float m = -INFINITY;
                    #pragma unroll
                    for (int ni = 0; ni < 8; ni++) {
                        m = fmaxf(m, acc[mi][ni][h * 2 + 0]);
                        m = fmaxf(m, acc[mi][ni][h * 2 + 1]);
                    }
                    m = fmaxf(m, __shfl_xor_sync(0xffffffffu, m, 1));
                    m = fmaxf(m, __shfl_xor_sync(0xffffffffu, m, 2));
                    float sl = 0.f;
                    #pragma unroll
                    for (int ni = 0; ni < 8; ni++) {
                        sl += __expf(acc[mi][ni][h * 2 + 0] - m);
                        sl += __expf(acc[mi][ni][h * 2 + 1] - m);
                    }
                    sl += __shfl_xor_sync(0xffffffffu, sl, 1);
                    sl += __shfl_xor_sync(0xffffffffu, sl, 2);
                    float mo = rm[mi][h];
                    float mn = fmaxf(mo, m);
                    rs[mi][h] = rs[mi][h] * __expf(mo - mn) + sl * __expf(m - mn);
                    rm[mi][h] = mn;
                }
            #pragma unroll
            for (int mi = 0; mi < 2; mi++)
                #pragma unroll
                for (int ni = 0; ni < 8; ni++)
                    #pragma unroll
                    for (int c = 0; c < 4; c++) acc[mi][ni][c] = 0.f;
        }
    }

    #pragma unroll
    for (int mi = 0; mi < 2; mi++)
        #pragma unroll
        for (int h = 0; h < 2; h++) {
            int rl = wm * 32 + mi * 16 + h * 8 + gid;
            if (tig == 0) { sm_m[wn][rl] = rm[mi][h]; sm_s[wn][rl] = rs[mi][h]; }
        }
    __syncthreads();
    if (t < 128) {
        float m0 = sm_m[0][t], m1 = sm_m[1][t];
        float s0 = sm_s[0][t], s1 = sm_s[1][t];
        float m = fmaxf(m0, m1);
        float ssum = s0 * __expf(m0 - m) + s1 * __expf(m1 - m);
        size_t r = (size_t)z * LI + br * 128 + t;
        gM[r] = m; gI[r] = 1.f / ssum;
    }
}

// ---------------- V transpose (hi+lo, 16-bit agnostic) ----------------
__global__ void __launch_bounds__(256) transpose_bf(const bf16* __restrict__ ih, const bf16* __restrict__ il,
                                                    bf16* __restrict__ oh, bf16* __restrict__ ol) {
    __shared__ bf16 th[32][33], tl[32][33];
    int z = blockIdx.z, l0 = blockIdx.y * 32, d0 = blockIdx.x * 32;
    int x = threadIdx.x, y = threadIdx.y;
    #pragma unroll
    for (int i = 0; i < 32; i += 8) {
        size_t g = ((size_t)z * LI + l0 + y + i) * 64 + d0 + x;
        th[y + i][x] = ih[g]; tl[y + i][x] = il[g];
    }
    __syncthreads();
    #pragma unroll
    for (int i = 0; i < 32; i += 8) {
        size_t g = ((size_t)z * 64 + d0 + y + i) * LI + l0 + x;
        oh[g] = th[x][y + i]; ol[g] = tl[x][y + i];
    }
}

// ---------------- residual + LayerNorm ----------------
__device__ __forceinline__ float warpSum(float v) {
    #pragma unroll
    for (int o = 16; o; o >>= 1) v += __shfl_xor_sync(0xffffffffu, v, o);
    return v;
}
__global__ void __launch_bounds__(256) ln_kernel(const float* __restrict__ o2, const float* __restrict__ res,
                                                 const float* __restrict__ gamma, const float* __restrict__ beta,
                                                 float* __restrict__ out) {
    size_t row = blockIdx.x;
    int t = threadIdx.x;
    float4 a = ((const float4*)(o2 + row * DI))[t];
    float4 r = ((const float4*)(res + row * DI))[t];
    float x0 = a.x + r.x, x1 = a.y + r.y, x2 = a.z + r.z, x3 = a.w + r.w;
    float s = x0 + x1 + x2 + x3, sq = x0 * x0 + x1 * x1 + x2 * x2 + x3 * x3;
    s = warpSum(s); sq = warpSum(sq);
    __shared__ float rs[8], rq[8];
    if ((t & 31) == 0) { rs[t >> 5] = s; rq[t >> 5] = sq; }
    __syncthreads();
    s = 0.f; sq = 0.f;
    #pragma unroll
    for (int i = 0; i < 8; i++) { s += rs[i]; sq += rq[i]; }
    float mu = s * (1.0f / DI);
    float rstd = rsqrtf(sq * (1.0f / DI) - mu * mu + 1e-5f);
    float4 g = ((const float4*)gamma)[t], b = ((const float4*)beta)[t];
    float4 o;
    o.x = (x0 - mu) * rstd * g.x + b.x; o.y = (x1 - mu) * rstd * g.y + b.y;
    o.z = (x2 - mu) * rstd * g.z + b.z; o.w = (x3 - mu) * rstd * g.w + b.w;
    ((float4*)(out + row * DI))[t] = o;
}

// ---------------------------------------------------------------------------
extern "C" void kernel_launch(void* const* d_in, const int* in_sizes, int n_in,
                              void* d_out, int out_size)
{
    const float* q  = (const float*)d_in[0];
    const float* k  = (const float*)d_in[1];
    const float* v  = (const float*)d_in[2];
    const float* Wq = (const float*)d_in[3];  const float* bq = (const float*)d_in[4];
    const float* Wk = (const float*)d_in[5];  const float* bk = (const float*)d_in[6];
    const float* Wv = (const float*)d_in[7];  const float* bv = (const float*)d_in[8];
    const float* Wo = (const float*)d_in[9];  const float* bo = (const float*)d_in[10];
    const float* gamma = (const float*)d_in[11];
    const float* beta  = (const float*)d_in[12];

    float* out  = (float*)d_out;
    float* attn = out + (size_t)BI * LI * DI;

    bf16 *qhi,*qlo,*khi,*klo,*vhi,*vlo,*wqh,*wql,*wkh,*wkl,*wvh,*wvl,*woh,*wol;
    bf16 *Qhi,*Qlo,*Khi,*Klo,*VHh,*VHl,*Vth,*Vtl,*Ohi;
    float *O2, *M, *I;
    cudaGetSymbolAddress((void**)&qhi, g_qhi);  cudaGetSymbolAddress((void**)&qlo, g_qlo);
    cudaGetSymbolAddress((void**)&khi, g_khi);  cudaGetSymbolAddress((void**)&klo, g_klo);
    cudaGetSymbolAddress((void**)&vhi, g_vhi);  cudaGetSymbolAddress((void**)&vlo, g_vlo);
    cudaGetSymbolAddress((void**)&wqh, g_wqhi); cudaGetSymbolAddress((void**)&wql, g_wqlo);
    cudaGetSymbolAddress((void**)&wkh, g_wkhi); cudaGetSymbolAddress((void**)&wkl, g_wklo);
    cudaGetSymbolAddress((void**)&wvh, g_wvhi); cudaGetSymbolAddress((void**)&wvl, g_wvlo);
    cudaGetSymbolAddress((void**)&woh, g_wohi); cudaGetSymbolAddress((void**)&wol, g_wolo);
    cudaGetSymbolAddress((void**)&Qhi, g_Qhi);  cudaGetSymbolAddress((void**)&Qlo, g_Qlo);
    cudaGetSymbolAddress((void**)&Khi, g_Khi);  cudaGetSymbolAddress((void**)&Klo, g_Klo);
    cudaGetSymbolAddress((void**)&VHh, g_VHhi); cudaGetSymbolAddress((void**)&VHl, g_VHlo);
    cudaGetSymbolAddress((void**)&Vth, g_Vthi); cudaGetSymbolAddress((void**)&Vtl, g_Vtlo);
    cudaGetSymbolAddress((void**)&Ohi, g_Ohi);
    cudaGetSymbolAddress((void**)&O2,  g_O2);
    cudaGetSymbolAddress((void**)&M,   g_M);    cudaGetSymbolAddress((void**)&I,   g_I);

    const int SM0  = 2 * (2*128*40*2 + 2*128*40*2);   // 81920 (MODE0)
    const int SM1  = 2 * (1*128*40*2 + 2*128*40*2);   // 61440 (MODE1)
    const int SM3  = 2 * (1*128*40*2 + 2*64*40*2);    // 40960 (MODE3)
    const int SMSC = 81920;
    cudaFuncSetAttribute(gemm_mma<128,0>, cudaFuncAttributeMaxDynamicSharedMemorySize, SM0);
    cudaFuncSetAttribute(gemm_mma<128,1>, cudaFuncAttributeMaxDynamicSharedMemorySize, SM1);
    cudaFuncSetAttribute(gemm_mma<64,3>,  cudaFuncAttributeMaxDynamicSharedMemorySize, SM3);
    cudaFuncSetAttribute(scores_mma,      cudaFuncAttributeMaxDynamicSharedMemorySize, SMSC);

    // input splits (bf16)
    CvtSet ci; ci.s[0]=q; ci.s[1]=k; ci.s[2]=v; ci.s[3]=q;
    ci.h[0]=qhi; ci.h[1]=khi; ci.h[2]=vhi; ci.h[3]=qhi;
    ci.l[0]=qlo; ci.l[1]=klo; ci.l[2]=vlo; ci.l[3]=qlo;
    ci.n4 = 2097152; ci.f16 = 0;
    convert_multi<<<dim3(8192,3), 256>>>(ci);
    // weight splits: Wq,Wk,Wv bf16
    CvtSet cw; cw.s[0]=Wq; cw.s[1]=Wk; cw.s[2]=Wv; cw.s[3]=Wq;
    cw.h[0]=wqh; cw.h[1]=wkh; cw.h[2]=wvh; cw.h[3]=wqh;
    cw.l[0]=wql; cw.l[1]=wkl; cw.l[2]=wvl; cw.l[3]=wql;
    cw.n4 = 262144; cw.f16 = 0;
    convert_multi<<<dim3(1024,3), 256>>>(cw);
    // Wo split: fp16
    CvtSet co; co.s[0]=Wo; co.s[1]=Wo; co.s[2]=Wo; co.s[3]=Wo;
    co.h[0]=woh; co.h[1]=woh; co.h[2]=woh; co.h[3]=woh;
    co.l[0]=wol; co.l[1]=wol; co.l[2]=wol; co.l[3]=wol;
    co.n4 = 262144; co.f16 = 1;
    convert_multi<<<dim3(1024,1), 256>>>(co);

    // merged QKV projections (bf16 3-term; V epilogue -> fp16 planes)
    GP3 P; memset(&P, 0, sizeof(P));
    P.g[0] = { qhi,qlo, wqh,wql, nullptr,Qhi,Qlo, bq, nullptr,nullptr, DI };
    P.g[1] = { khi,klo, wkh,wkl, nullptr,Khi,Klo, bk, nullptr,nullptr, DI };
    P.g[2] = { vhi,vlo, wvh,wvl, nullptr,VHh,VHl, bv, nullptr,nullptr, DI };
    gemm_mma<128,0><<<dim3(8,64,3), 256, SM0>>>(P);

    transpose_bf<<<dim3(2,64,64), dim3(32,8)>>>(VHh, VHl, Vth, Vtl);

    // persistent scores + online softmax stats (bf16 3-term)
    scores_mma<<<dim3(16,64), 256, SMSC>>>(Qhi,Qlo, Khi,Klo, attn, M, I);

    // fused normalize + attn write + attn @ V (fp16 2-term) -> Ohi (fp16)
    GP3 P3; memset(&P3, 0, sizeof(P3));
    P3.g[0] = { nullptr,nullptr, Vth,Vtl, attn,Ohi,nullptr, nullptr, M,I, LI };
    gemm_mma<64,3><<<dim3(1,16,64), 256, SM3>>>(P3);

    // output projection (fp16 2-term) + residual/LN
    GP3 P4; memset(&P4, 0, sizeof(P4));
    P4.g[0] = { Ohi,nullptr, woh,wol, O2,nullptr,nullptr, bo, nullptr,nullptr, DI };
    gemm_mma<128,1><<<dim3(8,64,1), 256, SM1>>>(P4);
    ln_kernel<<<BI*LI, 256>>>(O2, q, gamma, beta, out);
}

// round 14
// speedup vs baseline: 1.0711x; 1.0200x over previous
#include <cuda_runtime.h>
#include <cuda_bf16.h>
#include <cuda_fp16.h>
#include <cstdint>
#include <math.h>

#define BI 4
#define LI 2048
#define DI 1024
#define HI 16

typedef __nv_bfloat16 bf16;
#define ELI ((size_t)8192*1024)
#define ELW ((size_t)1024*1024)

// device-global scratch (allocation-free rule). 16-bit buffers hold bf16 OR fp16 bits.
__device__ __align__(256) bf16 g_qhi[ELI], g_qlo[ELI], g_khi[ELI], g_klo[ELI], g_vhi[ELI], g_vlo[ELI];
__device__ __align__(256) bf16 g_wqhi[ELW], g_wqlo[ELW], g_wkhi[ELW], g_wklo[ELW];
__device__ __align__(256) bf16 g_wvhi[ELW], g_wvlo[ELW], g_wohi[ELW], g_wolo[ELW];
__device__ __align__(256) bf16 g_Qhi[ELI], g_Qlo[ELI], g_Khi[ELI], g_Klo[ELI];   // [bh][l][64] bf16
__device__ __align__(256) bf16 g_VHhi[ELI];                                      // [bh][l][64] fp16 (single plane)
__device__ __align__(256) bf16 g_Vthi[ELI];                                      // [bh][64][2048] fp16
__device__ __align__(256) bf16 g_Ohi[ELI];                                       // [8192][1024] fp16
__device__ __align__(256) float g_O2[ELI];
__device__ __align__(256) float g_M[(size_t)64*2048], g_I[(size_t)64*2048];

// ---------------- helpers ----------------
__device__ __forceinline__ uint32_t s2u(const void* p) {
    uint32_t a;
    asm("{ .reg .u64 t; cvta.to.shared.u64 t, %1; cvt.u32.u64 %0, t; }" : "=r"(a) : "l"(p));
    return a;
}
__device__ __forceinline__ void ldm4(uint32_t* r, uint32_t a) {
    asm volatile("ldmatrix.sync.aligned.m8n8.x4.shared.b16 {%0,%1,%2,%3}, [%4];"
                 : "=r"(r[0]), "=r"(r[1]), "=r"(r[2]), "=r"(r[3]) : "r"(a));
}
__device__ __forceinline__ void mma_bf(float* c, const uint32_t* a, const uint32_t* b) {
    asm volatile("mma.sync.aligned.m16n8k16.row.col.f32.bf16.bf16.f32 "
                 "{%0,%1,%2,%3}, {%4,%5,%6,%7}, {%8,%9}, {%0,%1,%2,%3};"
                 : "+f"(c[0]), "+f"(c[1]), "+f"(c[2]), "+f"(c[3])
                 : "r"(a[0]), "r"(a[1]), "r"(a[2]), "r"(a[3]), "r"(b[0]), "r"(b[1]));
}
__device__ __forceinline__ void mma_fp(float* c, const uint32_t* a, const uint32_t* b) {
    asm volatile("mma.sync.aligned.m16n8k16.row.col.f32.f16.f16.f32 "
                 "{%0,%1,%2,%3}, {%4,%5,%6,%7}, {%8,%9}, {%0,%1,%2,%3};"
                 : "+f"(c[0]), "+f"(c[1]), "+f"(c[2]), "+f"(c[3])
                 : "r"(a[0]), "r"(a[1]), "r"(a[2]), "r"(a[3]), "r"(b[0]), "r"(b[1]));
}
#define CP16(d, s)   asm volatile("cp.async.cg.shared.global [%0], [%1], 16;" :: "r"(d), "l"(s))
#define CP_COMMIT()  asm volatile("cp.async.commit_group;")
#define CP_WAIT0()   asm volatile("cp.async.wait_group 0;")

__device__ __forceinline__ void split2(float x0, float x1, unsigned& H, unsigned& L) {
    bf16 h0 = __float2bfloat16(x0), h1 = __float2bfloat16(x1);
    bf16 l0 = __float2bfloat16(x0 - __bfloat162float(h0));
    bf16 l1 = __float2bfloat16(x1 - __bfloat162float(h1));
    H = (unsigned)__bfloat16_as_ushort(h0) | ((unsigned)__bfloat16_as_ushort(h1) << 16);
    L = (unsigned)__bfloat16_as_ushort(l0) | ((unsigned)__bfloat16_as_ushort(l1) << 16);
}
__device__ __forceinline__ void split2h(float x0, float x1, unsigned& H, unsigned& L) {
    __half h0 = __float2half_rn(x0), h1 = __float2half_rn(x1);
    __half l0 = __float2half_rn(x0 - __half2float(h0));
    __half l1 = __float2half_rn(x1 - __half2float(h1));
    H = (unsigned)__half_as_ushort(h0) | ((unsigned)__half_as_ushort(h1) << 16);
    L = (unsigned)__half_as_ushort(l0) | ((unsigned)__half_as_ushort(l1) << 16);
}
__device__ __forceinline__ unsigned pack2h(float x0, float x1) {
    __half2 h = __floats2half2_rn(x0, x1);
    return *reinterpret_cast<unsigned*>(&h);
}

struct CvtSet { const float* s[4]; bf16* h[4]; bf16* l[4]; int n4; int f16; };
__global__ void __launch_bounds__(256) convert_multi(CvtSet p) {
    int y = blockIdx.y;
    int i = blockIdx.x * 256 + threadIdx.x;
    if (i >= p.n4) return;
    float4 v = ((const float4*)p.s[y])[i];
    unsigned h01, l01, h23, l23;
    if (p.f16) { split2h(v.x, v.y, h01, l01); split2h(v.z, v.w, h23, l23); }
    else       { split2(v.x, v.y, h01, l01);  split2(v.z, v.w, h23, l23); }
    ((uint2*)p.h[y])[i] = make_uint2(h01, h23);
    ((uint2*)p.l[y])[i] = make_uint2(l01, l23);
}

// GEMM parameter block
struct GP {
    const bf16 *Ahi, *Alo, *Bhi, *Blo;
    float* Cf; bf16 *Chi, *Clo;
    const float *bias, *gM, *gI;
    int K;
};
struct GP3 { GP g[3]; };

// ---------------------------------------------------------------------------
// mma.sync split GEMM (BK=32, 2-stage cp.async, one sync per chunk).
// MODE 0: QKV proj, bf16 3-term. z==2 (V) epilogue -> single fp16 plane.
// MODE 1: out proj, fp16 2-term (A = Ohi single plane, B = Wo hi/lo). +bias.
// MODE 3: attn@V,  fp16 1-term (A = fp16(p), B = Vt hi only).
//         normalizes attn in place via gM/gI; epilogue -> Ohi fp16.
// ---------------------------------------------------------------------------
template<int BN, int MODE>
__global__ void __launch_bounds__(256, 2)
gemm_mma(GP3 P)
{
    constexpr int BM = 128, BK = 32, BKP = 40;
    constexpr int ASZ = BM * BKP * 2;
    constexpr int BSZ = BN * BKP * 2;
    constexpr int APL   = (MODE == 1 || MODE == 3) ? 1 : 2;   // A smem planes
    constexpr int BPL   = (MODE == 3) ? 1 : 2;                // B smem planes
    constexpr int TERMS = (MODE == 0) ? 3 : (MODE == 1) ? 2 : 1;
    constexpr bool F16  = (MODE == 1 || MODE == 3);
    constexpr int STAGE = APL * ASZ + BPL * BSZ;
    constexpr int NF = BN / 16;
    constexpr int BV = BN / 64;

    GP p = P.g[MODE == 0 ? blockIdx.z : 0];
    extern __shared__ char smem[];
    const uint32_t sbase = s2u(smem);
    __shared__ float sM[128], sI[128];

    const int t = threadIdx.x, l = t & 31, wid = t >> 5;
    const int wm = wid & 3, wn = wid >> 2;
    const int gid = l >> 2, tig = l & 3;
    const int bc = blockIdx.x, br = blockIdx.y, z = blockIdx.z;

    const bf16 *Ah = p.Ahi, *Al = p.Alo, *Bh = p.Bhi, *Bl = p.Blo;
    float* Aw = nullptr;
    if (MODE == 3) {
        Aw = p.Cf + ((size_t)((z & 15) * BI + (z >> 4))) * LI * LI;
        size_t o = (size_t)z * 64 * LI; Bh += o;
        if (t < 128) {
            size_t r = (size_t)z * LI + br * 128 + t;
            sM[t] = p.gM[r]; sI[t] = p.gI[r];
        }
        __syncthreads();
    }
    const int K = p.K;

    int aoff[2], boff[NF / 2];
    #pragma unroll
    for (int mi = 0; mi < 2; mi++)
        aoff[mi] = ((wm * 32 + mi * 16 + (l & 15)) * BKP + ((l & 16) >> 1)) * 2;
    #pragma unroll
    for (int pp = 0; pp < NF / 2; pp++)
        boff[pp] = ((wn * (BN / 2) + pp * 16 + (l & 7) + ((l >> 1) & 8)) * BKP + (l & 8)) * 2;

    float acc[2][NF][4];
    #pragma unroll
    for (int mi = 0; mi < 2; mi++)
        #pragma unroll
        for (int ni = 0; ni < NF; ni++)
            #pragma unroll
            for (int c = 0; c < 4; c++) acc[mi][ni][c] = 0.f;

    const int n = K / BK;
    float4 raf[4];

    auto issue = [&](int ck) {
        int k0 = ck * BK;
        uint32_t sd = sbase + (ck & 1) * STAGE;
        if (MODE != 3) {
            #pragma unroll
            for (int i = 0; i < 2; i++) {
                int vi = t + i * 256, row = vi >> 2, kc = (vi & 3) * 8;
                uint32_t off = (uint32_t)(row * BKP + kc) * 2;
                size_t g = (size_t)(br * 128 + row) * K + k0 + kc;
                CP16(sd + off, Ah + g);
                if (APL == 2) CP16(sd + ASZ + off, Al + g);
            }
        }
        #pragma unroll
        for (int i = 0; i < BV; i++) {
            int vi = t + i * 256, row = vi >> 2, kc = (vi & 3) * 8;
            uint32_t off = (uint32_t)(row * BKP + kc) * 2;
            size_t g = (size_t)(bc * BN + row) * K + k0 + kc;
            CP16(sd + APL * ASZ + off, Bh + g);
            if (BPL == 2) CP16(sd + APL * ASZ + BSZ + off, Bl + g);
        }
    };
    auto ldg3 = [&](int ck) {
        int k0 = ck * BK;
        #pragma unroll
        for (int i = 0; i < 4; i++) {
            int vi = t + i * 256, row = vi >> 3, kc = (vi & 7) * 4;
            raf[i] = *(const float4*)(Aw + (size_t)(br * 128 + row) * K + k0 + kc);
        }
    };
    auto proc3 = [&](int ck) {
        int k0 = ck * BK;
        char* st = smem + (ck & 1) * STAGE;
        #pragma unroll
        for (int i = 0; i < 4; i++) {
            int vi = t + i * 256, row = vi >> 3, kc = (vi & 7) * 4;
            float M = sM[row], I = sI[row];
            float4 v = raf[i];
            v.x = __expf(v.x - M) * I; v.y = __expf(v.y - M) * I;
            v.z = __expf(v.z - M) * I; v.w = __expf(v.w - M) * I;
            *(float4*)(Aw + (size_t)(br * 128 + row) * K + k0 + kc) = v;
            *(uint2*)(st + (row * BKP + kc) * 2) =
                make_uint2(pack2h(v.x, v.y), pack2h(v.z, v.w));
        }
    };
    auto compute = [&](int buf) {
        uint32_t sb = sbase + buf * STAGE;
        #pragma unroll
        for (int ks = 0; ks < 2; ks++) {
            int kb = ks * 32;
            uint32_t ah[2][4], al[2][4];
            #pragma unroll
            for (int mi = 0; mi < 2; mi++) {
                ldm4(ah[mi], sb + aoff[mi] + kb);
                if (TERMS == 3) ldm4(al[mi], sb + ASZ + aoff[mi] + kb);
            }
            uint32_t bh[NF][2], bl[NF][2];
            #pragma unroll
            for (int pp = 0; pp < NF / 2; pp++) {
                uint32_t r[4];
                ldm4(r, sb + APL * ASZ + boff[pp] + kb);
                bh[2*pp][0] = r[0]; bh[2*pp][1] = r[1]; bh[2*pp+1][0] = r[2]; bh[2*pp+1][1] = r[3];
                if (BPL == 2) {
                    ldm4(r, sb + APL * ASZ + BSZ + boff[pp] + kb);
                    bl[2*pp][0] = r[0]; bl[2*pp][1] = r[1]; bl[2*pp+1][0] = r[2]; bl[2*pp+1][1] = r[3];
                }
            }
            #pragma unroll
            for (int mi = 0; mi < 2; mi++)
                #pragma unroll
                for (int ni = 0; ni < NF; ni++) {
                    if (F16) mma_fp(acc[mi][ni], ah[mi], bh[ni]);
                    else     mma_bf(acc[mi][ni], ah[mi], bh[ni]);
                }
            if (TERMS >= 2) {
                #pragma unroll
                for (int mi = 0; mi < 2; mi++)
                    #pragma unroll
                    for (int ni = 0; ni < NF; ni++) {
                        if (F16) mma_fp(acc[mi][ni], ah[mi], bl[ni]);
                        else     mma_bf(acc[mi][ni], ah[mi], bl[ni]);
                    }
            }
            if (TERMS == 3) {
                #pragma unroll
                for (int mi = 0; mi < 2; mi++)
                    #pragma unroll
                    for (int ni = 0; ni < NF; ni++)
                        mma_bf(acc[mi][ni], al[mi], bh[ni]);
            }
        }
    };

    // pipeline: 2-stage ring, one sync per chunk (issue after barrier)
    if (MODE == 3) { ldg3(0); issue(0); proc3(0); }
    else           { issue(0); }
    CP_COMMIT();
    for (int ck = 0; ck < n; ck++) {
        CP_WAIT0();
        __syncthreads();
        if (ck + 1 < n) { issue(ck + 1); if (MODE == 3) ldg3(ck + 1); }
        compute(ck & 1);
        if (MODE == 3 && ck + 1 < n) proc3(ck + 1);
        CP_COMMIT();
    }

    // epilogue
    #pragma unroll
    for (int mi = 0; mi < 2; mi++)
        #pragma unroll
        for (int ni = 0; ni < NF; ni++)
            #pragma unroll
            for (int h = 0; h < 2; h++) {
                int gi = br * 128 + wm * 32 + mi * 16 + gid + h * 8;
                int gj = bc * BN + wn * (BN / 2) + ni * 8 + tig * 2;
                float v0 = acc[mi][ni][h * 2 + 0];
                float v1 = acc[mi][ni][h * 2 + 1];
                if (MODE == 1) {
                    v0 += p.bias[gj]; v1 += p.bias[gj + 1];
                    *(float2*)&p.Cf[(size_t)gi * DI + gj] = make_float2(v0, v1);
                } else if (MODE == 0) {
                    v0 += p.bias[gj]; v1 += p.bias[gj + 1];
                    size_t e = (((size_t)((gi >> 11) * HI + (gj >> 6)) * LI + (gi & 2047)) << 6) + (gj & 63);
                    if (z == 2) {
                        ((unsigned*)p.Chi)[e >> 1] = pack2h(v0, v1);   // V -> single fp16 plane
                    } else {
                        unsigned H, L;
                        split2(v0, v1, H, L);                          // Q,K -> bf16 hi/lo
                        ((unsigned*)p.Chi)[e >> 1] = H;
                        ((unsigned*)p.Clo)[e >> 1] = L;
                    }
                } else { // MODE 3: single fp16 plane output
                    size_t e = ((size_t)(z >> 4) * LI + gi) * DI + (z & 15) * 64 + gj;
                    ((unsigned*)p.Chi)[e >> 1] = pack2h(v0, v1);
                }
            }
}

// ---------------------------------------------------------------------------
// Scores kernel (persistent row-block, bf16 3-term): grid (br=16, z=64).
// Q tile loaded once; loop over 16 K-column tiles (2 BK=32 chunks each,
// double-buffered B ring, one sync per chunk). Online softmax stats -> M, 1/S.
// Writes raw scaled+masked scores to attn.
// ---------------------------------------------------------------------------
__global__ void __launch_bounds__(256, 2)
scores_mma(const bf16* __restrict__ Qhi, const bf16* __restrict__ Qlo,
           const bf16* __restrict__ Khi, const bf16* __restrict__ Klo,
           float* __restrict__ attn, float* __restrict__ gM, float* __restrict__ gI)
{
    constexpr int BKP = 40;
    constexpr int PAN = 128 * BKP * 2;          // 10240 B: one plane, one 32-k panel
    extern __shared__ char smem[];
    const uint32_t sbase = s2u(smem);
    __shared__ float sm_m[2][128], sm_s[2][128];

    const int t = threadIdx.x, l = t & 31, wid = t >> 5;
    const int wm = wid & 3, wn = wid >> 2;
    const int gid = l >> 2, tig = l & 3;
    const int br = blockIdx.x, z = blockIdx.y;

    const bf16* Ah = Qhi + (size_t)z * LI * 64;
    const bf16* Al = Qlo + (size_t)z * LI * 64;
    const bf16* Bh = Khi + (size_t)z * LI * 64;
    const bf16* Bl = Klo + (size_t)z * LI * 64;
    float* Cf = attn + ((size_t)((z & 15) * BI + (z >> 4))) * LI * LI;

    int aoff[2], boff[4];
    #pragma unroll
    for (int mi = 0; mi < 2; mi++)
        aoff[mi] = ((wm * 32 + mi * 16 + (l & 15)) * BKP + ((l & 16) >> 1)) * 2;
    #pragma unroll
    for (int pp = 0; pp < 4; pp++)
        boff[pp] = ((wn * 64 + pp * 16 + (l & 7) + ((l >> 1) & 8)) * BKP + (l & 8)) * 2;

    // issue full A tile once: 2 panels x 2 planes, 512 CP16 per plane-panel
    #pragma unroll
    for (int ck = 0; ck < 2; ck++)
        #pragma unroll
        for (int i = 0; i < 2; i++) {
            int vi = t + i * 256, row = vi >> 2, kc = (vi & 3) * 8;
            uint32_t off = (uint32_t)(row * BKP + kc) * 2;
            size_t g = (size_t)(br * 128 + row) * 64 + ck * 32 + kc;
            CP16(sbase + ck * 2 * PAN + off,       Ah + g);
            CP16(sbase + ck * 2 * PAN + PAN + off, Al + g);
        }
    CP_COMMIT();

    auto issueB = [&](int s) {        // s = bc*2 + ck  -> ring slot s&1
        int bc = s >> 1, ck = s & 1;
        uint32_t sd = sbase + 4 * PAN + (s & 1) * 2 * PAN;
        #pragma unroll
        for (int i = 0; i < 2; i++) {
            int vi = t + i * 256, row = vi >> 2, kc = (vi & 3) * 8;
            uint32_t off = (uint32_t)(row * BKP + kc) * 2;
            size_t g = (size_t)(bc * 128 + row) * 64 + ck * 32 + kc;
            CP16(sd + off,       Bh + g);
            CP16(sd + PAN + off, Bl + g);
        }
    };

    float acc[2][8][4];
    #pragma unroll
    for (int mi = 0; mi < 2; mi++)
        #pragma unroll
        for (int ni = 0; ni < 8; ni++)
            #pragma unroll
            for (int c = 0; c < 4; c++) acc[mi][ni][c] = 0.f;

    float rm[2][2], rs[2][2];
    #pragma unroll
    for (int mi = 0; mi < 2; mi++)
        #pragma unroll
        for (int h = 0; h < 2; h++) { rm[mi][h] = -INFINITY; rs[mi][h] = 0.f; }

    issueB(0); CP_COMMIT();

    for (int s = 0; s < 32; s++) {
        CP_WAIT0();
        __syncthreads();
        if (s + 1 < 32) issueB(s + 1);
        CP_COMMIT();

        {
            int ck = s & 1;
            uint32_t ab = sbase + ck * 2 * PAN;
            uint32_t bb = sbase + 4 * PAN + ck * 2 * PAN;
            #pragma unroll
            for (int ks = 0; ks < 2; ks++) {
                int kb = ks * 32;
                uint32_t ah[2][4], al[2][4];
                #pragma unroll
                for (int mi = 0; mi < 2; mi++) {
                    ldm4(ah[mi], ab + aoff[mi] + kb);
                    ldm4(al[mi], ab + PAN + aoff[mi] + kb);
                }
                uint32_t bhf[8][2], blf[8][2];
                #pragma unroll
                for (int pp = 0; pp < 4; pp++) {
                    uint32_t r[4];
                    ldm4(r, bb + boff[pp] + kb);
                    bhf[2*pp][0] = r[0]; bhf[2*pp][1] = r[1]; bhf[2*pp+1][0] = r[2]; bhf[2*pp+1][1] = r[3];
                    ldm4(r, bb + PAN + boff[pp] + kb);
                    blf[2*pp][0] = r[0]; blf[2*pp][1] = r[1]; blf[2*pp+1][0] = r[2]; blf[2*pp+1][1] = r[3];
                }
                #pragma unroll
                for (int mi = 0; mi < 2; mi++)
                    #pragma unroll
                    for (int ni = 0; ni < 8; ni++)
                        mma_bf(acc[mi][ni], ah[mi], bhf[ni]);
                #pragma unroll
                for (int mi = 0; mi < 2; mi++)
                    #pragma unroll
                    for (int ni = 0; ni < 8; ni++)
                        mma_bf(acc[mi][ni], ah[mi], blf[ni]);
                #pragma unroll
                for (int mi = 0; mi < 2; mi++)
                    #pragma unroll
                    for (int ni = 0; ni < 8; ni++)
                        mma_bf(acc[mi][ni], al[mi], bhf[ni]);
            }
        }

        if (s & 1) {
            int bc = s >> 1;
            #pragma unroll
            for (int mi = 0; mi < 2; mi++)
                #pragma unroll
                for (int ni = 0; ni < 8; ni++)
                    #pragma unroll
                    for (int c = 0; c < 4; c++) {
                        int gi = br * 128 + wm * 32 + mi * 16 + gid + (c >> 1) * 8;
                        int gj = bc * 128 + wn * 64 + ni * 8 + tig * 2 + (c & 1);
                        float v = acc[mi][ni][c] * 0.125f;
                        if (gi == gj) v = -INFINITY;
                        acc[mi][ni][c] = v;
                    }
            #pragma unroll
            for (int mi = 0; mi < 2; mi++)
                #pragma unroll
                for (int ni = 0; ni < 8; ni++)
                    #pragma unroll
                    for (int h = 0; h < 2; h++) {
                        int gi = br * 128 + wm * 32 + mi * 16 + gid + h * 8;
                        int gj = bc * 128 + wn * 64 + ni * 8 + tig * 2;
                        *(float2*)&Cf[(size_t)gi * LI + gj] =
                            make_float2(acc[mi][ni][h * 2], acc[mi][ni][h * 2 + 1]);
                    }
            #pragma unroll
            for (int mi = 0; mi < 2; mi++)
                #pragma unroll
                for (int h = 0; h < 2; h++) {
                    float m = -INFINITY;
                    #pragma unroll
                    for (int ni = 0; ni < 8; ni++) {
                        m = fmaxf(m, acc[mi][ni][h * 2 + 0]);
                        m = fmaxf(m, acc[mi][ni][h * 2 + 1]);
                    }
                    m = fmaxf(m, __shfl_xor_sync(0xffffffffu, m, 1));
                    m = fmaxf(m, __shfl_xor_sync(0xffffffffu, m, 2));
                    float sl = 0.f;
                    #pragma unroll
                    for (int ni = 0; ni < 8; ni++) {
                        sl += __expf(acc[mi][ni][h * 2 + 0] - m);
                        sl += __expf(acc[mi][ni][h * 2 + 1] - m);
                    }
                    sl += __shfl_xor_sync(0xffffffffu, sl, 1);
                    sl += __shfl_xor_sync(0xffffffffu, sl, 2);
                    float mo = rm[mi][h];
                    float mn = fmaxf(mo, m);
                    rs[mi][h] = rs[mi][h] * __expf(mo - mn) + sl * __expf(m - mn);
                    rm[mi][h] = mn;
                }
            #pragma unroll
            for (int mi = 0; mi < 2; mi++)
                #pragma unroll
                for (int ni = 0; ni < 8; ni++)
                    #pragma unroll
                    for (int c = 0; c < 4; c++) acc[mi][ni][c] = 0.f;
        }
    }

    #pragma unroll
    for (int mi = 0; mi < 2; mi++)
        #pragma unroll
        for (int h = 0; h < 2; h++) {
            int rl = wm * 32 + mi * 16 + h * 8 + gid;
            if (tig == 0) { sm_m[wn][rl] = rm[mi][h]; sm_s[wn][rl] = rs[mi][h]; }
        }
    __syncthreads();
    if (t < 128) {
        float m0 = sm_m[0][t], m1 = sm_m[1][t];
        float s0 = sm_s[0][t], s1 = sm_s[1][t];
        float m = fmaxf(m0, m1);
        float ssum = s0 * __expf(m0 - m) + s1 * __expf(m1 - m);
        size_t r = (size_t)z * LI + br * 128 + t;
        gM[r] = m; gI[r] = 1.f / ssum;
    }
}

// ---------------- V transpose (single plane): [bh][l][64] -> [bh][64][2048] --
__global__ void __launch_bounds__(256) transpose_bf(const bf16* __restrict__ ih,
                                                    bf16* __restrict__ oh) {
    __shared__ bf16 th[32][33];
    int z = blockIdx.z, l0 = blockIdx.y * 32, d0 = blockIdx.x * 32;
    int x = threadIdx.x, y = threadIdx.y;
    #pragma unroll
    for (int i = 0; i < 32; i += 8) {
        size_t g = ((size_t)z * LI + l0 + y + i) * 64 + d0 + x;
        th[y + i][x] = ih[g];
    }
    __syncthreads();
    #pragma unroll
    for (int i = 0; i < 32; i += 8) {
        size_t g = ((size_t)z * 64 + d0 + y + i) * LI + l0 + x;
        oh[g] = th[x][y + i];
    }
}

// ---------------- residual + LayerNorm ----------------
__device__ __forceinline__ float warpSum(float v) {
    #pragma unroll
    for (int o = 16; o; o >>= 1) v += __shfl_xor_sync(0xffffffffu, v, o);
    return v;
}
__global__ void __launch_bounds__(256) ln_kernel(const float* __restrict__ o2, const float* __restrict__ res,
                                                 const float* __restrict__ gamma, const float* __restrict__ beta,
                                                 float* __restrict__ out) {
    size_t row = blockIdx.x;
    int t = threadIdx.x;
    float4 a = ((const float4*)(o2 + row * DI))[t];
    float4 r = ((const float4*)(res + row * DI))[t];
    float x0 = a.x + r.x, x1 = a.y + r.y, x2 = a.z + r.z, x3 = a.w + r.w;
    float s = x0 + x1 + x2 + x3, sq = x0 * x0 + x1 * x1 + x2 * x2 + x3 * x3;
    s = warpSum(s); sq = warpSum(sq);
    __shared__ float rs[8], rq[8];
    if ((t & 31) == 0) { rs[t >> 5] = s; rq[t >> 5] = sq; }
    __syncthreads();
    s = 0.f; sq = 0.f;
    #pragma unroll
    for (int i = 0; i < 8; i++) { s += rs[i]; sq += rq[i]; }
    float mu = s * (1.0f / DI);
    float rstd = rsqrtf(sq * (1.0f / DI) - mu * mu + 1e-5f);
    float4 g = ((const float4*)gamma)[t], b = ((const float4*)beta)[t];
    float4 o;
    o.x = (x0 - mu) * rstd * g.x + b.x; o.y = (x1 - mu) * rstd * g.y + b.y;
    o.z = (x2 - mu) * rstd * g.z + b.z; o.w = (x3 - mu) * rstd * g.w + b.w;
    ((float4*)(out + row * DI))[t] = o;
}

// ---------------------------------------------------------------------------
extern "C" void kernel_launch(void* const* d_in, const int* in_sizes, int n_in,
                              void* d_out, int out_size)
{
    const float* q  = (const float*)d_in[0];
    const float* k  = (const float*)d_in[1];
    const float* v  = (const float*)d_in[2];
    const float* Wq = (const float*)d_in[3];  const float* bq = (const float*)d_in[4];
    const float* Wk = (const float*)d_in[5];  const float* bk = (const float*)d_in[6];
    const float* Wv = (const float*)d_in[7];  const float* bv = (const float*)d_in[8];
    const float* Wo = (const float*)d_in[9];  const float* bo = (const float*)d_in[10];
    const float* gamma = (const float*)d_in[11];
    const float* beta  = (const float*)d_in[12];

    float* out  = (float*)d_out;
    float* attn = out + (size_t)BI * LI * DI;

    bf16 *qhi,*qlo,*khi,*klo,*vhi,*vlo,*wqh,*wql,*wkh,*wkl,*wvh,*wvl,*woh,*wol;
    bf16 *Qhi,*Qlo,*Khi,*Klo,*VHh,*Vth,*Ohi;
    float *O2, *M, *I;
    cudaGetSymbolAddress((void**)&qhi, g_qhi);  cudaGetSymbolAddress((void**)&qlo, g_qlo);
    cudaGetSymbolAddress((void**)&khi, g_khi);  cudaGetSymbolAddress((void**)&klo, g_klo);
    cudaGetSymbolAddress((void**)&vhi, g_vhi);  cudaGetSymbolAddress((void**)&vlo, g_vlo);
    cudaGetSymbolAddress((void**)&wqh, g_wqhi); cudaGetSymbolAddress((void**)&wql, g_wqlo);
    cudaGetSymbolAddress((void**)&wkh, g_wkhi); cudaGetSymbolAddress((void**)&wkl, g_wklo);
    cudaGetSymbolAddress((void**)&wvh, g_wvhi); cudaGetSymbolAddress((void**)&wvl, g_wvlo);
    cudaGetSymbolAddress((void**)&woh, g_wohi); cudaGetSymbolAddress((void**)&wol, g_wolo);
    cudaGetSymbolAddress((void**)&Qhi, g_Qhi);  cudaGetSymbolAddress((void**)&Qlo, g_Qlo);
    cudaGetSymbolAddress((void**)&Khi, g_Khi);  cudaGetSymbolAddress((void**)&Klo, g_Klo);
    cudaGetSymbolAddress((void**)&VHh, g_VHhi);
    cudaGetSymbolAddress((void**)&Vth, g_Vthi);
    cudaGetSymbolAddress((void**)&Ohi, g_Ohi);
    cudaGetSymbolAddress((void**)&O2,  g_O2);
    cudaGetSymbolAddress((void**)&M,   g_M);    cudaGetSymbolAddress((void**)&I,   g_I);

    const int SM0  = 2 * (2*128*40*2 + 2*128*40*2);   // 81920 (MODE0)
    const int SM1  = 2 * (1*128*40*2 + 2*128*40*2);   // 61440 (MODE1)
    const int SM3  = 2 * (1*128*40*2 + 1*64*40*2);    // 30720 (MODE3)
    const int SMSC = 81920;
    cudaFuncSetAttribute(gemm_mma<128,0>, cudaFuncAttributeMaxDynamicSharedMemorySize, SM0);
    cudaFuncSetAttribute(gemm_mma<128,1>, cudaFuncAttributeMaxDynamicSharedMemorySize, SM1);
    cudaFuncSetAttribute(gemm_mma<64,3>,  cudaFuncAttributeMaxDynamicSharedMemorySize, SM3);
    cudaFuncSetAttribute(scores_mma,      cudaFuncAttributeMaxDynamicSharedMemorySize, SMSC);

    // input splits (bf16)
    CvtSet ci; ci.s[0]=q; ci.s[1]=k; ci.s[2]=v; ci.s[3]=q;
    ci.h[0]=qhi; ci.h[1]=khi; ci.h[2]=vhi; ci.h[3]=qhi;
    ci.l[0]=qlo; ci.l[1]=klo; ci.l[2]=vlo; ci.l[3]=qlo;
    ci.n4 = 2097152; ci.f16 = 0;
    convert_multi<<<dim3(8192,3), 256>>>(ci);
    // weight splits: Wq,Wk,Wv bf16
    CvtSet cw; cw.s[0]=Wq; cw.s[1]=Wk; cw.s[2]=Wv; cw.s[3]=Wq;
    cw.h[0]=wqh; cw.h[1]=wkh; cw.h[2]=wvh; cw.h[3]=wqh;
    cw.l[0]=wql; cw.l[1]=wkl; cw.l[2]=wvl; cw.l[3]=wql;
    cw.n4 = 262144; cw.f16 = 0;
    convert_multi<<<dim3(1024,3), 256>>>(cw);
    // Wo split: fp16
    CvtSet co; co.s[0]=Wo; co.s[1]=Wo; co.s[2]=Wo; co.s[3]=Wo;
    co.h[0]=woh; co.h[1]=woh; co.h[2]=woh; co.h[3]=woh;
    co.l[0]=wol; co.l[1]=wol; co.l[2]=wol; co.l[3]=wol;
    co.n4 = 262144; co.f16 = 1;
    convert_multi<<<dim3(1024,1), 256>>>(co);

    // merged QKV projections (bf16 3-term; V epilogue -> single fp16 plane)
    GP3 P; memset(&P, 0, sizeof(P));
    P.g[0] = { qhi,qlo, wqh,wql, nullptr,Qhi,Qlo, bq, nullptr,nullptr, DI };
    P.g[1] = { khi,klo, wkh,wkl, nullptr,Khi,Klo, bk, nullptr,nullptr, DI };
    P.g[2] = { vhi,vlo, wvh,wvl, nullptr,VHh,nullptr, bv, nullptr,nullptr, DI };
    gemm_mma<128,0><<<dim3(8,64,3), 256, SM0>>>(P);

    transpose_bf<<<dim3(2,64,64), dim3(32,8)>>>(VHh, Vth);

    // persistent scores + online softmax stats (bf16 3-term)
    scores_mma<<<dim3(16,64), 256, SMSC>>>(Qhi,Qlo, Khi,Klo, attn, M, I);

    // fused normalize + attn write + attn @ V (fp16 1-term) -> Ohi (fp16)
    GP3 P3; memset(&P3, 0, sizeof(P3));
    P3.g[0] = { nullptr,nullptr, Vth,nullptr, attn,Ohi,nullptr, nullptr, M,I, LI };
    gemm_mma<64,3><<<dim3(1,16,64), 256, SM3>>>(P3);

    // output projection (fp16 2-term) + residual/LN
    GP3 P4; memset(&P4, 0, sizeof(P4));
    P4.g[0] = { Ohi,nullptr, woh,wol, O2,nullptr,nullptr, bo, nullptr,nullptr, DI };
    gemm_mma<128,1><<<dim3(8,64,1), 256, SM1>>>(P4);
    ln_kernel<<<BI*LI, 256>>>(O2, q, gamma, beta, out);
}

// round 15
// speedup vs baseline: 1.1663x; 1.0889x over previous
#include <cuda_runtime.h>
#include <cuda_bf16.h>
#include <cuda_fp16.h>
#include <cstdint>
#include <math.h>

#define BI 4
#define LI 2048
#define DI 1024
#define HI 16

typedef __nv_bfloat16 bf16;
#define ELI ((size_t)8192*1024)
#define ELW ((size_t)1024*1024)

// device-global scratch (allocation-free rule). 16-bit buffers hold bf16 OR fp16 bits.
__device__ __align__(256) bf16 g_qhi[ELI], g_qlo[ELI], g_khi[ELI], g_klo[ELI], g_vhi[ELI], g_vlo[ELI];
__device__ __align__(256) bf16 g_wqhi[ELW], g_wqlo[ELW], g_wkhi[ELW], g_wklo[ELW];
__device__ __align__(256) bf16 g_wvhi[ELW], g_wvlo[ELW], g_wohi[ELW], g_wolo[ELW];
__device__ __align__(256) bf16 g_Qhi[ELI], g_Qlo[ELI], g_Khi[ELI], g_Klo[ELI];   // [bh][l][64] bf16
__device__ __align__(256) bf16 g_VHhi[ELI];                                      // [bh][l][64] fp16
__device__ __align__(256) bf16 g_Vthi[ELI];                                      // [bh][64][2048] fp16
__device__ __align__(256) bf16 g_Ohi[ELI];                                       // [8192][1024] fp16
__device__ __align__(256) float g_O2[ELI];

// ---------------- helpers ----------------
__device__ __forceinline__ uint32_t s2u(const void* p) {
    uint32_t a;
    asm("{ .reg .u64 t; cvta.to.shared.u64 t, %1; cvt.u32.u64 %0, t; }" : "=r"(a) : "l"(p));
    return a;
}
__device__ __forceinline__ void ldm4(uint32_t* r, uint32_t a) {
    asm volatile("ldmatrix.sync.aligned.m8n8.x4.shared.b16 {%0,%1,%2,%3}, [%4];"
                 : "=r"(r[0]), "=r"(r[1]), "=r"(r[2]), "=r"(r[3]) : "r"(a));
}
__device__ __forceinline__ void mma_bf(float* c, const uint32_t* a, const uint32_t* b) {
    asm volatile("mma.sync.aligned.m16n8k16.row.col.f32.bf16.bf16.f32 "
                 "{%0,%1,%2,%3}, {%4,%5,%6,%7}, {%8,%9}, {%0,%1,%2,%3};"
                 : "+f"(c[0]), "+f"(c[1]), "+f"(c[2]), "+f"(c[3])
                 : "r"(a[0]), "r"(a[1]), "r"(a[2]), "r"(a[3]), "r"(b[0]), "r"(b[1]));
}
__device__ __forceinline__ void mma_fp(float* c, const uint32_t* a, const uint32_t* b) {
    asm volatile("mma.sync.aligned.m16n8k16.row.col.f32.f16.f16.f32 "
                 "{%0,%1,%2,%3}, {%4,%5,%6,%7}, {%8,%9}, {%0,%1,%2,%3};"
                 : "+f"(c[0]), "+f"(c[1]), "+f"(c[2]), "+f"(c[3])
                 : "r"(a[0]), "r"(a[1]), "r"(a[2]), "r"(a[3]), "r"(b[0]), "r"(b[1]));
}
#define CP16(d, s)   asm volatile("cp.async.cg.shared.global [%0], [%1], 16;" :: "r"(d), "l"(s))
#define CP_COMMIT()  asm volatile("cp.async.commit_group;")
#define CP_WAIT0()   asm volatile("cp.async.wait_group 0;")

__device__ __forceinline__ void split2(float x0, float x1, unsigned& H, unsigned& L) {
    bf16 h0 = __float2bfloat16(x0), h1 = __float2bfloat16(x1);
    bf16 l0 = __float2bfloat16(x0 - __bfloat162float(h0));
    bf16 l1 = __float2bfloat16(x1 - __bfloat162float(h1));
    H = (unsigned)__bfloat16_as_ushort(h0) | ((unsigned)__bfloat16_as_ushort(h1) << 16);
    L = (unsigned)__bfloat16_as_ushort(l0) | ((unsigned)__bfloat16_as_ushort(l1) << 16);
}
__device__ __forceinline__ void split2h(float x0, float x1, unsigned& H, unsigned& L) {
    __half h0 = __float2half_rn(x0), h1 = __float2half_rn(x1);
    __half l0 = __float2half_rn(x0 - __half2float(h0));
    __half l1 = __float2half_rn(x1 - __half2float(h1));
    H = (unsigned)__half_as_ushort(h0) | ((unsigned)__half_as_ushort(h1) << 16);
    L = (unsigned)__half_as_ushort(l0) | ((unsigned)__half_as_ushort(l1) << 16);
}
__device__ __forceinline__ unsigned pack2h(float x0, float x1) {
    __half2 h = __floats2half2_rn(x0, x1);
    return *reinterpret_cast<unsigned*>(&h);
}

struct CvtSet { const float* s[4]; bf16* h[4]; bf16* l[4]; int n4; int f16; };
__global__ void __launch_bounds__(256) convert_multi(CvtSet p) {
    int y = blockIdx.y;
    int i = blockIdx.x * 256 + threadIdx.x;
    if (i >= p.n4) return;
    float4 v = ((const float4*)p.s[y])[i];
    unsigned h01, l01, h23, l23;
    if (p.f16) { split2h(v.x, v.y, h01, l01); split2h(v.z, v.w, h23, l23); }
    else       { split2(v.x, v.y, h01, l01);  split2(v.z, v.w, h23, l23); }
    ((uint2*)p.h[y])[i] = make_uint2(h01, h23);
    ((uint2*)p.l[y])[i] = make_uint2(l01, l23);
}

// GEMM parameter block
struct GP {
    const bf16 *Ahi, *Alo, *Bhi, *Blo;
    float* Cf; bf16 *Chi, *Clo;
    const float *bias;
    int K;
};
struct GP3 { GP g[3]; };

// ---------------------------------------------------------------------------
// mma.sync split GEMM (BK=32, 2-stage cp.async, one sync per chunk).
// MODE 0: QKV proj, bf16 3-term. z==2 (V) epilogue -> single fp16 plane.
// MODE 1: out proj, fp16 2-term (A = Ohi single plane, B = Wo hi/lo). +bias.
// ---------------------------------------------------------------------------
template<int BN, int MODE>
__global__ void __launch_bounds__(256, 2)
gemm_mma(GP3 P)
{
    constexpr int BM = 128, BK = 32, BKP = 40;
    constexpr int ASZ = BM * BKP * 2;
    constexpr int BSZ = BN * BKP * 2;
    constexpr int APL   = (MODE == 1) ? 1 : 2;
    constexpr int TERMS = (MODE == 0) ? 3 : 2;
    constexpr bool F16  = (MODE == 1);
    constexpr int STAGE = APL * ASZ + 2 * BSZ;
    constexpr int NF = BN / 16;
    constexpr int BV = BN / 64;

    GP p = P.g[MODE == 0 ? blockIdx.z : 0];
    extern __shared__ char smem[];
    const uint32_t sbase = s2u(smem);

    const int t = threadIdx.x, l = t & 31, wid = t >> 5;
    const int wm = wid & 3, wn = wid >> 2;
    const int gid = l >> 2, tig = l & 3;
    const int bc = blockIdx.x, br = blockIdx.y, z = blockIdx.z;

    const bf16 *Ah = p.Ahi, *Al = p.Alo, *Bh = p.Bhi, *Bl = p.Blo;
    const int K = p.K;

    int aoff[2], boff[NF / 2];
    #pragma unroll
    for (int mi = 0; mi < 2; mi++)
        aoff[mi] = ((wm * 32 + mi * 16 + (l & 15)) * BKP + ((l & 16) >> 1)) * 2;
    #pragma unroll
    for (int pp = 0; pp < NF / 2; pp++)
        boff[pp] = ((wn * (BN / 2) + pp * 16 + (l & 7) + ((l >> 1) & 8)) * BKP + (l & 8)) * 2;

    float acc[2][NF][4];
    #pragma unroll
    for (int mi = 0; mi < 2; mi++)
        #pragma unroll
        for (int ni = 0; ni < NF; ni++)
            #pragma unroll
            for (int c = 0; c < 4; c++) acc[mi][ni][c] = 0.f;

    const int n = K / BK;

    auto issue = [&](int ck) {
        int k0 = ck * BK;
        uint32_t sd = sbase + (ck & 1) * STAGE;
        #pragma unroll
        for (int i = 0; i < 2; i++) {
            int vi = t + i * 256, row = vi >> 2, kc = (vi & 3) * 8;
            uint32_t off = (uint32_t)(row * BKP + kc) * 2;
            size_t g = (size_t)(br * 128 + row) * K + k0 + kc;
            CP16(sd + off, Ah + g);
            if (APL == 2) CP16(sd + ASZ + off, Al + g);
        }
        #pragma unroll
        for (int i = 0; i < BV; i++) {
            int vi = t + i * 256, row = vi >> 2, kc = (vi & 3) * 8;
            uint32_t off = (uint32_t)(row * BKP + kc) * 2;
            size_t g = (size_t)(bc * BN + row) * K + k0 + kc;
            CP16(sd + APL * ASZ + off,       Bh + g);
            CP16(sd + APL * ASZ + BSZ + off, Bl + g);
        }
    };
    auto compute = [&](int buf) {
        uint32_t sb = sbase + buf * STAGE;
        #pragma unroll
        for (int ks = 0; ks < 2; ks++) {
            int kb = ks * 32;
            uint32_t ah[2][4], al[2][4];
            #pragma unroll
            for (int mi = 0; mi < 2; mi++) {
                ldm4(ah[mi], sb + aoff[mi] + kb);
                if (TERMS == 3) ldm4(al[mi], sb + ASZ + aoff[mi] + kb);
            }
            uint32_t bh[NF][2], bl[NF][2];
            #pragma unroll
            for (int pp = 0; pp < NF / 2; pp++) {
                uint32_t r[4];
                ldm4(r, sb + APL * ASZ + boff[pp] + kb);
                bh[2*pp][0] = r[0]; bh[2*pp][1] = r[1]; bh[2*pp+1][0] = r[2]; bh[2*pp+1][1] = r[3];
                ldm4(r, sb + APL * ASZ + BSZ + boff[pp] + kb);
                bl[2*pp][0] = r[0]; bl[2*pp][1] = r[1]; bl[2*pp+1][0] = r[2]; bl[2*pp+1][1] = r[3];
            }
            #pragma unroll
            for (int mi = 0; mi < 2; mi++)
                #pragma unroll
                for (int ni = 0; ni < NF; ni++) {
                    if (F16) mma_fp(acc[mi][ni], ah[mi], bh[ni]);
                    else     mma_bf(acc[mi][ni], ah[mi], bh[ni]);
                }
            #pragma unroll
            for (int mi = 0; mi < 2; mi++)
                #pragma unroll
                for (int ni = 0; ni < NF; ni++) {
                    if (F16) mma_fp(acc[mi][ni], ah[mi], bl[ni]);
                    else     mma_bf(acc[mi][ni], ah[mi], bl[ni]);
                }
            if (TERMS == 3) {
                #pragma unroll
                for (int mi = 0; mi < 2; mi++)
                    #pragma unroll
                    for (int ni = 0; ni < NF; ni++)
                        mma_bf(acc[mi][ni], al[mi], bh[ni]);
            }
        }
    };

    issue(0); CP_COMMIT();
    for (int ck = 0; ck < n; ck++) {
        CP_WAIT0();
        __syncthreads();
        if (ck + 1 < n) issue(ck + 1);
        compute(ck & 1);
        CP_COMMIT();
    }

    #pragma unroll
    for (int mi = 0; mi < 2; mi++)
        #pragma unroll
        for (int ni = 0; ni < NF; ni++)
            #pragma unroll
            for (int h = 0; h < 2; h++) {
                int gi = br * 128 + wm * 32 + mi * 16 + gid + h * 8;
                int gj = bc * BN + wn * (BN / 2) + ni * 8 + tig * 2;
                float v0 = acc[mi][ni][h * 2 + 0];
                float v1 = acc[mi][ni][h * 2 + 1];
                if (MODE == 1) {
                    v0 += p.bias[gj]; v1 += p.bias[gj + 1];
                    *(float2*)&p.Cf[(size_t)gi * DI + gj] = make_float2(v0, v1);
                } else {
                    v0 += p.bias[gj]; v1 += p.bias[gj + 1];
                    size_t e = (((size_t)((gi >> 11) * HI + (gj >> 6)) * LI + (gi & 2047)) << 6) + (gj & 63);
                    if (z == 2) {
                        ((unsigned*)p.Chi)[e >> 1] = pack2h(v0, v1);
                    } else {
                        unsigned H, L;
                        split2(v0, v1, H, L);
                        ((unsigned*)p.Chi)[e >> 1] = H;
                        ((unsigned*)p.Clo)[e >> 1] = L;
                    }
                }
            }
}

// ---------------------------------------------------------------------------
// Fused attention: grid (br=16, z=64), 8 warps x 16 rows, 64-wide KV tiles.
// Pass 1: S = QK^T (bf16 3-term), online softmax stats in registers.
// Pass 2: recompute S (bit-identical), p = exp(s-M)/S written directly to attn,
//         P fed from registers (C-frag == A-frag layout) into P·V (fp16 1-term).
// ---------------------------------------------------------------------------
__global__ void __launch_bounds__(256, 2)
fused_attn(const bf16* __restrict__ Qhi, const bf16* __restrict__ Qlo,
           const bf16* __restrict__ Khi, const bf16* __restrict__ Klo,
           const bf16* __restrict__ Vt,
           float* __restrict__ attn, bf16* __restrict__ Ohi)
{
    constexpr int PAN = 10240, KPAN = 5120, VPAN = 5120;
    constexpr int KSLOT = 4 * KPAN, VSLOT = 2 * VPAN;
    constexpr int KBASE = 4 * PAN;               // 40960
    constexpr int VBASE = KBASE + 2 * KSLOT;     // 81920 ; total 102400
    extern __shared__ char smem[];
    const uint32_t sb = s2u(smem);

    const int t = threadIdx.x, l = t & 31, wid = t >> 5;
    const int gid = l >> 2, tig = l & 3;
    const int br = blockIdx.x, z = blockIdx.y;

    const bf16* Ah = Qhi + (size_t)z * LI * 64;
    const bf16* Aq = Qlo + (size_t)z * LI * 64;
    const bf16* Bh = Khi + (size_t)z * LI * 64;
    const bf16* Bl = Klo + (size_t)z * LI * 64;
    const bf16* Vp = Vt + (size_t)z * 64 * LI;
    float* Cf = attn + ((size_t)((z & 15) * BI + (z >> 4))) * LI * LI;

    const int aoffQ = ((wid * 16 + (l & 15)) * 40 + ((l & 16) >> 1)) * 2;
    int boff[4];
    #pragma unroll
    for (int pp = 0; pp < 4; pp++)
        boff[pp] = ((pp * 16 + (l & 7) + ((l >> 1) & 8)) * 40 + (l & 8)) * 2;

    // Q tile once: 2 panels x 2 planes
    #pragma unroll
    for (int ck = 0; ck < 2; ck++)
        #pragma unroll
        for (int i = 0; i < 2; i++) {
            int vi = t + i * 256, row = vi >> 2, kc = (vi & 3) * 8;
            uint32_t off = (uint32_t)(row * 40 + kc) * 2;
            size_t g = (size_t)(br * 128 + row) * 64 + ck * 32 + kc;
            CP16(sb + ck * 2 * PAN + off,       Ah + g);
            CP16(sb + ck * 2 * PAN + PAN + off, Aq + g);
        }
    CP_COMMIT();

    auto issueK = [&](int tile) {
        int row = t >> 2, kc = (t & 3) * 8;
        uint32_t base = sb + KBASE + (tile & 1) * KSLOT;
        uint32_t off = (uint32_t)(row * 40 + kc) * 2;
        #pragma unroll
        for (int p = 0; p < 2; p++) {
            size_t g = (size_t)(tile * 64 + row) * 64 + p * 32 + kc;
            CP16(base + p * 2 * KPAN + off,        Bh + g);
            CP16(base + p * 2 * KPAN + KPAN + off, Bl + g);
        }
    };
    auto issueV = [&](int tile) {
        int row = t >> 2, kc = (t & 3) * 8;
        uint32_t base = sb + VBASE + (tile & 1) * VSLOT;
        uint32_t off = (uint32_t)(row * 40 + kc) * 2;
        #pragma unroll
        for (int p = 0; p < 2; p++)
            CP16(base + p * VPAN + off, Vp + (size_t)row * LI + tile * 64 + p * 32 + kc);
    };

    float S[8][4], O[8][4];
    #pragma unroll
    for (int ni = 0; ni < 8; ni++)
        #pragma unroll
        for (int c = 0; c < 4; c++) O[ni][c] = 0.f;

    auto computeS = [&](int slot) {
        #pragma unroll
        for (int ni = 0; ni < 8; ni++)
            #pragma unroll
            for (int c = 0; c < 4; c++) S[ni][c] = 0.f;
        uint32_t kbase = sb + KBASE + slot * KSLOT;
        #pragma unroll
        for (int p = 0; p < 2; p++)
            #pragma unroll
            for (int ks = 0; ks < 2; ks++) {
                int kb = ks * 32;
                uint32_t ah[4], aq[4];
                ldm4(ah, sb + p * 2 * PAN + aoffQ + kb);
                ldm4(aq, sb + p * 2 * PAN + PAN + aoffQ + kb);
                uint32_t bf[8][2];
                #pragma unroll
                for (int pp = 0; pp < 4; pp++) {
                    uint32_t r[4];
                    ldm4(r, kbase + p * 2 * KPAN + boff[pp] + kb);
                    bf[2*pp][0] = r[0]; bf[2*pp][1] = r[1]; bf[2*pp+1][0] = r[2]; bf[2*pp+1][1] = r[3];
                }
                #pragma unroll
                for (int ni = 0; ni < 8; ni++) mma_bf(S[ni], ah, bf[ni]);
                #pragma unroll
                for (int ni = 0; ni < 8; ni++) mma_bf(S[ni], aq, bf[ni]);
                #pragma unroll
                for (int pp = 0; pp < 4; pp++) {
                    uint32_t r[4];
                    ldm4(r, kbase + p * 2 * KPAN + KPAN + boff[pp] + kb);
                    bf[2*pp][0] = r[0]; bf[2*pp][1] = r[1]; bf[2*pp+1][0] = r[2]; bf[2*pp+1][1] = r[3];
                }
                #pragma unroll
                for (int ni = 0; ni < 8; ni++) mma_bf(S[ni], ah, bf[ni]);
            }
    };

    float rm[2] = {-INFINITY, -INFINITY}, rs[2] = {0.f, 0.f};
    const int gi0 = br * 128 + wid * 16 + gid;

    // ---- pass 1: stats only ----
    issueK(0); CP_COMMIT();
    for (int tile = 0; tile < 32; tile++) {
        CP_WAIT0();
        __syncthreads();
        if (tile + 1 < 32) issueK(tile + 1);
        CP_COMMIT();
        computeS(tile & 1);
        #pragma unroll
        for (int ni = 0; ni < 8; ni++)
            #pragma unroll
            for (int c = 0; c < 4; c++) {
                int gi = gi0 + (c >> 1) * 8;
                int gj = tile * 64 + ni * 8 + tig * 2 + (c & 1);
                float v = S[ni][c] * 0.125f;
                if (gi == gj) v = -INFINITY;
                S[ni][c] = v;
            }
        #pragma unroll
        for (int h = 0; h < 2; h++) {
            float m = -INFINITY;
            #pragma unroll
            for (int ni = 0; ni < 8; ni++) {
                m = fmaxf(m, S[ni][h*2+0]); m = fmaxf(m, S[ni][h*2+1]);
            }
            m = fmaxf(m, __shfl_xor_sync(0xffffffffu, m, 1));
            m = fmaxf(m, __shfl_xor_sync(0xffffffffu, m, 2));
            float sl = 0.f;
            #pragma unroll
            for (int ni = 0; ni < 8; ni++) {
                sl += __expf(S[ni][h*2+0] - m); sl += __expf(S[ni][h*2+1] - m);
            }
            sl += __shfl_xor_sync(0xffffffffu, sl, 1);
            sl += __shfl_xor_sync(0xffffffffu, sl, 2);
            float mo = rm[h], mn = fmaxf(mo, m);
            rs[h] = rs[h] * __expf(mo - mn) + sl * __expf(m - mn);
            rm[h] = mn;
        }
    }
    float Mv[2] = {rm[0], rm[1]};
    float Iv[2] = {1.f / rs[0], 1.f / rs[1]};

    // ---- pass 2: recompute, normalize-write, P·V ----
    __syncthreads();
    issueK(0); issueV(0); CP_COMMIT();
    for (int tile = 0; tile < 32; tile++) {
        CP_WAIT0();
        __syncthreads();
        if (tile + 1 < 32) { issueK(tile + 1); issueV(tile + 1); }
        CP_COMMIT();
        computeS(tile & 1);
        #pragma unroll
        for (int ni = 0; ni < 8; ni++) {
            #pragma unroll
            for (int c = 0; c < 4; c++) {
                int gi = gi0 + (c >> 1) * 8;
                int gj = tile * 64 + ni * 8 + tig * 2 + (c & 1);
                float v = S[ni][c] * 0.125f;
                if (gi == gj) v = -INFINITY;
                S[ni][c] = __expf(v - Mv[c >> 1]) * Iv[c >> 1];
            }
            int gj0 = tile * 64 + ni * 8 + tig * 2;
            *(float2*)&Cf[(size_t)gi0 * LI + gj0]       = make_float2(S[ni][0], S[ni][1]);
            *(float2*)&Cf[(size_t)(gi0 + 8) * LI + gj0] = make_float2(S[ni][2], S[ni][3]);
        }
        uint32_t vbase = sb + VBASE + (tile & 1) * VSLOT;
        #pragma unroll
        for (int j = 0; j < 4; j++) {
            uint32_t aP[4] = { pack2h(S[2*j][0],   S[2*j][1]),   pack2h(S[2*j][2],   S[2*j][3]),
                               pack2h(S[2*j+1][0], S[2*j+1][1]), pack2h(S[2*j+1][2], S[2*j+1][3]) };
            int p = j >> 1, kb = (j & 1) * 32;
            uint32_t vb[8][2];
            #pragma unroll
            for (int pp = 0; pp < 4; pp++) {
                uint32_t r[4];
                ldm4(r, vbase + p * VPAN + boff[pp] + kb);
                vb[2*pp][0] = r[0]; vb[2*pp][1] = r[1]; vb[2*pp+1][0] = r[2]; vb[2*pp+1][1] = r[3];
            }
            #pragma unroll
            for (int ni = 0; ni < 8; ni++) mma_fp(O[ni], aP, vb[ni]);
        }
    }

    // ---- O epilogue -> Ohi (fp16) ----
    #pragma unroll
    for (int ni = 0; ni < 8; ni++)
        #pragma unroll
        for (int h = 0; h < 2; h++) {
            int gi = gi0 + h * 8;
            int gj = ni * 8 + tig * 2;
            size_t e = ((size_t)(z >> 4) * LI + gi) * DI + (z & 15) * 64 + gj;
            ((unsigned*)Ohi)[e >> 1] = pack2h(O[ni][h*2], O[ni][h*2+1]);
        }
}

// ---------------- V transpose (single plane): [bh][l][64] -> [bh][64][2048] --
__global__ void __launch_bounds__(256) transpose_bf(const bf16* __restrict__ ih,
                                                    bf16* __restrict__ oh) {
    __shared__ bf16 th[32][33];
    int z = blockIdx.z, l0 = blockIdx.y * 32, d0 = blockIdx.x * 32;
    int x = threadIdx.x, y = threadIdx.y;
    #pragma unroll
    for (int i = 0; i < 32; i += 8) {
        size_t g = ((size_t)z * LI + l0 + y + i) * 64 + d0 + x;
        th[y + i][x] = ih[g];
    }
    __syncthreads();
    #pragma unroll
    for (int i = 0; i < 32; i += 8) {
        size_t g = ((size_t)z * 64 + d0 + y + i) * LI + l0 + x;
        oh[g] = th[x][y + i];
    }
}

// ---------------- residual + LayerNorm ----------------
__device__ __forceinline__ float warpSum(float v) {
    #pragma unroll
    for (int o = 16; o; o >>= 1) v += __shfl_xor_sync(0xffffffffu, v, o);
    return v;
}
__global__ void __launch_bounds__(256) ln_kernel(const float* __restrict__ o2, const float* __restrict__ res,
                                                 const float* __restrict__ gamma, const float* __restrict__ beta,
                                                 float* __restrict__ out) {
    size_t row = blockIdx.x;
    int t = threadIdx.x;
    float4 a = ((const float4*)(o2 + row * DI))[t];
    float4 r = ((const float4*)(res + row * DI))[t];
    float x0 = a.x + r.x, x1 = a.y + r.y, x2 = a.z + r.z, x3 = a.w + r.w;
    float s = x0 + x1 + x2 + x3, sq = x0 * x0 + x1 * x1 + x2 * x2 + x3 * x3;
    s = warpSum(s); sq = warpSum(sq);
    __shared__ float rs[8], rq[8];
    if ((t & 31) == 0) { rs[t >> 5] = s; rq[t >> 5] = sq; }
    __syncthreads();
    s = 0.f; sq = 0.f;
    #pragma unroll
    for (int i = 0; i < 8; i++) { s += rs[i]; sq += rq[i]; }
    float mu = s * (1.0f / DI);
    float rstd = rsqrtf(sq * (1.0f / DI) - mu * mu + 1e-5f);
    float4 g = ((const float4*)gamma)[t], b = ((const float4*)beta)[t];
    float4 o;
    o.x = (x0 - mu) * rstd * g.x + b.x; o.y = (x1 - mu) * rstd * g.y + b.y;
    o.z = (x2 - mu) * rstd * g.z + b.z; o.w = (x3 - mu) * rstd * g.w + b.w;
    ((float4*)(out + row * DI))[t] = o;
}

// ---------------------------------------------------------------------------
extern "C" void kernel_launch(void* const* d_in, const int* in_sizes, int n_in,
                              void* d_out, int out_size)
{
    const float* q  = (const float*)d_in[0];
    const float* k  = (const float*)d_in[1];
    const float* v  = (const float*)d_in[2];
    const float* Wq = (const float*)d_in[3];  const float* bq = (const float*)d_in[4];
    const float* Wk = (const float*)d_in[5];  const float* bk = (const float*)d_in[6];
    const float* Wv = (const float*)d_in[7];  const float* bv = (const float*)d_in[8];
    const float* Wo = (const float*)d_in[9];  const float* bo = (const float*)d_in[10];
    const float* gamma = (const float*)d_in[11];
    const float* beta  = (const float*)d_in[12];

    float* out  = (float*)d_out;
    float* attn = out + (size_t)BI * LI * DI;

    bf16 *qhi,*qlo,*khi,*klo,*vhi,*vlo,*wqh,*wql,*wkh,*wkl,*wvh,*wvl,*woh,*wol;
    bf16 *Qhi,*Qlo,*Khi,*Klo,*VHh,*Vth,*Ohi;
    float *O2;
    cudaGetSymbolAddress((void**)&qhi, g_qhi);  cudaGetSymbolAddress((void**)&qlo, g_qlo);
    cudaGetSymbolAddress((void**)&khi, g_khi);  cudaGetSymbolAddress((void**)&klo, g_klo);
    cudaGetSymbolAddress((void**)&vhi, g_vhi);  cudaGetSymbolAddress((void**)&vlo, g_vlo);
    cudaGetSymbolAddress((void**)&wqh, g_wqhi); cudaGetSymbolAddress((void**)&wql, g_wqlo);
    cudaGetSymbolAddress((void**)&wkh, g_wkhi); cudaGetSymbolAddress((void**)&wkl, g_wklo);
    cudaGetSymbolAddress((void**)&wvh, g_wvhi); cudaGetSymbolAddress((void**)&wvl, g_wvlo);
    cudaGetSymbolAddress((void**)&woh, g_wohi); cudaGetSymbolAddress((void**)&wol, g_wolo);
    cudaGetSymbolAddress((void**)&Qhi, g_Qhi);  cudaGetSymbolAddress((void**)&Qlo, g_Qlo);
    cudaGetSymbolAddress((void**)&Khi, g_Khi);  cudaGetSymbolAddress((void**)&Klo, g_Klo);
    cudaGetSymbolAddress((void**)&VHh, g_VHhi);
    cudaGetSymbolAddress((void**)&Vth, g_Vthi);
    cudaGetSymbolAddress((void**)&Ohi, g_Ohi);
    cudaGetSymbolAddress((void**)&O2,  g_O2);

    const int SM0 = 2 * (2*128*40*2 + 2*128*40*2);   // 81920 (MODE0)
    const int SM1 = 2 * (1*128*40*2 + 2*128*40*2);   // 61440 (MODE1)
    const int SMF = 102400;                          // fused_attn
    cudaFuncSetAttribute(gemm_mma<128,0>, cudaFuncAttributeMaxDynamicSharedMemorySize, SM0);
    cudaFuncSetAttribute(gemm_mma<128,1>, cudaFuncAttributeMaxDynamicSharedMemorySize, SM1);
    cudaFuncSetAttribute(fused_attn,      cudaFuncAttributeMaxDynamicSharedMemorySize, SMF);

    // input splits (bf16)
    CvtSet ci; ci.s[0]=q; ci.s[1]=k; ci.s[2]=v; ci.s[3]=q;
    ci.h[0]=qhi; ci.h[1]=khi; ci.h[2]=vhi; ci.h[3]=qhi;
    ci.l[0]=qlo; ci.l[1]=klo; ci.l[2]=vlo; ci.l[3]=qlo;
    ci.n4 = 2097152; ci.f16 = 0;
    convert_multi<<<dim3(8192,3), 256>>>(ci);
    // weight splits: Wq,Wk,Wv bf16
    CvtSet cw; cw.s[0]=Wq; cw.s[1]=Wk; cw.s[2]=Wv; cw.s[3]=Wq;
    cw.h[0]=wqh; cw.h[1]=wkh; cw.h[2]=wvh; cw.h[3]=wqh;
    cw.l[0]=wql; cw.l[1]=wkl; cw.l[2]=wvl; cw.l[3]=wql;
    cw.n4 = 262144; cw.f16 = 0;
    convert_multi<<<dim3(1024,3), 256>>>(cw);
    // Wo split: fp16
    CvtSet co; co.s[0]=Wo; co.s[1]=Wo; co.s[2]=Wo; co.s[3]=Wo;
    co.h[0]=woh; co.h[1]=woh; co.h[2]=woh; co.h[3]=woh;
    co.l[0]=wol; co.l[1]=wol; co.l[2]=wol; co.l[3]=wol;
    co.n4 = 262144; co.f16 = 1;
    convert_multi<<<dim3(1024,1), 256>>>(co);

    // merged QKV projections (bf16 3-term; V epilogue -> single fp16 plane)
    GP3 P; memset(&P, 0, sizeof(P));
    P.g[0] = { qhi,qlo, wqh,wql, nullptr,Qhi,Qlo, bq, DI };
    P.g[1] = { khi,klo, wkh,wkl, nullptr,Khi,Klo, bk, DI };
    P.g[2] = { vhi,vlo, wvh,wvl, nullptr,VHh,nullptr, bv, DI };
    gemm_mma<128,0><<<dim3(8,64,3), 256, SM0>>>(P);

    transpose_bf<<<dim3(2,64,64), dim3(32,8)>>>(VHh, Vth);

    // fused two-pass attention: stats, then normalized-attn write + P·V
    fused_attn<<<dim3(16,64), 256, SMF>>>(Qhi,Qlo, Khi,Klo, Vth, attn, Ohi);

    // output projection (fp16 2-term) + residual/LN
    GP3 P4; memset(&P4, 0, sizeof(P4));
    P4.g[0] = { Ohi,nullptr, woh,wol, O2,nullptr,nullptr, bo, DI };
    gemm_mma<128,1><<<dim3(8,64,1), 256, SM1>>>(P4);
    ln_kernel<<<BI*LI, 256>>>(O2, q, gamma, beta, out);
}

// round 16
// speedup vs baseline: 1.2534x; 1.0746x over previous
#include <cuda_runtime.h>
#include <cuda_bf16.h>
#include <cuda_fp16.h>
#include <cstdint>
#include <math.h>

#define BI 4
#define LI 2048
#define DI 1024
#define HI 16

typedef __nv_bfloat16 bf16;
#define ELI ((size_t)8192*1024)
#define ELW ((size_t)1024*1024)

// device-global scratch (allocation-free rule). 16-bit buffers hold bf16 OR fp16 bits.
__device__ __align__(256) bf16 g_qhi[ELI], g_qlo[ELI], g_khi[ELI], g_klo[ELI], g_vhi[ELI], g_vlo[ELI];
__device__ __align__(256) bf16 g_wqhi[ELW], g_wqlo[ELW], g_wkhi[ELW], g_wklo[ELW];
__device__ __align__(256) bf16 g_wvhi[ELW], g_wvlo[ELW], g_wohi[ELW], g_wolo[ELW];
__device__ __align__(256) bf16 g_Qhi[ELI], g_Qlo[ELI], g_Khi[ELI], g_Klo[ELI];   // [bh][l][64] bf16
__device__ __align__(256) bf16 g_VHhi[ELI];                                      // [bh][l][64] fp16
__device__ __align__(256) bf16 g_Vthi[ELI];                                      // [bh][64][2048] fp16
__device__ __align__(256) bf16 g_Ohi[ELI];                                       // [8192][1024] fp16
__device__ __align__(256) float g_O2[ELI];

// ---------------- helpers ----------------
__device__ __forceinline__ uint32_t s2u(const void* p) {
    uint32_t a;
    asm("{ .reg .u64 t; cvta.to.shared.u64 t, %1; cvt.u32.u64 %0, t; }" : "=r"(a) : "l"(p));
    return a;
}
__device__ __forceinline__ void ldm4(uint32_t* r, uint32_t a) {
    asm volatile("ldmatrix.sync.aligned.m8n8.x4.shared.b16 {%0,%1,%2,%3}, [%4];"
                 : "=r"(r[0]), "=r"(r[1]), "=r"(r[2]), "=r"(r[3]) : "r"(a));
}
__device__ __forceinline__ void mma_bf(float* c, const uint32_t* a, const uint32_t* b) {
    asm volatile("mma.sync.aligned.m16n8k16.row.col.f32.bf16.bf16.f32 "
                 "{%0,%1,%2,%3}, {%4,%5,%6,%7}, {%8,%9}, {%0,%1,%2,%3};"
                 : "+f"(c[0]), "+f"(c[1]), "+f"(c[2]), "+f"(c[3])
                 : "r"(a[0]), "r"(a[1]), "r"(a[2]), "r"(a[3]), "r"(b[0]), "r"(b[1]));
}
__device__ __forceinline__ void mma_fp(float* c, const uint32_t* a, const uint32_t* b) {
    asm volatile("mma.sync.aligned.m16n8k16.row.col.f32.f16.f16.f32 "
                 "{%0,%1,%2,%3}, {%4,%5,%6,%7}, {%8,%9}, {%0,%1,%2,%3};"
                 : "+f"(c[0]), "+f"(c[1]), "+f"(c[2]), "+f"(c[3])
                 : "r"(a[0]), "r"(a[1]), "r"(a[2]), "r"(a[3]), "r"(b[0]), "r"(b[1]));
}
#define CP16(d, s)   asm volatile("cp.async.cg.shared.global [%0], [%1], 16;" :: "r"(d), "l"(s))
#define CP_COMMIT()  asm volatile("cp.async.commit_group;")
#define CP_WAIT0()   asm volatile("cp.async.wait_group 0;")

__device__ __forceinline__ void split2(float x0, float x1, unsigned& H, unsigned& L) {
    bf16 h0 = __float2bfloat16(x0), h1 = __float2bfloat16(x1);
    bf16 l0 = __float2bfloat16(x0 - __bfloat162float(h0));
    bf16 l1 = __float2bfloat16(x1 - __bfloat162float(h1));
    H = (unsigned)__bfloat16_as_ushort(h0) | ((unsigned)__bfloat16_as_ushort(h1) << 16);
    L = (unsigned)__bfloat16_as_ushort(l0) | ((unsigned)__bfloat16_as_ushort(l1) << 16);
}
__device__ __forceinline__ void split2h(float x0, float x1, unsigned& H, unsigned& L) {
    __half h0 = __float2half_rn(x0), h1 = __float2half_rn(x1);
    __half l0 = __float2half_rn(x0 - __half2float(h0));
    __half l1 = __float2half_rn(x1 - __half2float(h1));
    H = (unsigned)__half_as_ushort(h0) | ((unsigned)__half_as_ushort(h1) << 16);
    L = (unsigned)__half_as_ushort(l0) | ((unsigned)__half_as_ushort(l1) << 16);
}
__device__ __forceinline__ unsigned pack2h(float x0, float x1) {
    __half2 h = __floats2half2_rn(x0, x1);
    return *reinterpret_cast<unsigned*>(&h);
}

struct CvtSet { const float* s[4]; bf16* h[4]; bf16* l[4]; int n4; int f16mask; };
__global__ void __launch_bounds__(256) convert_multi(CvtSet p) {
    int y = blockIdx.y;
    int i = blockIdx.x * 256 + threadIdx.x;
    if (i >= p.n4) return;
    float4 v = ((const float4*)p.s[y])[i];
    unsigned h01, l01, h23, l23;
    if ((p.f16mask >> y) & 1) { split2h(v.x, v.y, h01, l01); split2h(v.z, v.w, h23, l23); }
    else                      { split2(v.x, v.y, h01, l01);  split2(v.z, v.w, h23, l23); }
    ((uint2*)p.h[y])[i] = make_uint2(h01, h23);
    ((uint2*)p.l[y])[i] = make_uint2(l01, l23);
}

// GEMM parameter block
struct GP {
    const bf16 *Ahi, *Alo, *Bhi, *Blo;
    float* Cf; bf16 *Chi, *Clo;
    const float *bias;
    int K;
};
struct GP3 { GP g[3]; };

// ---------------------------------------------------------------------------
// mma.sync split GEMM (BK=32, 2-stage cp.async, one sync per chunk).
// MODE 0: QKV proj. z<2 (Q,K): bf16 3-term -> bf16 hi/lo planes.
//         z==2 (V): fp16 2-term (vhi+vlo)·Wvhi -> single fp16 plane.
// MODE 1: out proj, fp16 1-term (A = Ohi, B = Wo hi only). +bias -> Cf.
// ---------------------------------------------------------------------------
template<int BN, int MODE>
__global__ void __launch_bounds__(256, 2)
gemm_mma(GP3 P)
{
    constexpr int BM = 128, BK = 32, BKP = 40;
    constexpr int ASZ = BM * BKP * 2;
    constexpr int BSZ = BN * BKP * 2;
    constexpr int APL = (MODE == 1) ? 1 : 2;
    constexpr int BPL = (MODE == 1) ? 1 : 2;
    constexpr int STAGE = APL * ASZ + BPL * BSZ;
    constexpr int NF = BN / 16;
    constexpr int BV = BN / 64;

    GP p = P.g[MODE == 0 ? blockIdx.z : 0];
    extern __shared__ char smem[];
    const uint32_t sbase = s2u(smem);

    const int t = threadIdx.x, l = t & 31, wid = t >> 5;
    const int wm = wid & 3, wn = wid >> 2;
    const int gid = l >> 2, tig = l & 3;
    const int bc = blockIdx.x, br = blockIdx.y, z = blockIdx.z;
    const bool isV = (MODE == 0) && (z == 2);

    const bf16 *Ah = p.Ahi, *Al = p.Alo, *Bh = p.Bhi, *Bl = p.Blo;
    const int K = p.K;

    int aoff[2], boff[NF / 2];
    #pragma unroll
    for (int mi = 0; mi < 2; mi++)
        aoff[mi] = ((wm * 32 + mi * 16 + (l & 15)) * BKP + ((l & 16) >> 1)) * 2;
    #pragma unroll
    for (int pp = 0; pp < NF / 2; pp++)
        boff[pp] = ((wn * (BN / 2) + pp * 16 + (l & 7) + ((l >> 1) & 8)) * BKP + (l & 8)) * 2;

    float acc[2][NF][4];
    #pragma unroll
    for (int mi = 0; mi < 2; mi++)
        #pragma unroll
        for (int ni = 0; ni < NF; ni++)
            #pragma unroll
            for (int c = 0; c < 4; c++) acc[mi][ni][c] = 0.f;

    const int n = K / BK;

    auto issue = [&](int ck) {
        int k0 = ck * BK;
        uint32_t sd = sbase + (ck & 1) * STAGE;
        #pragma unroll
        for (int i = 0; i < 2; i++) {
            int vi = t + i * 256, row = vi >> 2, kc = (vi & 3) * 8;
            uint32_t off = (uint32_t)(row * BKP + kc) * 2;
            size_t g = (size_t)(br * 128 + row) * K + k0 + kc;
            CP16(sd + off, Ah + g);
            if (APL == 2) CP16(sd + ASZ + off, Al + g);
        }
        #pragma unroll
        for (int i = 0; i < BV; i++) {
            int vi = t + i * 256, row = vi >> 2, kc = (vi & 3) * 8;
            uint32_t off = (uint32_t)(row * BKP + kc) * 2;
            size_t g = (size_t)(bc * BN + row) * K + k0 + kc;
            CP16(sd + APL * ASZ + off, Bh + g);
            if (BPL == 2 && !isV) CP16(sd + APL * ASZ + BSZ + off, Bl + g);
        }
    };
    auto compute = [&](int buf) {
        uint32_t sb = sbase + buf * STAGE;
        #pragma unroll
        for (int ks = 0; ks < 2; ks++) {
            int kb = ks * 32;
            uint32_t ah[2][4], al[2][4];
            #pragma unroll
            for (int mi = 0; mi < 2; mi++) {
                ldm4(ah[mi], sb + aoff[mi] + kb);
                if (APL == 2) ldm4(al[mi], sb + ASZ + aoff[mi] + kb);
            }
            uint32_t bh[NF][2], bl[NF][2];
            #pragma unroll
            for (int pp = 0; pp < NF / 2; pp++) {
                uint32_t r[4];
                ldm4(r, sb + APL * ASZ + boff[pp] + kb);
                bh[2*pp][0] = r[0]; bh[2*pp][1] = r[1]; bh[2*pp+1][0] = r[2]; bh[2*pp+1][1] = r[3];
            }
            if (MODE == 0 && !isV) {
                #pragma unroll
                for (int pp = 0; pp < NF / 2; pp++) {
                    uint32_t r[4];
                    ldm4(r, sb + APL * ASZ + BSZ + boff[pp] + kb);
                    bl[2*pp][0] = r[0]; bl[2*pp][1] = r[1]; bl[2*pp+1][0] = r[2]; bl[2*pp+1][1] = r[3];
                }
            }
            if (MODE == 1) {
                #pragma unroll
                for (int mi = 0; mi < 2; mi++)
                    #pragma unroll
                    for (int ni = 0; ni < NF; ni++)
                        mma_fp(acc[mi][ni], ah[mi], bh[ni]);
            } else if (isV) {
                #pragma unroll
                for (int mi = 0; mi < 2; mi++)
                    #pragma unroll
                    for (int ni = 0; ni < NF; ni++)
                        mma_fp(acc[mi][ni], ah[mi], bh[ni]);
                #pragma unroll
                for (int mi = 0; mi < 2; mi++)
                    #pragma unroll
                    for (int ni = 0; ni < NF; ni++)
                        mma_fp(acc[mi][ni], al[mi], bh[ni]);
            } else {
                #pragma unroll
                for (int mi = 0; mi < 2; mi++)
                    #pragma unroll
                    for (int ni = 0; ni < NF; ni++)
                        mma_bf(acc[mi][ni], ah[mi], bh[ni]);
                #pragma unroll
                for (int mi = 0; mi < 2; mi++)
                    #pragma unroll
                    for (int ni = 0; ni < NF; ni++)
                        mma_bf(acc[mi][ni], ah[mi], bl[ni]);
                #pragma unroll
                for (int mi = 0; mi < 2; mi++)
                    #pragma unroll
                    for (int ni = 0; ni < NF; ni++)
                        mma_bf(acc[mi][ni], al[mi], bh[ni]);
            }
        }
    };

    issue(0); CP_COMMIT();
    for (int ck = 0; ck < n; ck++) {
        CP_WAIT0();
        __syncthreads();
        if (ck + 1 < n) issue(ck + 1);
        compute(ck & 1);
        CP_COMMIT();
    }

    #pragma unroll
    for (int mi = 0; mi < 2; mi++)
        #pragma unroll
        for (int ni = 0; ni < NF; ni++)
            #pragma unroll
            for (int h = 0; h < 2; h++) {
                int gi = br * 128 + wm * 32 + mi * 16 + gid + h * 8;
                int gj = bc * BN + wn * (BN / 2) + ni * 8 + tig * 2;
                float v0 = acc[mi][ni][h * 2 + 0];
                float v1 = acc[mi][ni][h * 2 + 1];
                if (MODE == 1) {
                    v0 += p.bias[gj]; v1 += p.bias[gj + 1];
                    *(float2*)&p.Cf[(size_t)gi * DI + gj] = make_float2(v0, v1);
                } else {
                    v0 += p.bias[gj]; v1 += p.bias[gj + 1];
                    size_t e = (((size_t)((gi >> 11) * HI + (gj >> 6)) * LI + (gi & 2047)) << 6) + (gj & 63);
                    if (isV) {
                        ((unsigned*)p.Chi)[e >> 1] = pack2h(v0, v1);
                    } else {
                        unsigned H, L;
                        split2(v0, v1, H, L);
                        ((unsigned*)p.Chi)[e >> 1] = H;
                        ((unsigned*)p.Clo)[e >> 1] = L;
                    }
                }
            }
}

// ---------------------------------------------------------------------------
// Fused attention: grid (br=16, z=64), 8 warps x 16 rows, 64-wide KV tiles.
// Pass 1: S = QK^T (bf16 3-term), online softmax stats in registers.
// Pass 2: recompute S (bit-identical), p = exp(s-M)/S written directly to attn,
//         P fed from registers into P·V (fp16 1-term).
// ---------------------------------------------------------------------------
__global__ void __launch_bounds__(256, 2)
fused_attn(const bf16* __restrict__ Qhi, const bf16* __restrict__ Qlo,
           const bf16* __restrict__ Khi, const bf16* __restrict__ Klo,
           const bf16* __restrict__ Vt,
           float* __restrict__ attn, bf16* __restrict__ Ohi)
{
    constexpr int PAN = 10240, KPAN = 5120, VPAN = 5120;
    constexpr int KSLOT = 4 * KPAN, VSLOT = 2 * VPAN;
    constexpr int KBASE = 4 * PAN;
    constexpr int VBASE = KBASE + 2 * KSLOT;     // total 102400
    extern __shared__ char smem[];
    const uint32_t sb = s2u(smem);

    const int t = threadIdx.x, l = t & 31, wid = t >> 5;
    const int gid = l >> 2, tig = l & 3;
    const int br = blockIdx.x, z = blockIdx.y;

    const bf16* Ah = Qhi + (size_t)z * LI * 64;
    const bf16* Aq = Qlo + (size_t)z * LI * 64;
    const bf16* Bh = Khi + (size_t)z * LI * 64;
    const bf16* Bl = Klo + (size_t)z * LI * 64;
    const bf16* Vp = Vt + (size_t)z * 64 * LI;
    float* Cf = attn + ((size_t)((z & 15) * BI + (z >> 4))) * LI * LI;

    const int aoffQ = ((wid * 16 + (l & 15)) * 40 + ((l & 16) >> 1)) * 2;
    int boff[4];
    #pragma unroll
    for (int pp = 0; pp < 4; pp++)
        boff[pp] = ((pp * 16 + (l & 7) + ((l >> 1) & 8)) * 40 + (l & 8)) * 2;

    #pragma unroll
    for (int ck = 0; ck < 2; ck++)
        #pragma unroll
        for (int i = 0; i < 2; i++) {
            int vi = t + i * 256, row = vi >> 2, kc = (vi & 3) * 8;
            uint32_t off = (uint32_t)(row * 40 + kc) * 2;
            size_t g = (size_t)(br * 128 + row) * 64 + ck * 32 + kc;
            CP16(sb + ck * 2 * PAN + off,       Ah + g);
            CP16(sb + ck * 2 * PAN + PAN + off, Aq + g);
        }
    CP_COMMIT();

    auto issueK = [&](int tile) {
        int row = t >> 2, kc = (t & 3) * 8;
        uint32_t base = sb + KBASE + (tile & 1) * KSLOT;
        uint32_t off = (uint32_t)(row * 40 + kc) * 2;
        #pragma unroll
        for (int p = 0; p < 2; p++) {
            size_t g = (size_t)(tile * 64 + row) * 64 + p * 32 + kc;
            CP16(base + p * 2 * KPAN + off,        Bh + g);
            CP16(base + p * 2 * KPAN + KPAN + off, Bl + g);
        }
    };
    auto issueV = [&](int tile) {
        int row = t >> 2, kc = (t & 3) * 8;
        uint32_t base = sb + VBASE + (tile & 1) * VSLOT;
        uint32_t off = (uint32_t)(row * 40 + kc) * 2;
        #pragma unroll
        for (int p = 0; p < 2; p++)
            CP16(base + p * VPAN + off, Vp + (size_t)row * LI + tile * 64 + p * 32 + kc);
    };

    float S[8][4], O[8][4];
    #pragma unroll
    for (int ni = 0; ni < 8; ni++)
        #pragma unroll
        for (int c = 0; c < 4; c++) O[ni][c] = 0.f;

    auto computeS = [&](int slot) {
        #pragma unroll
        for (int ni = 0; ni < 8; ni++)
            #pragma unroll
            for (int c = 0; c < 4; c++) S[ni][c] = 0.f;
        uint32_t kbase = sb + KBASE + slot * KSLOT;
        #pragma unroll
        for (int p = 0; p < 2; p++)
            #pragma unroll
            for (int ks = 0; ks < 2; ks++) {
                int kb = ks * 32;
                uint32_t ah[4], aq[4];
                ldm4(ah, sb + p * 2 * PAN + aoffQ + kb);
                ldm4(aq, sb + p * 2 * PAN + PAN + aoffQ + kb);
                uint32_t bf[8][2];
                #pragma unroll
                for (int pp = 0; pp < 4; pp++) {
                    uint32_t r[4];
                    ldm4(r, kbase + p * 2 * KPAN + boff[pp] + kb);
                    bf[2*pp][0] = r[0]; bf[2*pp][1] = r[1]; bf[2*pp+1][0] = r[2]; bf[2*pp+1][1] = r[3];
                }
                #pragma unroll
                for (int ni = 0; ni < 8; ni++) mma_bf(S[ni], ah, bf[ni]);
                #pragma unroll
                for (int ni = 0; ni < 8; ni++) mma_bf(S[ni], aq, bf[ni]);
                #pragma unroll
                for (int pp = 0; pp < 4; pp++) {
                    uint32_t r[4];
                    ldm4(r, kbase + p * 2 * KPAN + KPAN + boff[pp] + kb);
                    bf[2*pp][0] = r[0]; bf[2*pp][1] = r[1]; bf[2*pp+1][0] = r[2]; bf[2*pp+1][1] = r[3];
                }
                #pragma unroll
                for (int ni = 0; ni < 8; ni++) mma_bf(S[ni], ah, bf[ni]);
            }
    };

    float rm[2] = {-INFINITY, -INFINITY}, rs[2] = {0.f, 0.f};
    const int gi0 = br * 128 + wid * 16 + gid;

    // ---- pass 1 ----
    issueK(0); CP_COMMIT();
    for (int tile = 0; tile < 32; tile++) {
        CP_WAIT0();
        __syncthreads();
        if (tile + 1 < 32) issueK(tile + 1);
        CP_COMMIT();
        computeS(tile & 1);
        #pragma unroll
        for (int ni = 0; ni < 8; ni++)
            #pragma unroll
            for (int c = 0; c < 4; c++) {
                int gi = gi0 + (c >> 1) * 8;
                int gj = tile * 64 + ni * 8 + tig * 2 + (c & 1);
                float v = S[ni][c] * 0.125f;
                if (gi == gj) v = -INFINITY;
                S[ni][c] = v;
            }
        #pragma unroll
        for (int h = 0; h < 2; h++) {
            float m = -INFINITY;
            #pragma unroll
            for (int ni = 0; ni < 8; ni++) {
                m = fmaxf(m, S[ni][h*2+0]); m = fmaxf(m, S[ni][h*2+1]);
            }
            m = fmaxf(m, __shfl_xor_sync(0xffffffffu, m, 1));
            m = fmaxf(m, __shfl_xor_sync(0xffffffffu, m, 2));
            float sl = 0.f;
            #pragma unroll
            for (int ni = 0; ni < 8; ni++) {
                sl += __expf(S[ni][h*2+0] - m); sl += __expf(S[ni][h*2+1] - m);
            }
            sl += __shfl_xor_sync(0xffffffffu, sl, 1);
            sl += __shfl_xor_sync(0xffffffffu, sl, 2);
            float mo = rm[h], mn = fmaxf(mo, m);
            rs[h] = rs[h] * __expf(mo - mn) + sl * __expf(m - mn);
            rm[h] = mn;
        }
    }
    float Mv[2] = {rm[0], rm[1]};
    float Iv[2] = {1.f / rs[0], 1.f / rs[1]};

    // ---- pass 2 ----
    __syncthreads();
    issueK(0); issueV(0); CP_COMMIT();
    for (int tile = 0; tile < 32; tile++) {
        CP_WAIT0();
        __syncthreads();
        if (tile + 1 < 32) { issueK(tile + 1); issueV(tile + 1); }
        CP_COMMIT();
        computeS(tile & 1);
        #pragma unroll
        for (int ni = 0; ni < 8; ni++) {
            #pragma unroll
            for (int c = 0; c < 4; c++) {
                int gi = gi0 + (c >> 1) * 8;
                int gj = tile * 64 + ni * 8 + tig * 2 + (c & 1);
                float v = S[ni][c] * 0.125f;
                if (gi == gj) v = -INFINITY;
                S[ni][c] = __expf(v - Mv[c >> 1]) * Iv[c >> 1];
            }
            int gj0 = tile * 64 + ni * 8 + tig * 2;
            *(float2*)&Cf[(size_t)gi0 * LI + gj0]       = make_float2(S[ni][0], S[ni][1]);
            *(float2*)&Cf[(size_t)(gi0 + 8) * LI + gj0] = make_float2(S[ni][2], S[ni][3]);
        }
        uint32_t vbase = sb + VBASE + (tile & 1) * VSLOT;
        #pragma unroll
        for (int j = 0; j < 4; j++) {
            uint32_t aP[4] = { pack2h(S[2*j][0],   S[2*j][1]),   pack2h(S[2*j][2],   S[2*j][3]),
                               pack2h(S[2*j+1][0], S[2*j+1][1]), pack2h(S[2*j+1][2], S[2*j+1][3]) };
            int p = j >> 1, kb = (j & 1) * 32;
            uint32_t vb[8][2];
            #pragma unroll
            for (int pp = 0; pp < 4; pp++) {
                uint32_t r[4];
                ldm4(r, vbase + p * VPAN + boff[pp] + kb);
                vb[2*pp][0] = r[0]; vb[2*pp][1] = r[1]; vb[2*pp+1][0] = r[2]; vb[2*pp+1][1] = r[3];
            }
            #pragma unroll
            for (int ni = 0; ni < 8; ni++) mma_fp(O[ni], aP, vb[ni]);
        }
    }

    #pragma unroll
    for (int ni = 0; ni < 8; ni++)
        #pragma unroll
        for (int h = 0; h < 2; h++) {
            int gi = gi0 + h * 8;
            int gj = ni * 8 + tig * 2;
            size_t e = ((size_t)(z >> 4) * LI + gi) * DI + (z & 15) * 64 + gj;
            ((unsigned*)Ohi)[e >> 1] = pack2h(O[ni][h*2], O[ni][h*2+1]);
        }
}

// ---------------- V transpose (single plane): [bh][l][64] -> [bh][64][2048] --
__global__ void __launch_bounds__(256) transpose_bf(const bf16* __restrict__ ih,
                                                    bf16* __restrict__ oh) {
    __shared__ bf16 th[32][33];
    int z = blockIdx.z, l0 = blockIdx.y * 32, d0 = blockIdx.x * 32;
    int x = threadIdx.x, y = threadIdx.y;
    #pragma unroll
    for (int i = 0; i < 32; i += 8) {
        size_t g = ((size_t)z * LI + l0 + y + i) * 64 + d0 + x;
        th[y + i][x] = ih[g];
    }
    __syncthreads();
    #pragma unroll
    for (int i = 0; i < 32; i += 8) {
        size_t g = ((size_t)z * 64 + d0 + y + i) * LI + l0 + x;
        oh[g] = th[x][y + i];
    }
}

// ---------------- residual + LayerNorm ----------------
__device__ __forceinline__ float warpSum(float v) {
    #pragma unroll
    for (int o = 16; o; o >>= 1) v += __shfl_xor_sync(0xffffffffu, v, o);
    return v;
}
__global__ void __launch_bounds__(256) ln_kernel(const float* __restrict__ o2, const float* __restrict__ res,
                                                 const float* __restrict__ gamma, const float* __restrict__ beta,
                                                 float* __restrict__ out) {
    size_t row = blockIdx.x;
    int t = threadIdx.x;
    float4 a = ((const float4*)(o2 + row * DI))[t];
    float4 r = ((const float4*)(res + row * DI))[t];
    float x0 = a.x + r.x, x1 = a.y + r.y, x2 = a.z + r.z, x3 = a.w + r.w;
    float s = x0 + x1 + x2 + x3, sq = x0 * x0 + x1 * x1 + x2 * x2 + x3 * x3;
    s = warpSum(s); sq = warpSum(sq);
    __shared__ float rs[8], rq[8];
    if ((t & 31) == 0) { rs[t >> 5] = s; rq[t >> 5] = sq; }
    __syncthreads();
    s = 0.f; sq = 0.f;
    #pragma unroll
    for (int i = 0; i < 8; i++) { s += rs[i]; sq += rq[i]; }
    float mu = s * (1.0f / DI);
    float rstd = rsqrtf(sq * (1.0f / DI) - mu * mu + 1e-5f);
    float4 g = ((const float4*)gamma)[t], b = ((const float4*)beta)[t];
    float4 o;
    o.x = (x0 - mu) * rstd * g.x + b.x; o.y = (x1 - mu) * rstd * g.y + b.y;
    o.z = (x2 - mu) * rstd * g.z + b.z; o.w = (x3 - mu) * rstd * g.w + b.w;
    ((float4*)(out + row * DI))[t] = o;
}

// ---------------------------------------------------------------------------
extern "C" void kernel_launch(void* const* d_in, const int* in_sizes, int n_in,
                              void* d_out, int out_size)
{
    const float* q  = (const float*)d_in[0];
    const float* k  = (const float*)d_in[1];
    const float* v  = (const float*)d_in[2];
    const float* Wq = (const float*)d_in[3];  const float* bq = (const float*)d_in[4];
    const float* Wk = (const float*)d_in[5];  const float* bk = (const float*)d_in[6];
    const float* Wv = (const float*)d_in[7];  const float* bv = (const float*)d_in[8];
    const float* Wo = (const float*)d_in[9];  const float* bo = (const float*)d_in[10];
    const float* gamma = (const float*)d_in[11];
    const float* beta  = (const float*)d_in[12];

    float* out  = (float*)d_out;
    float* attn = out + (size_t)BI * LI * DI;

    bf16 *qhi,*qlo,*khi,*klo,*vhi,*vlo,*wqh,*wql,*wkh,*wkl,*wvh,*wvl,*woh,*wol;
    bf16 *Qhi,*Qlo,*Khi,*Klo,*VHh,*Vth,*Ohi;
    float *O2;
    cudaGetSymbolAddress((void**)&qhi, g_qhi);  cudaGetSymbolAddress((void**)&qlo, g_qlo);
    cudaGetSymbolAddress((void**)&khi, g_khi);  cudaGetSymbolAddress((void**)&klo, g_klo);
    cudaGetSymbolAddress((void**)&vhi, g_vhi);  cudaGetSymbolAddress((void**)&vlo, g_vlo);
    cudaGetSymbolAddress((void**)&wqh, g_wqhi); cudaGetSymbolAddress((void**)&wql, g_wqlo);
    cudaGetSymbolAddress((void**)&wkh, g_wkhi); cudaGetSymbolAddress((void**)&wkl, g_wklo);
    cudaGetSymbolAddress((void**)&wvh, g_wvhi); cudaGetSymbolAddress((void**)&wvl, g_wvlo);
    cudaGetSymbolAddress((void**)&woh, g_wohi); cudaGetSymbolAddress((void**)&wol, g_wolo);
    cudaGetSymbolAddress((void**)&Qhi, g_Qhi);  cudaGetSymbolAddress((void**)&Qlo, g_Qlo);
    cudaGetSymbolAddress((void**)&Khi, g_Khi);  cudaGetSymbolAddress((void**)&Klo, g_Klo);
    cudaGetSymbolAddress((void**)&VHh, g_VHhi);
    cudaGetSymbolAddress((void**)&Vth, g_Vthi);
    cudaGetSymbolAddress((void**)&Ohi, g_Ohi);
    cudaGetSymbolAddress((void**)&O2,  g_O2);

    const int SM0 = 2 * (2*128*40*2 + 2*128*40*2);   // 81920 (MODE0)
    const int SM1 = 2 * (1*128*40*2 + 1*128*40*2);   // 40960 (MODE1, 1-term)
    const int SMF = 102400;                          // fused_attn
    cudaFuncSetAttribute(gemm_mma<128,0>, cudaFuncAttributeMaxDynamicSharedMemorySize, SM0);
    cudaFuncSetAttribute(gemm_mma<128,1>, cudaFuncAttributeMaxDynamicSharedMemorySize, SM1);
    cudaFuncSetAttribute(fused_attn,      cudaFuncAttributeMaxDynamicSharedMemorySize, SMF);

    // input splits: q,k bf16; v fp16
    CvtSet ci; ci.s[0]=q; ci.s[1]=k; ci.s[2]=v; ci.s[3]=q;
    ci.h[0]=qhi; ci.h[1]=khi; ci.h[2]=vhi; ci.h[3]=qhi;
    ci.l[0]=qlo; ci.l[1]=klo; ci.l[2]=vlo; ci.l[3]=qlo;
    ci.n4 = 2097152; ci.f16mask = 0b100;
    convert_multi<<<dim3(8192,3), 256>>>(ci);
    // weight splits: Wq,Wk bf16; Wv,Wo fp16
    CvtSet cw; cw.s[0]=Wq; cw.s[1]=Wk; cw.s[2]=Wv; cw.s[3]=Wo;
    cw.h[0]=wqh; cw.h[1]=wkh; cw.h[2]=wvh; cw.h[3]=woh;
    cw.l[0]=wql; cw.l[1]=wkl; cw.l[2]=wvl; cw.l[3]=wol;
    cw.n4 = 262144; cw.f16mask = 0b1100;
    convert_multi<<<dim3(1024,4), 256>>>(cw);

    // merged QKV projections (Q,K bf16 3-term; V fp16 2-term -> fp16 plane)
    GP3 P; memset(&P, 0, sizeof(P));
    P.g[0] = { qhi,qlo, wqh,wql, nullptr,Qhi,Qlo, bq, DI };
    P.g[1] = { khi,klo, wkh,wkl, nullptr,Khi,Klo, bk, DI };
    P.g[2] = { vhi,vlo, wvh,nullptr, nullptr,VHh,nullptr, bv, DI };
    gemm_mma<128,0><<<dim3(8,64,3), 256, SM0>>>(P);

    transpose_bf<<<dim3(2,64,64), dim3(32,8)>>>(VHh, Vth);

    // fused two-pass attention
    fused_attn<<<dim3(16,64), 256, SMF>>>(Qhi,Qlo, Khi,Klo, Vth, attn, Ohi);

    // output projection (fp16 1-term) + residual/LN
    GP3 P4; memset(&P4, 0, sizeof(P4));
    P4.g[0] = { Ohi,nullptr, woh,nullptr, O2,nullptr,nullptr, bo, DI };
    gemm_mma<128,1><<<dim3(8,64,1), 256, SM1>>>(P4);
    ln_kernel<<<BI*LI, 256>>>(O2, q, gamma, beta, out);
}

// round 17
// speedup vs baseline: 1.2624x; 1.0072x over previous
#include <cuda_runtime.h>
#include <cuda_bf16.h>
#include <cuda_fp16.h>
#include <cstdint>
#include <math.h>

#define BI 4
#define LI 2048
#define DI 1024
#define HI 16

typedef __nv_bfloat16 bf16;
#define ELI ((size_t)8192*1024)
#define ELW ((size_t)1024*1024)

// device-global scratch (allocation-free rule). 16-bit buffers hold bf16 OR fp16 bits.
__device__ __align__(256) bf16 g_qhi[ELI], g_qlo[ELI], g_khi[ELI], g_klo[ELI], g_vhi[ELI], g_vlo[ELI];
__device__ __align__(256) bf16 g_wqhi[ELW], g_wqlo[ELW], g_wkhi[ELW], g_wklo[ELW];
__device__ __align__(256) bf16 g_wvhi[ELW], g_wvlo[ELW], g_wohi[ELW], g_wolo[ELW];
__device__ __align__(256) bf16 g_Qhi[ELI], g_Qlo[ELI], g_Khi[ELI], g_Klo[ELI];   // [bh][l][64] bf16
__device__ __align__(256) bf16 g_VHhi[ELI];                                      // [bh][l][64] fp16
__device__ __align__(256) bf16 g_Vthi[ELI];                                      // [bh][64][2048] fp16
__device__ __align__(256) bf16 g_Ohi[ELI];                                       // [8192][1024] fp16
__device__ __align__(256) float g_O2[ELI];
// unnormalized fp16 probabilities, thread-blocked: [z][br][tile][t][32 halves]
__device__ __align__(256) bf16 g_P16[(size_t)64*16*32*256*32];
// per (z,row,tile) tile max
__device__ __align__(256) float g_mt[(size_t)64*2048*32];

// ---------------- helpers ----------------
__device__ __forceinline__ uint32_t s2u(const void* p) {
    uint32_t a;
    asm("{ .reg .u64 t; cvta.to.shared.u64 t, %1; cvt.u32.u64 %0, t; }" : "=r"(a) : "l"(p));
    return a;
}
__device__ __forceinline__ void ldm4(uint32_t* r, uint32_t a) {
    asm volatile("ldmatrix.sync.aligned.m8n8.x4.shared.b16 {%0,%1,%2,%3}, [%4];"
                 : "=r"(r[0]), "=r"(r[1]), "=r"(r[2]), "=r"(r[3]) : "r"(a));
}
__device__ __forceinline__ void mma_bf(float* c, const uint32_t* a, const uint32_t* b) {
    asm volatile("mma.sync.aligned.m16n8k16.row.col.f32.bf16.bf16.f32 "
                 "{%0,%1,%2,%3}, {%4,%5,%6,%7}, {%8,%9}, {%0,%1,%2,%3};"
                 : "+f"(c[0]), "+f"(c[1]), "+f"(c[2]), "+f"(c[3])
                 : "r"(a[0]), "r"(a[1]), "r"(a[2]), "r"(a[3]), "r"(b[0]), "r"(b[1]));
}
__device__ __forceinline__ void mma_fp(float* c, const uint32_t* a, const uint32_t* b) {
    asm volatile("mma.sync.aligned.m16n8k16.row.col.f32.f16.f16.f32 "
                 "{%0,%1,%2,%3}, {%4,%5,%6,%7}, {%8,%9}, {%0,%1,%2,%3};"
                 : "+f"(c[0]), "+f"(c[1]), "+f"(c[2]), "+f"(c[3])
                 : "r"(a[0]), "r"(a[1]), "r"(a[2]), "r"(a[3]), "r"(b[0]), "r"(b[1]));
}
#define CP16(d, s)   asm volatile("cp.async.cg.shared.global [%0], [%1], 16;" :: "r"(d), "l"(s))
#define CP_COMMIT()  asm volatile("cp.async.commit_group;")
#define CP_WAIT0()   asm volatile("cp.async.wait_group 0;")

__device__ __forceinline__ void split2(float x0, float x1, unsigned& H, unsigned& L) {
    bf16 h0 = __float2bfloat16(x0), h1 = __float2bfloat16(x1);
    bf16 l0 = __float2bfloat16(x0 - __bfloat162float(h0));
    bf16 l1 = __float2bfloat16(x1 - __bfloat162float(h1));
    H = (unsigned)__bfloat16_as_ushort(h0) | ((unsigned)__bfloat16_as_ushort(h1) << 16);
    L = (unsigned)__bfloat16_as_ushort(l0) | ((unsigned)__bfloat16_as_ushort(l1) << 16);
}
__device__ __forceinline__ void split2h(float x0, float x1, unsigned& H, unsigned& L) {
    __half h0 = __float2half_rn(x0), h1 = __float2half_rn(x1);
    __half l0 = __float2half_rn(x0 - __half2float(h0));
    __half l1 = __float2half_rn(x1 - __half2float(h1));
    H = (unsigned)__half_as_ushort(h0) | ((unsigned)__half_as_ushort(h1) << 16);
    L = (unsigned)__half_as_ushort(l0) | ((unsigned)__half_as_ushort(l1) << 16);
}
__device__ __forceinline__ unsigned pack2h(float x0, float x1) {
    __half2 h = __floats2half2_rn(x0, x1);
    return *reinterpret_cast<unsigned*>(&h);
}

struct CvtSet { const float* s[4]; bf16* h[4]; bf16* l[4]; int n4; int f16mask; };
__global__ void __launch_bounds__(256) convert_multi(CvtSet p) {
    int y = blockIdx.y;
    int i = blockIdx.x * 256 + threadIdx.x;
    if (i >= p.n4) return;
    float4 v = ((const float4*)p.s[y])[i];
    unsigned h01, l01, h23, l23;
    if ((p.f16mask >> y) & 1) { split2h(v.x, v.y, h01, l01); split2h(v.z, v.w, h23, l23); }
    else                      { split2(v.x, v.y, h01, l01);  split2(v.z, v.w, h23, l23); }
    ((uint2*)p.h[y])[i] = make_uint2(h01, h23);
    ((uint2*)p.l[y])[i] = make_uint2(l01, l23);
}

// GEMM parameter block
struct GP {
    const bf16 *Ahi, *Alo, *Bhi, *Blo;
    float* Cf; bf16 *Chi, *Clo;
    const float *bias;
    int K;
};
struct GP3 { GP g[3]; };

// ---------------------------------------------------------------------------
// mma.sync split GEMM (BK=32, 2-stage cp.async, one sync per chunk).
// MODE 0: QKV proj. z<2 (Q,K): bf16 3-term -> bf16 hi/lo planes.
//         z==2 (V): fp16 2-term (vhi+vlo)·Wvhi -> single fp16 plane.
// MODE 1: out proj, fp16 1-term (A = Ohi, B = Wo hi only). +bias -> Cf.
// ---------------------------------------------------------------------------
template<int BN, int MODE>
__global__ void __launch_bounds__(256, 2)
gemm_mma(GP3 P)
{
    constexpr int BM = 128, BK = 32, BKP = 40;
    constexpr int ASZ = BM * BKP * 2;
    constexpr int BSZ = BN * BKP * 2;
    constexpr int APL = (MODE == 1) ? 1 : 2;
    constexpr int BPL = (MODE == 1) ? 1 : 2;
    constexpr int STAGE = APL * ASZ + BPL * BSZ;
    constexpr int NF = BN / 16;
    constexpr int BV = BN / 64;

    GP p = P.g[MODE == 0 ? blockIdx.z : 0];
    extern __shared__ char smem[];
    const uint32_t sbase = s2u(smem);

    const int t = threadIdx.x, l = t & 31, wid = t >> 5;
    const int wm = wid & 3, wn = wid >> 2;
    const int gid = l >> 2, tig = l & 3;
    const int bc = blockIdx.x, br = blockIdx.y, z = blockIdx.z;
    const bool isV = (MODE == 0) && (z == 2);

    const bf16 *Ah = p.Ahi, *Al = p.Alo, *Bh = p.Bhi, *Bl = p.Blo;
    const int K = p.K;

    int aoff[2], boff[NF / 2];
    #pragma unroll
    for (int mi = 0; mi < 2; mi++)
        aoff[mi] = ((wm * 32 + mi * 16 + (l & 15)) * BKP + ((l & 16) >> 1)) * 2;
    #pragma unroll
    for (int pp = 0; pp < NF / 2; pp++)
        boff[pp] = ((wn * (BN / 2) + pp * 16 + (l & 7) + ((l >> 1) & 8)) * BKP + (l & 8)) * 2;

    float acc[2][NF][4];
    #pragma unroll
    for (int mi = 0; mi < 2; mi++)
        #pragma unroll
        for (int ni = 0; ni < NF; ni++)
            #pragma unroll
            for (int c = 0; c < 4; c++) acc[mi][ni][c] = 0.f;

    const int n = K / BK;

    auto issue = [&](int ck) {
        int k0 = ck * BK;
        uint32_t sd = sbase + (ck & 1) * STAGE;
        #pragma unroll
        for (int i = 0; i < 2; i++) {
            int vi = t + i * 256, row = vi >> 2, kc = (vi & 3) * 8;
            uint32_t off = (uint32_t)(row * BKP + kc) * 2;
            size_t g = (size_t)(br * 128 + row) * K + k0 + kc;
            CP16(sd + off, Ah + g);
            if (APL == 2) CP16(sd + ASZ + off, Al + g);
        }
        #pragma unroll
        for (int i = 0; i < BV; i++) {
            int vi = t + i * 256, row = vi >> 2, kc = (vi & 3) * 8;
            uint32_t off = (uint32_t)(row * BKP + kc) * 2;
            size_t g = (size_t)(bc * BN + row) * K + k0 + kc;
            CP16(sd + APL * ASZ + off, Bh + g);
            if (BPL == 2 && !isV) CP16(sd + APL * ASZ + BSZ + off, Bl + g);
        }
    };
    auto compute = [&](int buf) {
        uint32_t sb = sbase + buf * STAGE;
        #pragma unroll
        for (int ks = 0; ks < 2; ks++) {
            int kb = ks * 32;
            uint32_t ah[2][4], al[2][4];
            #pragma unroll
            for (int mi = 0; mi < 2; mi++) {
                ldm4(ah[mi], sb + aoff[mi] + kb);
                if (APL == 2) ldm4(al[mi], sb + ASZ + aoff[mi] + kb);
            }
            uint32_t bh[NF][2], bl[NF][2];
            #pragma unroll
            for (int pp = 0; pp < NF / 2; pp++) {
                uint32_t r[4];
                ldm4(r, sb + APL * ASZ + boff[pp] + kb);
                bh[2*pp][0] = r[0]; bh[2*pp][1] = r[1]; bh[2*pp+1][0] = r[2]; bh[2*pp+1][1] = r[3];
            }
            if (MODE == 0 && !isV) {
                #pragma unroll
                for (int pp = 0; pp < NF / 2; pp++) {
                    uint32_t r[4];
                    ldm4(r, sb + APL * ASZ + BSZ + boff[pp] + kb);
                    bl[2*pp][0] = r[0]; bl[2*pp][1] = r[1]; bl[2*pp+1][0] = r[2]; bl[2*pp+1][1] = r[3];
                }
            }
            if (MODE == 1) {
                #pragma unroll
                for (int mi = 0; mi < 2; mi++)
                    #pragma unroll
                    for (int ni = 0; ni < NF; ni++)
                        mma_fp(acc[mi][ni], ah[mi], bh[ni]);
            } else if (isV) {
                #pragma unroll
                for (int mi = 0; mi < 2; mi++)
                    #pragma unroll
                    for (int ni = 0; ni < NF; ni++)
                        mma_fp(acc[mi][ni], ah[mi], bh[ni]);
                #pragma unroll
                for (int mi = 0; mi < 2; mi++)
                    #pragma unroll
                    for (int ni = 0; ni < NF; ni++)
                        mma_fp(acc[mi][ni], al[mi], bh[ni]);
            } else {
                #pragma unroll
                for (int mi = 0; mi < 2; mi++)
                    #pragma unroll
                    for (int ni = 0; ni < NF; ni++)
                        mma_bf(acc[mi][ni], ah[mi], bh[ni]);
                #pragma unroll
                for (int mi = 0; mi < 2; mi++)
                    #pragma unroll
                    for (int ni = 0; ni < NF; ni++)
                        mma_bf(acc[mi][ni], ah[mi], bl[ni]);
                #pragma unroll
                for (int mi = 0; mi < 2; mi++)
                    #pragma unroll
                    for (int ni = 0; ni < NF; ni++)
                        mma_bf(acc[mi][ni], al[mi], bh[ni]);
            }
        }
    };

    issue(0); CP_COMMIT();
    for (int ck = 0; ck < n; ck++) {
        CP_WAIT0();
        __syncthreads();
        if (ck + 1 < n) issue(ck + 1);
        compute(ck & 1);
        CP_COMMIT();
    }

    #pragma unroll
    for (int mi = 0; mi < 2; mi++)
        #pragma unroll
        for (int ni = 0; ni < NF; ni++)
            #pragma unroll
            for (int h = 0; h < 2; h++) {
                int gi = br * 128 + wm * 32 + mi * 16 + gid + h * 8;
                int gj = bc * BN + wn * (BN / 2) + ni * 8 + tig * 2;
                float v0 = acc[mi][ni][h * 2 + 0];
                float v1 = acc[mi][ni][h * 2 + 1];
                if (MODE == 1) {
                    v0 += p.bias[gj]; v1 += p.bias[gj + 1];
                    *(float2*)&p.Cf[(size_t)gi * DI + gj] = make_float2(v0, v1);
                } else {
                    v0 += p.bias[gj]; v1 += p.bias[gj + 1];
                    size_t e = (((size_t)((gi >> 11) * HI + (gj >> 6)) * LI + (gi & 2047)) << 6) + (gj & 63);
                    if (isV) {
                        ((unsigned*)p.Chi)[e >> 1] = pack2h(v0, v1);
                    } else {
                        unsigned H, L;
                        split2(v0, v1, H, L);
                        ((unsigned*)p.Chi)[e >> 1] = H;
                        ((unsigned*)p.Clo)[e >> 1] = L;
                    }
                }
            }
}

// ---------------------------------------------------------------------------
// Fused attention: grid (br=16, z=64), 8 warps x 16 rows, 64-wide KV tiles.
// Pass 1: S = QK^T (bf16 3-term), p_t = exp(s - m_tile) stored as fp16
//         (thread-blocked, coalesced), m_tile stored; online stats in regs.
// Pass 2: reload p_t, scale by exp(m_tile - M)·I in fp32, write fp32 attn,
//         feed P into P·V (fp16 1-term). No S recompute, no K reads.
// ---------------------------------------------------------------------------
__global__ void __launch_bounds__(256, 2)
fused_attn(const bf16* __restrict__ Qhi, const bf16* __restrict__ Qlo,
           const bf16* __restrict__ Khi, const bf16* __restrict__ Klo,
           const bf16* __restrict__ Vt,
           float* __restrict__ attn, bf16* __restrict__ Ohi,
           bf16* __restrict__ P16, float* __restrict__ mt)
{
    constexpr int PAN = 10240, KPAN = 5120, VPAN = 5120;
    constexpr int KSLOT = 4 * KPAN, VSLOT = 2 * VPAN;
    constexpr int KBASE = 4 * PAN;
    constexpr int VBASE = KBASE + 2 * KSLOT;     // total 102400
    extern __shared__ char smem[];
    const uint32_t sb = s2u(smem);

    const int t = threadIdx.x, l = t & 31, wid = t >> 5;
    const int gid = l >> 2, tig = l & 3;
    const int br = blockIdx.x, z = blockIdx.y;

    const bf16* Ah = Qhi + (size_t)z * LI * 64;
    const bf16* Aq = Qlo + (size_t)z * LI * 64;
    const bf16* Bh = Khi + (size_t)z * LI * 64;
    const bf16* Bl = Klo + (size_t)z * LI * 64;
    const bf16* Vp = Vt + (size_t)z * 64 * LI;
    float* Cf = attn + ((size_t)((z & 15) * BI + (z >> 4))) * LI * LI;
    uint4* Pblk = (uint4*)P16 + ((((size_t)z * 16 + br) * 32) * 256 + t) * 4;

    const int aoffQ = ((wid * 16 + (l & 15)) * 40 + ((l & 16) >> 1)) * 2;
    int boff[4];
    #pragma unroll
    for (int pp = 0; pp < 4; pp++)
        boff[pp] = ((pp * 16 + (l & 7) + ((l >> 1) & 8)) * 40 + (l & 8)) * 2;

    #pragma unroll
    for (int ck = 0; ck < 2; ck++)
        #pragma unroll
        for (int i = 0; i < 2; i++) {
            int vi = t + i * 256, row = vi >> 2, kc = (vi & 3) * 8;
            uint32_t off = (uint32_t)(row * 40 + kc) * 2;
            size_t g = (size_t)(br * 128 + row) * 64 + ck * 32 + kc;
            CP16(sb + ck * 2 * PAN + off,       Ah + g);
            CP16(sb + ck * 2 * PAN + PAN + off, Aq + g);
        }
    CP_COMMIT();

    auto issueK = [&](int tile) {
        int row = t >> 2, kc = (t & 3) * 8;
        uint32_t base = sb + KBASE + (tile & 1) * KSLOT;
        uint32_t off = (uint32_t)(row * 40 + kc) * 2;
        #pragma unroll
        for (int p = 0; p < 2; p++) {
            size_t g = (size_t)(tile * 64 + row) * 64 + p * 32 + kc;
            CP16(base + p * 2 * KPAN + off,        Bh + g);
            CP16(base + p * 2 * KPAN + KPAN + off, Bl + g);
        }
    };
    auto issueV = [&](int tile) {
        int row = t >> 2, kc = (t & 3) * 8;
        uint32_t base = sb + VBASE + (tile & 1) * VSLOT;
        uint32_t off = (uint32_t)(row * 40 + kc) * 2;
        #pragma unroll
        for (int p = 0; p < 2; p++)
            CP16(base + p * VPAN + off, Vp + (size_t)row * LI + tile * 64 + p * 32 + kc);
    };

    float S[8][4], O[8][4];
    #pragma unroll
    for (int ni = 0; ni < 8; ni++)
        #pragma unroll
        for (int c = 0; c < 4; c++) O[ni][c] = 0.f;

    auto computeS = [&](int slot) {
        #pragma unroll
        for (int ni = 0; ni < 8; ni++)
            #pragma unroll
            for (int c = 0; c < 4; c++) S[ni][c] = 0.f;
        uint32_t kbase = sb + KBASE + slot * KSLOT;
        #pragma unroll
        for (int p = 0; p < 2; p++)
            #pragma unroll
            for (int ks = 0; ks < 2; ks++) {
                int kb = ks * 32;
                uint32_t ah[4], aq[4];
                ldm4(ah, sb + p * 2 * PAN + aoffQ + kb);
                ldm4(aq, sb + p * 2 * PAN + PAN + aoffQ + kb);
                uint32_t bf[8][2];
                #pragma unroll
                for (int pp = 0; pp < 4; pp++) {
                    uint32_t r[4];
                    ldm4(r, kbase + p * 2 * KPAN + boff[pp] + kb);
                    bf[2*pp][0] = r[0]; bf[2*pp][1] = r[1]; bf[2*pp+1][0] = r[2]; bf[2*pp+1][1] = r[3];
                }
                #pragma unroll
                for (int ni = 0; ni < 8; ni++) mma_bf(S[ni], ah, bf[ni]);
                #pragma unroll
                for (int ni = 0; ni < 8; ni++) mma_bf(S[ni], aq, bf[ni]);
                #pragma unroll
                for (int pp = 0; pp < 4; pp++) {
                    uint32_t r[4];
                    ldm4(r, kbase + p * 2 * KPAN + KPAN + boff[pp] + kb);
                    bf[2*pp][0] = r[0]; bf[2*pp][1] = r[1]; bf[2*pp+1][0] = r[2]; bf[2*pp+1][1] = r[3];
                }
                #pragma unroll
                for (int ni = 0; ni < 8; ni++) mma_bf(S[ni], ah, bf[ni]);
            }
    };

    float rm[2] = {-INFINITY, -INFINITY}, rs[2] = {0.f, 0.f};
    const int gi0 = br * 128 + wid * 16 + gid;

    // ---- pass 1: stats + store p16/m_tile ----
    issueK(0); CP_COMMIT();
    for (int tile = 0; tile < 32; tile++) {
        CP_WAIT0();
        __syncthreads();
        if (tile + 1 < 32) issueK(tile + 1);
        CP_COMMIT();
        computeS(tile & 1);
        #pragma unroll
        for (int ni = 0; ni < 8; ni++)
            #pragma unroll
            for (int c = 0; c < 4; c++) {
                int gi = gi0 + (c >> 1) * 8;
                int gj = tile * 64 + ni * 8 + tig * 2 + (c & 1);
                float v = S[ni][c] * 0.125f;
                if (gi == gj) v = -INFINITY;
                S[ni][c] = v;
            }
        float mh[2];
        #pragma unroll
        for (int h = 0; h < 2; h++) {
            float m = -INFINITY;
            #pragma unroll
            for (int ni = 0; ni < 8; ni++) {
                m = fmaxf(m, S[ni][h*2+0]); m = fmaxf(m, S[ni][h*2+1]);
            }
            m = fmaxf(m, __shfl_xor_sync(0xffffffffu, m, 1));
            m = fmaxf(m, __shfl_xor_sync(0xffffffffu, m, 2));
            mh[h] = m;
        }
        // p = exp(s - m_tile) in place
        #pragma unroll
        for (int ni = 0; ni < 8; ni++)
            #pragma unroll
            for (int c = 0; c < 4; c++)
                S[ni][c] = __expf(S[ni][c] - mh[c >> 1]);
        #pragma unroll
        for (int h = 0; h < 2; h++) {
            float sl = 0.f;
            #pragma unroll
            for (int ni = 0; ni < 8; ni++) { sl += S[ni][h*2+0]; sl += S[ni][h*2+1]; }
            sl += __shfl_xor_sync(0xffffffffu, sl, 1);
            sl += __shfl_xor_sync(0xffffffffu, sl, 2);
            float mo = rm[h], mn = fmaxf(mo, mh[h]);
            rs[h] = rs[h] * __expf(mo - mn) + sl * __expf(mh[h] - mn);
            rm[h] = mn;
        }
        // store p16 (thread-blocked, 64B contiguous) + m_tile
        uint32_t pk[16];
        #pragma unroll
        for (int ni = 0; ni < 8; ni++)
            #pragma unroll
            for (int h = 0; h < 2; h++)
                pk[ni * 2 + h] = pack2h(S[ni][h*2], S[ni][h*2+1]);
        uint4* pd = Pblk + (size_t)tile * 256 * 4;
        pd[0] = make_uint4(pk[0],  pk[1],  pk[2],  pk[3]);
        pd[1] = make_uint4(pk[4],  pk[5],  pk[6],  pk[7]);
        pd[2] = make_uint4(pk[8],  pk[9],  pk[10], pk[11]);
        pd[3] = make_uint4(pk[12], pk[13], pk[14], pk[15]);
        if (tig == 0) {
            mt[((size_t)z * LI + gi0)     * 32 + tile] = mh[0];
            mt[((size_t)z * LI + gi0 + 8) * 32 + tile] = mh[1];
        }
    }
    float Mv[2] = {rm[0], rm[1]};
    float Iv[2] = {1.f / rs[0], 1.f / rs[1]};

    // ---- pass 2: reload p16, scale, write attn, P·V ----
    __syncthreads();
    issueV(0); CP_COMMIT();
    for (int tile = 0; tile < 32; tile++) {
        CP_WAIT0();
        __syncthreads();
        if (tile + 1 < 32) issueV(tile + 1);
        CP_COMMIT();

        float f0 = __expf(mt[((size_t)z * LI + gi0)     * 32 + tile] - Mv[0]) * Iv[0];
        float f1 = __expf(mt[((size_t)z * LI + gi0 + 8) * 32 + tile] - Mv[1]) * Iv[1];
        const uint4* pd = Pblk + (size_t)tile * 256 * 4;
        uint4 u0 = pd[0], u1 = pd[1], u2 = pd[2], u3 = pd[3];
        uint32_t pk[16] = { u0.x,u0.y,u0.z,u0.w, u1.x,u1.y,u1.z,u1.w,
                            u2.x,u2.y,u2.z,u2.w, u3.x,u3.y,u3.z,u3.w };
        #pragma unroll
        for (int ni = 0; ni < 8; ni++)
            #pragma unroll
            for (int h = 0; h < 2; h++) {
                __half2 hh = *reinterpret_cast<__half2*>(&pk[ni * 2 + h]);
                float2 v = __half22float2(hh);
                float f = h ? f1 : f0;
                v.x *= f; v.y *= f;
                S[ni][h*2+0] = v.x; S[ni][h*2+1] = v.y;
            }
        #pragma unroll
        for (int ni = 0; ni < 8; ni++) {
            int gj0 = tile * 64 + ni * 8 + tig * 2;
            *(float2*)&Cf[(size_t)gi0 * LI + gj0]       = make_float2(S[ni][0], S[ni][1]);
            *(float2*)&Cf[(size_t)(gi0 + 8) * LI + gj0] = make_float2(S[ni][2], S[ni][3]);
        }
        uint32_t vbase = sb + VBASE + (tile & 1) * VSLOT;
        #pragma unroll
        for (int j = 0; j < 4; j++) {
            uint32_t aP[4] = { pack2h(S[2*j][0],   S[2*j][1]),   pack2h(S[2*j][2],   S[2*j][3]),
                               pack2h(S[2*j+1][0], S[2*j+1][1]), pack2h(S[2*j+1][2], S[2*j+1][3]) };
            int p = j >> 1, kb = (j & 1) * 32;
            uint32_t vb[8][2];
            #pragma unroll
            for (int pp = 0; pp < 4; pp++) {
                uint32_t r[4];
                ldm4(r, vbase + p * VPAN + boff[pp] + kb);
                vb[2*pp][0] = r[0]; vb[2*pp][1] = r[1]; vb[2*pp+1][0] = r[2]; vb[2*pp+1][1] = r[3];
            }
            #pragma unroll
            for (int ni = 0; ni < 8; ni++) mma_fp(O[ni], aP, vb[ni]);
        }
    }

    #pragma unroll
    for (int ni = 0; ni < 8; ni++)
        #pragma unroll
        for (int h = 0; h < 2; h++) {
            int gi = gi0 + h * 8;
            int gj = ni * 8 + tig * 2;
            size_t e = ((size_t)(z >> 4) * LI + gi) * DI + (z & 15) * 64 + gj;
            ((unsigned*)Ohi)[e >> 1] = pack2h(O[ni][h*2], O[ni][h*2+1]);
        }
}

// ---------------- V transpose (single plane): [bh][l][64] -> [bh][64][2048] --
__global__ void __launch_bounds__(256) transpose_bf(const bf16* __restrict__ ih,
                                                    bf16* __restrict__ oh) {
    __shared__ bf16 th[32][33];
    int z = blockIdx.z, l0 = blockIdx.y * 32, d0 = blockIdx.x * 32;
    int x = threadIdx.x, y = threadIdx.y;
    #pragma unroll
    for (int i = 0; i < 32; i += 8) {
        size_t g = ((size_t)z * LI + l0 + y + i) * 64 + d0 + x;
        th[y + i][x] = ih[g];
    }
    __syncthreads();
    #pragma unroll
    for (int i = 0; i < 32; i += 8) {
        size_t g = ((size_t)z * 64 + d0 + y + i) * LI + l0 + x;
        oh[g] = th[x][y + i];
    }
}

// ---------------- residual + LayerNorm ----------------
__device__ __forceinline__ float warpSum(float v) {
    #pragma unroll
    for (int o = 16; o; o >>= 1) v += __shfl_xor_sync(0xffffffffu, v, o);
    return v;
}
__global__ void __launch_bounds__(256) ln_kernel(const float* __restrict__ o2, const float* __restrict__ res,
                                                 const float* __restrict__ gamma, const float* __restrict__ beta,
                                                 float* __restrict__ out) {
    size_t row = blockIdx.x;
    int t = threadIdx.x;
    float4 a = ((const float4*)(o2 + row * DI))[t];
    float4 r = ((const float4*)(res + row * DI))[t];
    float x0 = a.x + r.x, x1 = a.y + r.y, x2 = a.z + r.z, x3 = a.w + r.w;
    float s = x0 + x1 + x2 + x3, sq = x0 * x0 + x1 * x1 + x2 * x2 + x3 * x3;
    s = warpSum(s); sq = warpSum(sq);
    __shared__ float rs[8], rq[8];
    if ((t & 31) == 0) { rs[t >> 5] = s; rq[t >> 5] = sq; }
    __syncthreads();
    s = 0.f; sq = 0.f;
    #pragma unroll
    for (int i = 0; i < 8; i++) { s += rs[i]; sq += rq[i]; }
    float mu = s * (1.0f / DI);
    float rstd = rsqrtf(sq * (1.0f / DI) - mu * mu + 1e-5f);
    float4 g = ((const float4*)gamma)[t], b = ((const float4*)beta)[t];
    float4 o;
    o.x = (x0 - mu) * rstd * g.x + b.x; o.y = (x1 - mu) * rstd * g.y + b.y;
    o.z = (x2 - mu) * rstd * g.z + b.z; o.w = (x3 - mu) * rstd * g.w + b.w;
    ((float4*)(out + row * DI))[t] = o;
}

// ---------------------------------------------------------------------------
extern "C" void kernel_launch(void* const* d_in, const int* in_sizes, int n_in,
                              void* d_out, int out_size)
{
    const float* q  = (const float*)d_in[0];
    const float* k  = (const float*)d_in[1];
    const float* v  = (const float*)d_in[2];
    const float* Wq = (const float*)d_in[3];  const float* bq = (const float*)d_in[4];
    const float* Wk = (const float*)d_in[5];  const float* bk = (const float*)d_in[6];
    const float* Wv = (const float*)d_in[7];  const float* bv = (const float*)d_in[8];
    const float* Wo = (const float*)d_in[9];  const float* bo = (const float*)d_in[10];
    const float* gamma = (const float*)d_in[11];
    const float* beta  = (const float*)d_in[12];

    float* out  = (float*)d_out;
    float* attn = out + (size_t)BI * LI * DI;

    bf16 *qhi,*qlo,*khi,*klo,*vhi,*vlo,*wqh,*wql,*wkh,*wkl,*wvh,*wvl,*woh,*wol;
    bf16 *Qhi,*Qlo,*Khi,*Klo,*VHh,*Vth,*Ohi,*P16;
    float *O2, *mt;
    cudaGetSymbolAddress((void**)&qhi, g_qhi);  cudaGetSymbolAddress((void**)&qlo, g_qlo);
    cudaGetSymbolAddress((void**)&khi, g_khi);  cudaGetSymbolAddress((void**)&klo, g_klo);
    cudaGetSymbolAddress((void**)&vhi, g_vhi);  cudaGetSymbolAddress((void**)&vlo, g_vlo);
    cudaGetSymbolAddress((void**)&wqh, g_wqhi); cudaGetSymbolAddress((void**)&wql, g_wqlo);
    cudaGetSymbolAddress((void**)&wkh, g_wkhi); cudaGetSymbolAddress((void**)&wkl, g_wklo);
    cudaGetSymbolAddress((void**)&wvh, g_wvhi); cudaGetSymbolAddress((void**)&wvl, g_wvlo);
    cudaGetSymbolAddress((void**)&woh, g_wohi); cudaGetSymbolAddress((void**)&wol, g_wolo);
    cudaGetSymbolAddress((void**)&Qhi, g_Qhi);  cudaGetSymbolAddress((void**)&Qlo, g_Qlo);
    cudaGetSymbolAddress((void**)&Khi, g_Khi);  cudaGetSymbolAddress((void**)&Klo, g_Klo);
    cudaGetSymbolAddress((void**)&VHh, g_VHhi);
    cudaGetSymbolAddress((void**)&Vth, g_Vthi);
    cudaGetSymbolAddress((void**)&Ohi, g_Ohi);
    cudaGetSymbolAddress((void**)&O2,  g_O2);
    cudaGetSymbolAddress((void**)&P16, g_P16);
    cudaGetSymbolAddress((void**)&mt,  g_mt);

    const int SM0 = 2 * (2*128*40*2 + 2*128*40*2);   // 81920 (MODE0)
    const int SM1 = 2 * (1*128*40*2 + 1*128*40*2);   // 40960 (MODE1)
    const int SMF = 102400;                          // fused_attn
    cudaFuncSetAttribute(gemm_mma<128,0>, cudaFuncAttributeMaxDynamicSharedMemorySize, SM0);
    cudaFuncSetAttribute(gemm_mma<128,1>, cudaFuncAttributeMaxDynamicSharedMemorySize, SM1);
    cudaFuncSetAttribute(fused_attn,      cudaFuncAttributeMaxDynamicSharedMemorySize, SMF);

    // input splits: q,k bf16; v fp16
    CvtSet ci; ci.s[0]=q; ci.s[1]=k; ci.s[2]=v; ci.s[3]=q;
    ci.h[0]=qhi; ci.h[1]=khi; ci.h[2]=vhi; ci.h[3]=qhi;
    ci.l[0]=qlo; ci.l[1]=klo; ci.l[2]=vlo; ci.l[3]=qlo;
    ci.n4 = 2097152; ci.f16mask = 0b100;
    convert_multi<<<dim3(8192,3), 256>>>(ci);
    // weight splits: Wq,Wk bf16; Wv,Wo fp16
    CvtSet cw; cw.s[0]=Wq; cw.s[1]=Wk; cw.s[2]=Wv; cw.s[3]=Wo;
    cw.h[0]=wqh; cw.h[1]=wkh; cw.h[2]=wvh; cw.h[3]=woh;
    cw.l[0]=wql; cw.l[1]=wkl; cw.l[2]=wvl; cw.l[3]=wol;
    cw.n4 = 262144; cw.f16mask = 0b1100;
    convert_multi<<<dim3(1024,4), 256>>>(cw);

    // merged QKV projections (Q,K bf16 3-term; V fp16 2-term -> fp16 plane)
    GP3 P; memset(&P, 0, sizeof(P));
    P.g[0] = { qhi,qlo, wqh,wql, nullptr,Qhi,Qlo, bq, DI };
    P.g[1] = { khi,klo, wkh,wkl, nullptr,Khi,Klo, bk, DI };
    P.g[2] = { vhi,vlo, wvh,nullptr, nullptr,VHh,nullptr, bv, DI };
    gemm_mma<128,0><<<dim3(8,64,3), 256, SM0>>>(P);

    transpose_bf<<<dim3(2,64,64), dim3(32,8)>>>(VHh, Vth);

    // fused two-pass attention (p16 materialization, no recompute)
    fused_attn<<<dim3(16,64), 256, SMF>>>(Qhi,Qlo, Khi,Klo, Vth, attn, Ohi, P16, mt);

    // output projection (fp16 1-term) + residual/LN
    GP3 P4; memset(&P4, 0, sizeof(P4));
    P4.g[0] = { Ohi,nullptr, woh,nullptr, O2,nullptr,nullptr, bo, DI };
    gemm_mma<128,1><<<dim3(8,64,1), 256, SM1>>>(P4);
    ln_kernel<<<BI*LI, 256>>>(O2, q, gamma, beta, out);
}